// round 1
// baseline (speedup 1.0000x reference)
#include <cuda_runtime.h>
#include <math.h>

// Shapes (fixed by the problem)
#define Bb   32
#define N1c  512
#define N2c  256
#define Dc   256
#define Hc   8
#define HDc  32
#define Sc   768   // N1 + N2

// ---------------- scratch (device globals; no allocations allowed) ----------
__device__ float d_qkv [Bb * Sc * 3 * Dc];   // 75.5 MB
__device__ float d_lf  [Bb * Sc * Dc];       // 25 MB
__device__ float d_xout[Bb * N1c * Dc];      // 16.8 MB
__device__ float d_o   [Bb * Sc * Dc];       // 25 MB
__device__ float d_op  [Bb * Sc * Dc];       // 25 MB
__device__ float d_wts [Bb * 4];

// ---------------- router: means -> Linear -> LN -> GELU -> Linear -> softmax(4)
__global__ __launch_bounds__(256) void router_kernel(
    const float* __restrict__ x1, const float* __restrict__ x2,
    const float* __restrict__ r_w1, const float* __restrict__ r_b1,
    const float* __restrict__ ln_g, const float* __restrict__ ln_b,
    const float* __restrict__ r_w2, const float* __restrict__ r_b2)
{
    __shared__ float m[2 * Dc];
    __shared__ float hb[Dc];
    __shared__ float red[8];
    __shared__ float lg[4];
    int b = blockIdx.x, t = threadIdx.x;

    // column means of x1[b] and x2[b]
    float s1 = 0.f;
    const float* p1 = x1 + (size_t)b * N1c * Dc + t;
    for (int n = 0; n < N1c; n++) s1 += p1[(size_t)n * Dc];
    m[t] = s1 * (1.f / N1c);
    float s2 = 0.f;
    const float* p2 = x2 + (size_t)b * N2c * Dc + t;
    for (int n = 0; n < N2c; n++) s2 += p2[(size_t)n * Dc];
    m[Dc + t] = s2 * (1.f / N2c);
    __syncthreads();

    // t1 = m @ r_w1.T + r_b1   (each thread one output dim)
    float acc = r_b1[t];
    const float* wr = r_w1 + (size_t)t * (2 * Dc);
    #pragma unroll 4
    for (int k = 0; k < 2 * Dc; k++) acc += m[k] * wr[k];

    // LayerNorm over 256 dims
    float v = acc;
    for (int o = 16; o; o >>= 1) v += __shfl_down_sync(0xffffffffu, v, o);
    if ((t & 31) == 0) red[t >> 5] = v;
    __syncthreads();
    if (t < 8) {
        v = red[t];
        for (int o = 4; o; o >>= 1) v += __shfl_down_sync(0xffu, v, o);
        if (t == 0) red[0] = v;
    }
    __syncthreads();
    float mu = red[0] * (1.f / Dc);
    __syncthreads();
    float dd = acc - mu;
    v = dd * dd;
    for (int o = 16; o; o >>= 1) v += __shfl_down_sync(0xffffffffu, v, o);
    if ((t & 31) == 0) red[t >> 5] = v;
    __syncthreads();
    if (t < 8) {
        v = red[t];
        for (int o = 4; o; o >>= 1) v += __shfl_down_sync(0xffu, v, o);
        if (t == 0) red[0] = v;
    }
    __syncthreads();
    float var = red[0] * (1.f / Dc);
    float y = dd * rsqrtf(var + 1e-5f) * ln_g[t] + ln_b[t];
    // exact GELU
    float g = 0.5f * y * (1.f + erff(y * 0.70710678118654752f));
    hb[t] = g;
    __syncthreads();

    if (t < 4) {
        float a = r_b2[t];
        const float* w2 = r_w2 + (size_t)t * Dc;
        for (int k = 0; k < Dc; k++) a += hb[k] * w2[k];
        lg[t] = a;
    }
    __syncthreads();
    if (t == 0) {
        float mx = fmaxf(fmaxf(lg[0], lg[1]), fmaxf(lg[2], lg[3]));
        float e0 = expf(lg[0] - mx), e1 = expf(lg[1] - mx);
        float e2 = expf(lg[2] - mx), e3 = expf(lg[3] - mx);
        float inv = 1.f / (e0 + e1 + e2 + e3);
        d_wts[b * 4 + 0] = e0 * inv; d_wts[b * 4 + 1] = e1 * inv;
        d_wts[b * 4 + 2] = e2 * inv; d_wts[b * 4 + 3] = e3 * inv;
    }
}

// ---------------- generic SGEMM: C[row_map(r)] = act(A[r,:] @ W[n,:]^T + bias[n])
// A: [M,K] row-major, W: [N,K] row-major, C has leading-dim N.
// row mapping: grow = (r / rpb) * out_stride + out_off + (r % rpb)
// ACT: 0 = none, 1 = ELU
template <int ACT>
__global__ __launch_bounds__(256) void sgemm_tn(
    const float* __restrict__ A, const float* __restrict__ W,
    const float* __restrict__ bias, float* __restrict__ C,
    int M, int N, int K, int rpb, int out_stride, int out_off)
{
    __shared__ float As[16][64];
    __shared__ float Ws[16][64];
    int tid = threadIdx.x;
    int tx = tid & 15, ty = tid >> 4;
    int m0 = blockIdx.y * 64, n0 = blockIdx.x * 64;
    int lrow = tid >> 2, lcol = tid & 3;

    float acc[4][4];
    #pragma unroll
    for (int i = 0; i < 4; i++)
        #pragma unroll
        for (int j = 0; j < 4; j++) acc[i][j] = 0.f;

    for (int k0 = 0; k0 < K; k0 += 16) {
        float4 av = *(const float4*)(A + (size_t)(m0 + lrow) * K + k0 + lcol * 4);
        float4 wv = *(const float4*)(W + (size_t)(n0 + lrow) * K + k0 + lcol * 4);
        As[lcol * 4 + 0][lrow] = av.x; As[lcol * 4 + 1][lrow] = av.y;
        As[lcol * 4 + 2][lrow] = av.z; As[lcol * 4 + 3][lrow] = av.w;
        Ws[lcol * 4 + 0][lrow] = wv.x; Ws[lcol * 4 + 1][lrow] = wv.y;
        Ws[lcol * 4 + 2][lrow] = wv.z; Ws[lcol * 4 + 3][lrow] = wv.w;
        __syncthreads();
        #pragma unroll
        for (int kk = 0; kk < 16; kk++) {
            float4 a = *(const float4*)&As[kk][ty * 4];
            float4 bv = *(const float4*)&Ws[kk][tx * 4];
            acc[0][0] += a.x * bv.x; acc[0][1] += a.x * bv.y; acc[0][2] += a.x * bv.z; acc[0][3] += a.x * bv.w;
            acc[1][0] += a.y * bv.x; acc[1][1] += a.y * bv.y; acc[1][2] += a.y * bv.z; acc[1][3] += a.y * bv.w;
            acc[2][0] += a.z * bv.x; acc[2][1] += a.z * bv.y; acc[2][2] += a.z * bv.z; acc[2][3] += a.z * bv.w;
            acc[3][0] += a.w * bv.x; acc[3][1] += a.w * bv.y; acc[3][2] += a.w * bv.z; acc[3][3] += a.w * bv.w;
        }
        __syncthreads();
    }

    int cbase = n0 + tx * 4;
    float4 bv = *(const float4*)(bias + cbase);
    #pragma unroll
    for (int i = 0; i < 4; i++) {
        int r = m0 + ty * 4 + i;
        int grow = (r / rpb) * out_stride + out_off + (r % rpb);
        float4 v;
        v.x = acc[i][0] + bv.x; v.y = acc[i][1] + bv.y;
        v.z = acc[i][2] + bv.z; v.w = acc[i][3] + bv.w;
        if (ACT == 1) {
            v.x = v.x > 0.f ? v.x : expm1f(v.x);
            v.y = v.y > 0.f ? v.y : expm1f(v.y);
            v.z = v.z > 0.f ? v.z : expm1f(v.z);
            v.w = v.w > 0.f ? v.w : expm1f(v.w);
        }
        *(float4*)(C + (size_t)grow * N + cbase) = v;
    }
}

// ---------------- a2: per-batch NN GEMM  xout[b,p,d] += elu(af3_w[p,:] @ x2[b,:,d] + af3_b[p])
__global__ __launch_bounds__(256) void a2_kernel(
    const float* __restrict__ Aw,   // [512, 256]
    const float* __restrict__ x2,   // [B, 256, 256]
    const float* __restrict__ bias) // [512]
{
    int b = blockIdx.z;
    __shared__ float As[16][64];
    __shared__ float Xs[16][64];
    int tid = threadIdx.x;
    int tx = tid & 15, ty = tid >> 4;
    int m0 = blockIdx.y * 64, n0 = blockIdx.x * 64;
    int lrow = tid >> 2, lcol = tid & 3;
    const float* X = x2 + (size_t)b * N2c * Dc;

    float acc[4][4];
    #pragma unroll
    for (int i = 0; i < 4; i++)
        #pragma unroll
        for (int j = 0; j < 4; j++) acc[i][j] = 0.f;

    for (int k0 = 0; k0 < N2c; k0 += 16) {
        float4 av = *(const float4*)(Aw + (size_t)(m0 + lrow) * N2c + k0 + lcol * 4);
        As[lcol * 4 + 0][lrow] = av.x; As[lcol * 4 + 1][lrow] = av.y;
        As[lcol * 4 + 2][lrow] = av.z; As[lcol * 4 + 3][lrow] = av.w;
        float4 xv = *(const float4*)(X + (size_t)(k0 + (tid >> 4)) * Dc + n0 + (tid & 15) * 4);
        *(float4*)&Xs[tid >> 4][(tid & 15) * 4] = xv;
        __syncthreads();
        #pragma unroll
        for (int kk = 0; kk < 16; kk++) {
            float4 a = *(const float4*)&As[kk][ty * 4];
            float4 bv = *(const float4*)&Xs[kk][tx * 4];
            acc[0][0] += a.x * bv.x; acc[0][1] += a.x * bv.y; acc[0][2] += a.x * bv.z; acc[0][3] += a.x * bv.w;
            acc[1][0] += a.y * bv.x; acc[1][1] += a.y * bv.y; acc[1][2] += a.y * bv.z; acc[1][3] += a.y * bv.w;
            acc[2][0] += a.z * bv.x; acc[2][1] += a.z * bv.y; acc[2][2] += a.z * bv.z; acc[2][3] += a.z * bv.w;
            acc[3][0] += a.w * bv.x; acc[3][1] += a.w * bv.y; acc[3][2] += a.w * bv.z; acc[3][3] += a.w * bv.w;
        }
        __syncthreads();
    }

    #pragma unroll
    for (int i = 0; i < 4; i++) {
        int p = m0 + ty * 4 + i;
        float bp = bias[p];
        float* dst = d_xout + ((size_t)(b * N1c + p)) * Dc + n0 + tx * 4;
        float4 cur = *(float4*)dst;
        float4 v;
        v.x = acc[i][0] + bp; v.y = acc[i][1] + bp; v.z = acc[i][2] + bp; v.w = acc[i][3] + bp;
        v.x = v.x > 0.f ? v.x : expm1f(v.x);
        v.y = v.y > 0.f ? v.y : expm1f(v.y);
        v.z = v.z > 0.f ? v.z : expm1f(v.z);
        v.w = v.w > 0.f ? v.w : expm1f(v.w);
        cur.x += v.x; cur.y += v.y; cur.z += v.z; cur.w += v.w;
        *(float4*)dst = cur;
    }
}

// ---------------- attention: one block per (b,h); K,V resident in smem; online softmax
__global__ __launch_bounds__(256) void attn_kernel()
{
    extern __shared__ float sm[];
    float* Ks = sm;               // Sc * 32
    float* Vs = sm + Sc * HDc;    // Sc * 32
    int bh = blockIdx.x;
    int b = bh >> 3;
    int h = bh & 7;
    int tid = threadIdx.x;
    const float* base = d_qkv + (size_t)b * Sc * (3 * Dc);

    for (int i = tid; i < Sc * 8; i += 256) {
        int s = i >> 3, d4 = i & 7;
        const float* row = base + (size_t)s * (3 * Dc) + h * HDc + d4 * 4;
        *(float4*)&Ks[s * HDc + d4 * 4] = *(const float4*)(row + Dc);
        *(float4*)&Vs[s * HDc + d4 * 4] = *(const float4*)(row + 2 * Dc);
    }
    __syncthreads();

    const float scale = 0.17677669529663688f;  // 1/sqrt(32)
    for (int rr = 0; rr < 3; rr++) {
        int sq = rr * 256 + tid;
        float q[HDc];
        const float* qp = base + (size_t)sq * (3 * Dc) + h * HDc;
        #pragma unroll
        for (int d = 0; d < HDc; d++) q[d] = qp[d] * scale;
        float acc[HDc];
        #pragma unroll
        for (int d = 0; d < HDc; d++) acc[d] = 0.f;
        float mmax = -1e30f, l = 0.f;

        for (int s = 0; s < Sc; s++) {
            const float4* kp = (const float4*)&Ks[s * HDc];
            float dot = 0.f;
            #pragma unroll
            for (int d4 = 0; d4 < 8; d4++) {
                float4 kv = kp[d4];
                dot += q[d4 * 4 + 0] * kv.x + q[d4 * 4 + 1] * kv.y
                     + q[d4 * 4 + 2] * kv.z + q[d4 * 4 + 3] * kv.w;
            }
            if (dot > mmax) {
                float c = __expf(mmax - dot);
                #pragma unroll
                for (int d = 0; d < HDc; d++) acc[d] *= c;
                l *= c;
                mmax = dot;
            }
            float p = __expf(dot - mmax);
            l += p;
            const float4* vp = (const float4*)&Vs[s * HDc];
            #pragma unroll
            for (int d4 = 0; d4 < 8; d4++) {
                float4 vv = vp[d4];
                acc[d4 * 4 + 0] += p * vv.x;
                acc[d4 * 4 + 1] += p * vv.y;
                acc[d4 * 4 + 2] += p * vv.z;
                acc[d4 * 4 + 3] += p * vv.w;
            }
        }
        float inv = 1.f / l;
        float* op = d_o + ((size_t)(b * Sc + sq)) * Dc + h * HDc;
        #pragma unroll
        for (int d = 0; d < HDc; d++) op[d] = acc[d] * inv;
    }
}

// ---------------- final weighted combine -> out = [gene | img]
__global__ __launch_bounds__(256) void combine_kernel(
    const float* __restrict__ x1, const float* __restrict__ x2,
    float* __restrict__ out)
{
    int idx = blockIdx.x * 256 + threadIdx.x;
    const int GENE4 = Bb * N1c * Dc / 4;   // 1,048,576
    const int TOT4  = GENE4 + Bb * N2c * Dc / 4;
    if (idx >= TOT4) return;
    const float4* lf4 = (const float4*)d_lf;
    const float4* xo4 = (const float4*)d_xout;
    const float4* op4 = (const float4*)d_op;

    float4 r;
    if (idx < GENE4) {
        int d4 = idx & 63;
        int rem = idx >> 6;
        int p = rem & (N1c - 1);
        int b = rem >> 9;
        const float* w = &d_wts[b * 4];
        float4 g0 = lf4[(size_t)(b * Sc + p) * 64 + d4];
        float4 g1 = xo4[(size_t)(b * N1c + p) * 64 + d4];
        float4 g2 = op4[(size_t)(b * Sc + p) * 64 + d4];
        float4 g3 = ((const float4*)x1)[(size_t)(b * N1c + p) * 64 + d4];
        r.x = w[0] * g0.x + w[1] * g1.x + w[2] * g2.x + w[3] * g3.x;
        r.y = w[0] * g0.y + w[1] * g1.y + w[2] * g2.y + w[3] * g3.y;
        r.z = w[0] * g0.z + w[1] * g1.z + w[2] * g2.z + w[3] * g3.z;
        r.w = w[0] * g0.w + w[1] * g1.w + w[2] * g2.w + w[3] * g3.w;
    } else {
        int i2 = idx - GENE4;
        int d4 = i2 & 63;
        int rem = i2 >> 6;
        int s = rem & (N2c - 1);
        int b = rem >> 8;
        const float* w = &d_wts[b * 4];
        float4 v0 = lf4[(size_t)(b * Sc + N1c + s) * 64 + d4];
        float4 v1 = xo4[(size_t)(b * N1c + s) * 64 + d4];   // i1 = x_out[:, :n2, :]
        float4 v2 = op4[(size_t)(b * Sc + N1c + s) * 64 + d4];
        float4 v3 = ((const float4*)x2)[(size_t)(b * N2c + s) * 64 + d4];
        r.x = w[0] * v0.x + w[1] * v1.x + w[2] * v2.x + w[3] * v3.x;
        r.y = w[0] * v0.y + w[1] * v1.y + w[2] * v2.y + w[3] * v3.y;
        r.z = w[0] * v0.z + w[1] * v1.z + w[2] * v2.z + w[3] * v3.z;
        r.w = w[0] * v0.w + w[1] * v1.w + w[2] * v2.w + w[3] * v3.w;
    }
    ((float4*)out)[idx] = r;
}

// ---------------- launch ----------------------------------------------------
extern "C" void kernel_launch(void* const* d_in, const int* in_sizes, int n_in,
                              void* d_out, int out_size)
{
    const float* x1        = (const float*)d_in[0];
    const float* x2        = (const float*)d_in[1];
    const float* r_w1      = (const float*)d_in[2];
    const float* r_b1      = (const float*)d_in[3];
    const float* ln_g      = (const float*)d_in[4];
    const float* ln_b      = (const float*)d_in[5];
    const float* r_w2      = (const float*)d_in[6];
    const float* r_b2      = (const float*)d_in[7];
    const float* lf_w      = (const float*)d_in[8];
    const float* lf_b      = (const float*)d_in[9];
    const float* af2_w     = (const float*)d_in[10];
    const float* af2_b     = (const float*)d_in[11];
    const float* af3_w     = (const float*)d_in[12];
    const float* af3_b     = (const float*)d_in[13];
    const float* attn_in_w = (const float*)d_in[14];
    const float* attn_in_b = (const float*)d_in[15];
    const float* attn_out_w= (const float*)d_in[16];
    const float* attn_out_b= (const float*)d_in[17];
    float* out = (float*)d_out;

    float *qkv, *lf, *xout, *o, *op;
    cudaGetSymbolAddress((void**)&qkv,  d_qkv);
    cudaGetSymbolAddress((void**)&lf,   d_lf);
    cudaGetSymbolAddress((void**)&xout, d_xout);
    cudaGetSymbolAddress((void**)&o,    d_o);
    cudaGetSymbolAddress((void**)&op,   d_op);

    const int ATTN_SMEM = 2 * Sc * HDc * (int)sizeof(float);  // 196608
    cudaFuncSetAttribute(attn_kernel, cudaFuncAttributeMaxDynamicSharedMemorySize, ATTN_SMEM);

    // 1. router weights
    router_kernel<<<Bb, 256>>>(x1, x2, r_w1, r_b1, ln_g, ln_b, r_w2, r_b2);

    // 2. qkv = z @ attn_in_w.T + b   (z never materialized: two launches)
    sgemm_tn<0><<<dim3(12, 256), 256>>>(x1, attn_in_w, attn_in_b, qkv,
                                        Bb * N1c, 3 * Dc, Dc, N1c, Sc, 0);
    sgemm_tn<0><<<dim3(12, 128), 256>>>(x2, attn_in_w, attn_in_b, qkv,
                                        Bb * N2c, 3 * Dc, Dc, N2c, Sc, N1c);

    // 3. lf = elu(z @ lf_w.T + lf_b)
    sgemm_tn<1><<<dim3(4, 256), 256>>>(x1, lf_w, lf_b, lf,
                                       Bb * N1c, Dc, Dc, N1c, Sc, 0);
    sgemm_tn<1><<<dim3(4, 128), 256>>>(x2, lf_w, lf_b, lf,
                                       Bb * N2c, Dc, Dc, N2c, Sc, N1c);

    // 4. a1 = elu(x1 @ af2_w.T + af2_b) -> xout
    sgemm_tn<1><<<dim3(4, 256), 256>>>(x1, af2_w, af2_b, xout,
                                       Bb * N1c, Dc, Dc, Bb * N1c, Bb * N1c, 0);

    // 5. xout += elu(a2)
    a2_kernel<<<dim3(4, 8, Bb), 256>>>(af3_w, x2, af3_b);

    // 6. attention (reads d_qkv, writes d_o)
    attn_kernel<<<Bb * Hc, 256, ATTN_SMEM>>>();

    // 7. o @ attn_out_w.T + attn_out_b -> d_op
    sgemm_tn<0><<<dim3(4, 384), 256>>>(o, attn_out_w, attn_out_b, op,
                                       Bb * Sc, Dc, Dc, Bb * Sc, Bb * Sc, 0);

    // 8. weighted combine -> out
    combine_kernel<<<6144, 256>>>(x1, x2, out);
}

// round 2
// speedup vs baseline: 1.4326x; 1.4326x over previous
#include <cuda_runtime.h>
#include <math.h>

// Shapes (fixed by the problem)
#define Bb   32
#define N1c  512
#define N2c  256
#define Dc   256
#define Hc   8
#define HDc  32
#define Sc   768   // N1 + N2

typedef unsigned long long u64t;

// ---------------- f32x2 packed-FMA helpers ----------------------------------
__device__ __forceinline__ u64t pk2(float x, float y) {
    u64t r; asm("mov.b64 %0,{%1,%2};" : "=l"(r) : "f"(x), "f"(y)); return r;
}
__device__ __forceinline__ float2 upk(u64t v) {
    float2 r; asm("mov.b64 {%0,%1},%2;" : "=f"(r.x), "=f"(r.y) : "l"(v)); return r;
}
__device__ __forceinline__ void fma2(u64t& d, u64t a, u64t b) {
    asm("fma.rn.f32x2 %0,%1,%2,%0;" : "+l"(d) : "l"(a), "l"(b));
}
__device__ __forceinline__ u64t add2(u64t a, u64t b) {
    u64t d; asm("add.rn.f32x2 %0,%1,%2;" : "=l"(d) : "l"(a), "l"(b)); return d;
}
__device__ __forceinline__ u64t mul2(u64t a, u64t b) {
    u64t d; asm("mul.rn.f32x2 %0,%1,%2;" : "=l"(d) : "l"(a), "l"(b)); return d;
}
__device__ __forceinline__ u64t d2u(double d) { return __double_as_longlong(d); }

// ---------------- scratch (device globals; no allocations allowed) ----------
__device__ float d_qkv [Bb * Sc * 3 * Dc];
__device__ float d_lf  [Bb * Sc * Dc];
__device__ float d_xout[Bb * N1c * Dc];
__device__ float d_o   [Bb * Sc * Dc];
__device__ float d_op  [Bb * Sc * Dc];
__device__ float d_wts [Bb * 4];

// ---------------- router: means -> Linear -> LN -> GELU -> Linear -> softmax(4)
__global__ __launch_bounds__(256) void router_kernel(
    const float* __restrict__ x1, const float* __restrict__ x2,
    const float* __restrict__ r_w1, const float* __restrict__ r_b1,
    const float* __restrict__ ln_g, const float* __restrict__ ln_b,
    const float* __restrict__ r_w2, const float* __restrict__ r_b2)
{
    __shared__ float m[2 * Dc];
    __shared__ float hb[Dc];
    __shared__ float red[8];
    __shared__ float lg[4];
    int b = blockIdx.x, t = threadIdx.x;

    float s1 = 0.f;
    const float* p1 = x1 + (size_t)b * N1c * Dc + t;
    for (int n = 0; n < N1c; n++) s1 += p1[(size_t)n * Dc];
    m[t] = s1 * (1.f / N1c);
    float s2 = 0.f;
    const float* p2 = x2 + (size_t)b * N2c * Dc + t;
    for (int n = 0; n < N2c; n++) s2 += p2[(size_t)n * Dc];
    m[Dc + t] = s2 * (1.f / N2c);
    __syncthreads();

    float acc = r_b1[t];
    const float* wr = r_w1 + (size_t)t * (2 * Dc);
    #pragma unroll 4
    for (int k = 0; k < 2 * Dc; k++) acc += m[k] * wr[k];

    float v = acc;
    for (int o = 16; o; o >>= 1) v += __shfl_down_sync(0xffffffffu, v, o);
    if ((t & 31) == 0) red[t >> 5] = v;
    __syncthreads();
    if (t < 8) {
        v = red[t];
        for (int o = 4; o; o >>= 1) v += __shfl_down_sync(0xffu, v, o);
        if (t == 0) red[0] = v;
    }
    __syncthreads();
    float mu = red[0] * (1.f / Dc);
    __syncthreads();
    float dd = acc - mu;
    v = dd * dd;
    for (int o = 16; o; o >>= 1) v += __shfl_down_sync(0xffffffffu, v, o);
    if ((t & 31) == 0) red[t >> 5] = v;
    __syncthreads();
    if (t < 8) {
        v = red[t];
        for (int o = 4; o; o >>= 1) v += __shfl_down_sync(0xffu, v, o);
        if (t == 0) red[0] = v;
    }
    __syncthreads();
    float var = red[0] * (1.f / Dc);
    float y = dd * rsqrtf(var + 1e-5f) * ln_g[t] + ln_b[t];
    float g = 0.5f * y * (1.f + erff(y * 0.70710678118654752f));
    hb[t] = g;
    __syncthreads();

    if (t < 4) {
        float a = r_b2[t];
        const float* w2 = r_w2 + (size_t)t * Dc;
        for (int k = 0; k < Dc; k++) a += hb[k] * w2[k];
        lg[t] = a;
    }
    __syncthreads();
    if (t == 0) {
        float mx = fmaxf(fmaxf(lg[0], lg[1]), fmaxf(lg[2], lg[3]));
        float e0 = expf(lg[0] - mx), e1 = expf(lg[1] - mx);
        float e2 = expf(lg[2] - mx), e3 = expf(lg[3] - mx);
        float inv = 1.f / (e0 + e1 + e2 + e3);
        d_wts[b * 4 + 0] = e0 * inv; d_wts[b * 4 + 1] = e1 * inv;
        d_wts[b * 4 + 2] = e2 * inv; d_wts[b * 4 + 3] = e3 * inv;
    }
}

// ---------------- 128x128x8 GEMM, 8x8 per thread, packed f32x2 FMAs ---------
// C[row_map(r), n] (= or +=) act(A[r,:] @ B(n,:) + bias[n])
// BT=false: B is W[N,K] row-major (K contiguous)
// BT=true : B is X[K,N] row-major (N contiguous), ldB = row stride of X
// ACT: 0 none, 1 ELU.  ACCUM: C += result (else C = result).
template <int ACT, bool BT, bool ACCUM>
__global__ __launch_bounds__(256) void gemm128(
    const float* __restrict__ A, const float* __restrict__ B,
    const float* __restrict__ bias, float* __restrict__ C,
    int M, int N, int K, int ldB,
    int rpb, int out_stride, int out_off,
    size_t aBatch, size_t bBatch, size_t cBatch)
{
    __shared__ __align__(16) float As[8][128];
    __shared__ __align__(16) float Bs[8][128];

    int bz = blockIdx.z;
    const float* Ap = A + (size_t)bz * aBatch;
    const float* Bp = B + (size_t)bz * bBatch;
    float* Cp = C + (size_t)bz * cBatch;

    int tid = threadIdx.x;
    int tx = tid & 15, ty = tid >> 4;
    int m0 = blockIdx.y * 128, n0 = blockIdx.x * 128;

    u64t acc[4][8];
    #pragma unroll
    for (int i = 0; i < 4; i++)
        #pragma unroll
        for (int j = 0; j < 8; j++) acc[i][j] = 0ull;

    int lrow = tid >> 1, lc4 = (tid & 1) * 4;

    for (int k0 = 0; k0 < K; k0 += 8) {
        {
            float4 av = *(const float4*)(Ap + (size_t)(m0 + lrow) * K + k0 + lc4);
            As[lc4 + 0][lrow] = av.x; As[lc4 + 1][lrow] = av.y;
            As[lc4 + 2][lrow] = av.z; As[lc4 + 3][lrow] = av.w;
        }
        if (BT) {
            int kr = tid >> 5, nc = (tid & 31) * 4;
            *(float4*)&Bs[kr][nc] =
                *(const float4*)(Bp + (size_t)(k0 + kr) * ldB + n0 + nc);
        } else {
            float4 wv = *(const float4*)(Bp + (size_t)(n0 + lrow) * K + k0 + lc4);
            Bs[lc4 + 0][lrow] = wv.x; Bs[lc4 + 1][lrow] = wv.y;
            Bs[lc4 + 2][lrow] = wv.z; Bs[lc4 + 3][lrow] = wv.w;
        }
        __syncthreads();
        #pragma unroll
        for (int kk = 0; kk < 8; kk++) {
            double2 a01 = *(const double2*)&As[kk][ty * 8];
            double2 a23 = *(const double2*)&As[kk][ty * 8 + 4];
            u64t ap0 = d2u(a01.x), ap1 = d2u(a01.y);
            u64t ap2 = d2u(a23.x), ap3 = d2u(a23.y);
            float4 b0 = *(const float4*)&Bs[kk][tx * 8];
            float4 b1 = *(const float4*)&Bs[kk][tx * 8 + 4];
            u64t bb[8];
            bb[0] = pk2(b0.x, b0.x); bb[1] = pk2(b0.y, b0.y);
            bb[2] = pk2(b0.z, b0.z); bb[3] = pk2(b0.w, b0.w);
            bb[4] = pk2(b1.x, b1.x); bb[5] = pk2(b1.y, b1.y);
            bb[6] = pk2(b1.z, b1.z); bb[7] = pk2(b1.w, b1.w);
            #pragma unroll
            for (int j = 0; j < 8; j++) {
                fma2(acc[0][j], ap0, bb[j]);
                fma2(acc[1][j], ap1, bb[j]);
                fma2(acc[2][j], ap2, bb[j]);
                fma2(acc[3][j], ap3, bb[j]);
            }
        }
        __syncthreads();
    }

    int cbase = n0 + tx * 8;
    float4 bv0 = *(const float4*)(bias + cbase);
    float4 bv1 = *(const float4*)(bias + cbase + 4);
    float bj[8] = {bv0.x, bv0.y, bv0.z, bv0.w, bv1.x, bv1.y, bv1.z, bv1.w};

    #pragma unroll
    for (int i2 = 0; i2 < 4; i2++) {
        float vlo[8], vhi[8];
        #pragma unroll
        for (int j = 0; j < 8; j++) {
            float2 p = upk(acc[i2][j]);
            vlo[j] = p.x + bj[j];
            vhi[j] = p.y + bj[j];
        }
        #pragma unroll
        for (int h = 0; h < 2; h++) {
            float* v = h ? vhi : vlo;
            int r = m0 + ty * 8 + i2 * 2 + h;
            int grow = (r / rpb) * out_stride + out_off + (r % rpb);
            float4 o0, o1;
            if (ACT == 1) {
                #pragma unroll
                for (int j = 0; j < 8; j++) v[j] = v[j] > 0.f ? v[j] : expm1f(v[j]);
            }
            float* dst = Cp + (size_t)grow * N + cbase;
            if (ACCUM) {
                float4 c0 = *(float4*)dst, c1 = *(float4*)(dst + 4);
                o0.x = c0.x + v[0]; o0.y = c0.y + v[1]; o0.z = c0.z + v[2]; o0.w = c0.w + v[3];
                o1.x = c1.x + v[4]; o1.y = c1.y + v[5]; o1.z = c1.z + v[6]; o1.w = c1.w + v[7];
            } else {
                o0.x = v[0]; o0.y = v[1]; o0.z = v[2]; o0.w = v[3];
                o1.x = v[4]; o1.y = v[5]; o1.z = v[6]; o1.w = v[7];
            }
            *(float4*)dst = o0;
            *(float4*)(dst + 4) = o1;
        }
    }
}

// ---------------- attention: one block per (b,h); packed f32x2 math ---------
__global__ __launch_bounds__(256) void attn_kernel()
{
    extern __shared__ float sm[];
    float* Ks = sm;               // Sc * 32
    float* Vs = sm + Sc * HDc;    // Sc * 32
    int bh = blockIdx.x;
    int b = bh >> 3;
    int h = bh & 7;
    int tid = threadIdx.x;
    const float* base = d_qkv + (size_t)b * Sc * (3 * Dc);

    for (int i = tid; i < Sc * 8; i += 256) {
        int s = i >> 3, d4 = i & 7;
        const float* row = base + (size_t)s * (3 * Dc) + h * HDc + d4 * 4;
        *(float4*)&Ks[s * HDc + d4 * 4] = *(const float4*)(row + Dc);
        *(float4*)&Vs[s * HDc + d4 * 4] = *(const float4*)(row + 2 * Dc);
    }
    __syncthreads();

    const float scale = 0.17677669529663688f;  // 1/sqrt(32)
    u64t sc2 = pk2(scale, scale);

    for (int rr = 0; rr < 3; rr++) {
        int sq = rr * 256 + tid;
        const double2* qp = (const double2*)(base + (size_t)sq * (3 * Dc) + h * HDc);
        u64t q2[16];
        #pragma unroll
        for (int i = 0; i < 8; i++) {
            double2 qd = qp[i];
            q2[2 * i]     = mul2(d2u(qd.x), sc2);
            q2[2 * i + 1] = mul2(d2u(qd.y), sc2);
        }
        u64t acc2[16];
        #pragma unroll
        for (int i = 0; i < 16; i++) acc2[i] = 0ull;
        float mmax = -1e30f, l = 0.f;

        for (int s = 0; s < Sc; s++) {
            const double2* kp = (const double2*)&Ks[s * HDc];
            u64t t0 = 0ull, t1 = 0ull, t2 = 0ull, t3 = 0ull;
            #pragma unroll
            for (int i = 0; i < 8; i++) {
                double2 kd = kp[i];
                if (i & 1) {
                    fma2(t2, q2[2 * i],     d2u(kd.x));
                    fma2(t3, q2[2 * i + 1], d2u(kd.y));
                } else {
                    fma2(t0, q2[2 * i],     d2u(kd.x));
                    fma2(t1, q2[2 * i + 1], d2u(kd.y));
                }
            }
            float2 r0 = upk(add2(t0, t2));
            float2 r1 = upk(add2(t1, t3));
            float dot = (r0.x + r0.y) + (r1.x + r1.y);

            if (dot > mmax) {
                float c = __expf(mmax - dot);
                u64t c2 = pk2(c, c);
                #pragma unroll
                for (int i = 0; i < 16; i++) acc2[i] = mul2(acc2[i], c2);
                l *= c;
                mmax = dot;
            }
            float p = __expf(dot - mmax);
            l += p;
            u64t pb = pk2(p, p);
            const double2* vp = (const double2*)&Vs[s * HDc];
            #pragma unroll
            for (int i = 0; i < 8; i++) {
                double2 vd = vp[i];
                fma2(acc2[2 * i],     pb, d2u(vd.x));
                fma2(acc2[2 * i + 1], pb, d2u(vd.y));
            }
        }
        float inv = 1.f / l;
        float* op = d_o + ((size_t)(b * Sc + sq)) * Dc + h * HDc;
        #pragma unroll
        for (int i = 0; i < 8; i++) {
            float2 ra = upk(acc2[2 * i]);
            float2 rb = upk(acc2[2 * i + 1]);
            float4 o;
            o.x = ra.x * inv; o.y = ra.y * inv;
            o.z = rb.x * inv; o.w = rb.y * inv;
            *(float4*)(op + i * 4) = o;
        }
    }
}

// ---------------- final weighted combine -> out = [gene | img]
__global__ __launch_bounds__(256) void combine_kernel(
    const float* __restrict__ x1, const float* __restrict__ x2,
    float* __restrict__ out)
{
    int idx = blockIdx.x * 256 + threadIdx.x;
    const int GENE4 = Bb * N1c * Dc / 4;
    const int TOT4  = GENE4 + Bb * N2c * Dc / 4;
    if (idx >= TOT4) return;
    const float4* lf4 = (const float4*)d_lf;
    const float4* xo4 = (const float4*)d_xout;
    const float4* op4 = (const float4*)d_op;

    float4 r;
    if (idx < GENE4) {
        int d4 = idx & 63;
        int rem = idx >> 6;
        int p = rem & (N1c - 1);
        int b = rem >> 9;
        const float* w = &d_wts[b * 4];
        float4 g0 = lf4[(size_t)(b * Sc + p) * 64 + d4];
        float4 g1 = xo4[(size_t)(b * N1c + p) * 64 + d4];
        float4 g2 = op4[(size_t)(b * Sc + p) * 64 + d4];
        float4 g3 = ((const float4*)x1)[(size_t)(b * N1c + p) * 64 + d4];
        r.x = w[0] * g0.x + w[1] * g1.x + w[2] * g2.x + w[3] * g3.x;
        r.y = w[0] * g0.y + w[1] * g1.y + w[2] * g2.y + w[3] * g3.y;
        r.z = w[0] * g0.z + w[1] * g1.z + w[2] * g2.z + w[3] * g3.z;
        r.w = w[0] * g0.w + w[1] * g1.w + w[2] * g2.w + w[3] * g3.w;
    } else {
        int i2 = idx - GENE4;
        int d4 = i2 & 63;
        int rem = i2 >> 6;
        int s = rem & (N2c - 1);
        int b = rem >> 8;
        const float* w = &d_wts[b * 4];
        float4 v0 = lf4[(size_t)(b * Sc + N1c + s) * 64 + d4];
        float4 v1 = xo4[(size_t)(b * N1c + s) * 64 + d4];
        float4 v2 = op4[(size_t)(b * Sc + N1c + s) * 64 + d4];
        float4 v3 = ((const float4*)x2)[(size_t)(b * N2c + s) * 64 + d4];
        r.x = w[0] * v0.x + w[1] * v1.x + w[2] * v2.x + w[3] * v3.x;
        r.y = w[0] * v0.y + w[1] * v1.y + w[2] * v2.y + w[3] * v3.y;
        r.z = w[0] * v0.z + w[1] * v1.z + w[2] * v2.z + w[3] * v3.z;
        r.w = w[0] * v0.w + w[1] * v1.w + w[2] * v2.w + w[3] * v3.w;
    }
    ((float4*)out)[idx] = r;
}

// ---------------- launch ----------------------------------------------------
extern "C" void kernel_launch(void* const* d_in, const int* in_sizes, int n_in,
                              void* d_out, int out_size)
{
    const float* x1        = (const float*)d_in[0];
    const float* x2        = (const float*)d_in[1];
    const float* r_w1      = (const float*)d_in[2];
    const float* r_b1      = (const float*)d_in[3];
    const float* ln_g      = (const float*)d_in[4];
    const float* ln_b      = (const float*)d_in[5];
    const float* r_w2      = (const float*)d_in[6];
    const float* r_b2      = (const float*)d_in[7];
    const float* lf_w      = (const float*)d_in[8];
    const float* lf_b      = (const float*)d_in[9];
    const float* af2_w     = (const float*)d_in[10];
    const float* af2_b     = (const float*)d_in[11];
    const float* af3_w     = (const float*)d_in[12];
    const float* af3_b     = (const float*)d_in[13];
    const float* attn_in_w = (const float*)d_in[14];
    const float* attn_in_b = (const float*)d_in[15];
    const float* attn_out_w= (const float*)d_in[16];
    const float* attn_out_b= (const float*)d_in[17];
    float* out = (float*)d_out;

    float *qkv, *lf, *xout, *o, *op;
    cudaGetSymbolAddress((void**)&qkv,  d_qkv);
    cudaGetSymbolAddress((void**)&lf,   d_lf);
    cudaGetSymbolAddress((void**)&xout, d_xout);
    cudaGetSymbolAddress((void**)&o,    d_o);
    cudaGetSymbolAddress((void**)&op,   d_op);

    const int ATTN_SMEM = 2 * Sc * HDc * (int)sizeof(float);  // 196608
    cudaFuncSetAttribute(attn_kernel, cudaFuncAttributeMaxDynamicSharedMemorySize, ATTN_SMEM);

    const int BIGR = 1 << 30;

    // 1. router weights
    router_kernel<<<Bb, 256>>>(x1, x2, r_w1, r_b1, ln_g, ln_b, r_w2, r_b2);

    // 2. qkv = z @ attn_in_w.T + b   (z never materialized: two launches)
    gemm128<0, false, false><<<dim3(6, 128), 256>>>(x1, attn_in_w, attn_in_b, qkv,
        Bb * N1c, 3 * Dc, Dc, Dc, N1c, Sc, 0, 0, 0, 0);
    gemm128<0, false, false><<<dim3(6, 64), 256>>>(x2, attn_in_w, attn_in_b, qkv,
        Bb * N2c, 3 * Dc, Dc, Dc, N2c, Sc, N1c, 0, 0, 0);

    // 3. lf = elu(z @ lf_w.T + lf_b)
    gemm128<1, false, false><<<dim3(2, 128), 256>>>(x1, lf_w, lf_b, lf,
        Bb * N1c, Dc, Dc, Dc, N1c, Sc, 0, 0, 0, 0);
    gemm128<1, false, false><<<dim3(2, 64), 256>>>(x2, lf_w, lf_b, lf,
        Bb * N2c, Dc, Dc, Dc, N2c, Sc, N1c, 0, 0, 0);

    // 4. a1 = elu(x1 @ af2_w.T + af2_b) -> xout
    gemm128<1, false, false><<<dim3(2, 128), 256>>>(x1, af2_w, af2_b, xout,
        Bb * N1c, Dc, Dc, Dc, BIGR, 0, 0, 0, 0, 0);

    // 5. xout += elu(af3_w @ x2[b] + af3_b)   (per-batch NN GEMM)
    gemm128<1, true, true><<<dim3(2, 4, Bb), 256>>>(af3_w, x2, af3_b, xout,
        N1c, Dc, N2c, Dc, BIGR, 0, 0,
        0, (size_t)N2c * Dc, (size_t)N1c * Dc);

    // 6. attention (reads d_qkv, writes d_o)
    attn_kernel<<<Bb * Hc, 256, ATTN_SMEM>>>();

    // 7. o @ attn_out_w.T + attn_out_b -> d_op
    gemm128<0, false, false><<<dim3(2, 192), 256>>>(o, attn_out_w, attn_out_b, op,
        Bb * Sc, Dc, Dc, Dc, BIGR, 0, 0, 0, 0, 0);

    // 8. weighted combine -> out
    combine_kernel<<<6144, 256>>>(x1, x2, out);
}

// round 3
// speedup vs baseline: 1.7542x; 1.2245x over previous
#include <cuda_runtime.h>
#include <math.h>

// Shapes (fixed by the problem)
#define Bb   32
#define N1c  512
#define N2c  256
#define Dc   256
#define Hc   8
#define HDc  32
#define Sc   768   // N1 + N2

typedef unsigned long long u64t;

// ---------------- f32x2 packed-FMA helpers ----------------------------------
__device__ __forceinline__ u64t pk2(float x, float y) {
    u64t r; asm("mov.b64 %0,{%1,%2};" : "=l"(r) : "f"(x), "f"(y)); return r;
}
__device__ __forceinline__ float2 upk(u64t v) {
    float2 r; asm("mov.b64 {%0,%1},%2;" : "=f"(r.x), "=f"(r.y) : "l"(v)); return r;
}
__device__ __forceinline__ void fma2(u64t& d, u64t a, u64t b) {
    asm("fma.rn.f32x2 %0,%1,%2,%0;" : "+l"(d) : "l"(a), "l"(b));
}
__device__ __forceinline__ u64t add2(u64t a, u64t b) {
    u64t d; asm("add.rn.f32x2 %0,%1,%2;" : "=l"(d) : "l"(a), "l"(b)); return d;
}
__device__ __forceinline__ u64t mul2(u64t a, u64t b) {
    u64t d; asm("mul.rn.f32x2 %0,%1,%2;" : "=l"(d) : "l"(a), "l"(b)); return d;
}
__device__ __forceinline__ u64t d2u(double d) { return __double_as_longlong(d); }

// ---------------- scratch (device globals; no allocations allowed) ----------
__device__ __align__(16) float d_qkv [Bb * Sc * 3 * Dc];
__device__ __align__(16) float d_lf  [Bb * Sc * Dc];
__device__ __align__(16) float d_xout[Bb * N1c * Dc];
__device__ __align__(16) float d_o   [Bb * Sc * Dc];
__device__ __align__(16) float d_op  [Bb * Sc * Dc];
__device__ float d_wts [Bb * 4];

// ---------------- router ----------------------------------------------------
__global__ __launch_bounds__(256) void router_kernel(
    const float* __restrict__ x1, const float* __restrict__ x2,
    const float* __restrict__ r_w1, const float* __restrict__ r_b1,
    const float* __restrict__ ln_g, const float* __restrict__ ln_b,
    const float* __restrict__ r_w2, const float* __restrict__ r_b2)
{
    __shared__ float m[2 * Dc];
    __shared__ float hb[Dc];
    __shared__ float red[8];
    __shared__ float lg[4];
    int b = blockIdx.x, t = threadIdx.x;

    float s1 = 0.f;
    const float* p1 = x1 + (size_t)b * N1c * Dc + t;
    for (int n = 0; n < N1c; n++) s1 += p1[(size_t)n * Dc];
    m[t] = s1 * (1.f / N1c);
    float s2 = 0.f;
    const float* p2 = x2 + (size_t)b * N2c * Dc + t;
    for (int n = 0; n < N2c; n++) s2 += p2[(size_t)n * Dc];
    m[Dc + t] = s2 * (1.f / N2c);
    __syncthreads();

    float acc = r_b1[t];
    const float* wr = r_w1 + (size_t)t * (2 * Dc);
    #pragma unroll 4
    for (int k = 0; k < 2 * Dc; k++) acc += m[k] * wr[k];

    float v = acc;
    for (int o = 16; o; o >>= 1) v += __shfl_down_sync(0xffffffffu, v, o);
    if ((t & 31) == 0) red[t >> 5] = v;
    __syncthreads();
    if (t < 8) {
        v = red[t];
        for (int o = 4; o; o >>= 1) v += __shfl_down_sync(0xffu, v, o);
        if (t == 0) red[0] = v;
    }
    __syncthreads();
    float mu = red[0] * (1.f / Dc);
    __syncthreads();
    float dd = acc - mu;
    v = dd * dd;
    for (int o = 16; o; o >>= 1) v += __shfl_down_sync(0xffffffffu, v, o);
    if ((t & 31) == 0) red[t >> 5] = v;
    __syncthreads();
    if (t < 8) {
        v = red[t];
        for (int o = 4; o; o >>= 1) v += __shfl_down_sync(0xffu, v, o);
        if (t == 0) red[0] = v;
    }
    __syncthreads();
    float var = red[0] * (1.f / Dc);
    float y = dd * rsqrtf(var + 1e-5f) * ln_g[t] + ln_b[t];
    float g = 0.5f * y * (1.f + erff(y * 0.70710678118654752f));
    hb[t] = g;
    __syncthreads();

    if (t < 4) {
        float a = r_b2[t];
        const float* w2 = r_w2 + (size_t)t * Dc;
        for (int k = 0; k < Dc; k++) a += hb[k] * w2[k];
        lg[t] = a;
    }
    __syncthreads();
    if (t == 0) {
        float mx = fmaxf(fmaxf(lg[0], lg[1]), fmaxf(lg[2], lg[3]));
        float e0 = expf(lg[0] - mx), e1 = expf(lg[1] - mx);
        float e2 = expf(lg[2] - mx), e3 = expf(lg[3] - mx);
        float inv = 1.f / (e0 + e1 + e2 + e3);
        d_wts[b * 4 + 0] = e0 * inv; d_wts[b * 4 + 1] = e1 * inv;
        d_wts[b * 4 + 2] = e2 * inv; d_wts[b * 4 + 3] = e3 * inv;
    }
}

// ---------------- GEMM core: BM=256, BN=128, BK=8, thread tile 16x8 ---------
// Double-buffered smem prefetch. Packed f32x2 FMAs (pairs along M).
// BT=false: W is [N,K] row-major.  BT=true: W is [K,N] row-major, ldB = N stride.
// RB: bias indexed by output row (a2); else by column.
// Row mapping: grow = (r/rpb)*ostride + ooff + r%rpb.  act: 0 none, 1 ELU.
template<bool BT, bool ACCUM, bool RB>
__device__ __forceinline__ void gemm_core(
    float As[2][8][256], float Bs[2][8][128],
    const float* __restrict__ A, const float* __restrict__ W,
    const float* __restrict__ bias, float* __restrict__ C,
    int K, int ldB, int ldC, int m0, int gn0,
    int rpb, int ostride, int ooff, int act)
{
    const int tid = threadIdx.x;
    const int tx = tid & 15, ty = tid >> 4;

    u64t acc[8][8];
    #pragma unroll
    for (int i = 0; i < 8; i++)
        #pragma unroll
        for (int j = 0; j < 8; j++) acc[i][j] = 0ull;

    const float* aRow = A + (size_t)(m0 + tid) * K;
    float4 pa0, pa1, pb;

    // prologue: load tile 0
    pa0 = *(const float4*)(aRow + 0);
    pa1 = *(const float4*)(aRow + 4);
    if (BT) pb = *(const float4*)(W + (size_t)(tid >> 5) * ldB + gn0 + (tid & 31) * 4);
    else    pb = *(const float4*)(W + (size_t)(gn0 + (tid & 127)) * K + (tid >> 7) * 4);

    As[0][0][tid] = pa0.x; As[0][1][tid] = pa0.y; As[0][2][tid] = pa0.z; As[0][3][tid] = pa0.w;
    As[0][4][tid] = pa1.x; As[0][5][tid] = pa1.y; As[0][6][tid] = pa1.z; As[0][7][tid] = pa1.w;
    if (BT) {
        *(float4*)&Bs[0][tid >> 5][(tid & 31) * 4] = pb;
    } else {
        int kb = (tid >> 7) * 4, n = tid & 127;
        Bs[0][kb + 0][n] = pb.x; Bs[0][kb + 1][n] = pb.y;
        Bs[0][kb + 2][n] = pb.z; Bs[0][kb + 3][n] = pb.w;
    }
    __syncthreads();

    int buf = 0;
    for (int k0 = 0; k0 < K; k0 += 8) {
        int kn = k0 + 8;
        bool more = kn < K;
        if (more) {   // prefetch next tile into registers while computing
            pa0 = *(const float4*)(aRow + kn);
            pa1 = *(const float4*)(aRow + kn + 4);
            if (BT) pb = *(const float4*)(W + (size_t)(kn + (tid >> 5)) * ldB + gn0 + (tid & 31) * 4);
            else    pb = *(const float4*)(W + (size_t)(gn0 + (tid & 127)) * K + kn + (tid >> 7) * 4);
        }
        #pragma unroll
        for (int kk = 0; kk < 8; kk++) {
            const double2* aP = (const double2*)&As[buf][kk][ty * 16];
            double2 d0 = aP[0], d1 = aP[1], d2 = aP[2], d3 = aP[3];
            u64t ap[8] = { d2u(d0.x), d2u(d0.y), d2u(d1.x), d2u(d1.y),
                           d2u(d2.x), d2u(d2.y), d2u(d3.x), d2u(d3.y) };
            const float4* bP = (const float4*)&Bs[buf][kk][tx * 8];
            float4 f0 = bP[0], f1 = bP[1];
            u64t bb[8] = { pk2(f0.x, f0.x), pk2(f0.y, f0.y), pk2(f0.z, f0.z), pk2(f0.w, f0.w),
                           pk2(f1.x, f1.x), pk2(f1.y, f1.y), pk2(f1.z, f1.z), pk2(f1.w, f1.w) };
            #pragma unroll
            for (int i = 0; i < 8; i++)
                #pragma unroll
                for (int j = 0; j < 8; j++) fma2(acc[i][j], ap[i], bb[j]);
        }
        if (more) {
            int nb2 = buf ^ 1;
            As[nb2][0][tid] = pa0.x; As[nb2][1][tid] = pa0.y;
            As[nb2][2][tid] = pa0.z; As[nb2][3][tid] = pa0.w;
            As[nb2][4][tid] = pa1.x; As[nb2][5][tid] = pa1.y;
            As[nb2][6][tid] = pa1.z; As[nb2][7][tid] = pa1.w;
            if (BT) {
                *(float4*)&Bs[nb2][tid >> 5][(tid & 31) * 4] = pb;
            } else {
                int kb = (tid >> 7) * 4, n = tid & 127;
                Bs[nb2][kb + 0][n] = pb.x; Bs[nb2][kb + 1][n] = pb.y;
                Bs[nb2][kb + 2][n] = pb.z; Bs[nb2][kb + 3][n] = pb.w;
            }
        }
        __syncthreads();
        buf ^= 1;
    }

    // epilogue
    int cb = gn0 + tx * 8;
    float bj[8];
    if (!RB) {
        float4 b0v = *(const float4*)(bias + cb);
        float4 b1v = *(const float4*)(bias + cb + 4);
        bj[0] = b0v.x; bj[1] = b0v.y; bj[2] = b0v.z; bj[3] = b0v.w;
        bj[4] = b1v.x; bj[5] = b1v.y; bj[6] = b1v.z; bj[7] = b1v.w;
    }
    #pragma unroll
    for (int i2 = 0; i2 < 8; i2++) {
        float vl[8], vh[8];
        #pragma unroll
        for (int j = 0; j < 8; j++) {
            float2 p = upk(acc[i2][j]);
            vl[j] = p.x; vh[j] = p.y;
        }
        #pragma unroll
        for (int hh = 0; hh < 2; hh++) {
            float* v = hh ? vh : vl;
            int r = m0 + ty * 16 + i2 * 2 + hh;
            float rb = RB ? bias[r] : 0.f;
            int grow = (r / rpb) * ostride + ooff + (r % rpb);
            float o8[8];
            #pragma unroll
            for (int j = 0; j < 8; j++) {
                float x = v[j] + (RB ? rb : bj[j]);
                if (act) x = x > 0.f ? x : expm1f(x);
                o8[j] = x;
            }
            float* dst = C + (size_t)grow * ldC + cb;
            if (ACCUM) {
                float4 c0 = *(float4*)dst, c1 = *(float4*)(dst + 4);
                o8[0] += c0.x; o8[1] += c0.y; o8[2] += c0.z; o8[3] += c0.w;
                o8[4] += c1.x; o8[5] += c1.y; o8[6] += c1.z; o8[7] += c1.w;
            }
            *(float4*)dst       = make_float4(o8[0], o8[1], o8[2], o8[3]);
            *(float4*)(dst + 4) = make_float4(o8[4], o8[5], o8[6], o8[7]);
        }
    }
}

// ---------------- segmented multi-output GEMM (shared A) ---------------------
struct SegP {
    const float* W; const float* bias; float* C;
    int ldC; int rpb; int ostride; int ooff; int act;
};

__global__ __launch_bounds__(256, 1) void gemm_ms(
    const float* __restrict__ A, int K,
    SegP s0, SegP s1, SegP s2, int t1, int t2)
{
    __shared__ __align__(16) float As[2][8][256];
    __shared__ __align__(16) float Bs[2][8][128];
    int bx = blockIdx.x;
    SegP sp; int nb;
    if (bx < t1)      { sp = s0; nb = bx; }
    else if (bx < t2) { sp = s1; nb = bx - t1; }
    else              { sp = s2; nb = bx - t2; }
    gemm_core<false, false, false>(As, Bs, A, sp.W, sp.bias, sp.C,
        K, 0, sp.ldC, blockIdx.y * 256, nb * 128,
        sp.rpb, sp.ostride, sp.ooff, sp.act);
}

// ---------------- standalone (batched) GEMM ----------------------------------
template<int ACT, bool BT, bool ACCUM, bool RB>
__global__ __launch_bounds__(256, 1) void gemm1(
    const float* __restrict__ A, const float* __restrict__ W,
    const float* __restrict__ bias, float* __restrict__ C,
    int K, int ldB, int ldC, int rpb, int ostride, int ooff,
    size_t aB, size_t bB, size_t cB)
{
    __shared__ __align__(16) float As[2][8][256];
    __shared__ __align__(16) float Bs[2][8][128];
    int bz = blockIdx.z;
    gemm_core<BT, ACCUM, RB>(As, Bs,
        A + (size_t)bz * aB, W + (size_t)bz * bB, bias, C + (size_t)bz * cB,
        K, ldB, ldC, blockIdx.y * 256, blockIdx.x * 128,
        rpb, ostride, ooff, ACT);
}

// ---------------- attention --------------------------------------------------
// One block per (b,h); K,V resident in smem. NR query rows per thread processed
// jointly, sharing K/V smem broadcasts. No max-subtract: |scores| <= ~4 here.
template<int NR>
__device__ __forceinline__ void attn_body(
    const float* __restrict__ base, const float* Ks, const float* Vs,
    int b, int h, int sq0)
{
    const float scale = 0.17677669529663688f;  // 1/sqrt(32)
    u64t sc2 = pk2(scale, scale);

    u64t q[NR][16], acc[NR][16];
    float l[NR];
    #pragma unroll
    for (int r = 0; r < NR; r++) {
        const double2* qp = (const double2*)(base + (size_t)(sq0 + r * 256) * (3 * Dc) + h * HDc);
        #pragma unroll
        for (int i = 0; i < 8; i++) {
            double2 qd = qp[i];
            q[r][2 * i]     = mul2(d2u(qd.x), sc2);
            q[r][2 * i + 1] = mul2(d2u(qd.y), sc2);
        }
        #pragma unroll
        for (int i = 0; i < 16; i++) acc[r][i] = 0ull;
        l[r] = 0.f;
    }

    for (int s = 0; s < Sc; s++) {
        const double2* kp = (const double2*)&Ks[s * HDc];
        u64t t0[NR], t1[NR];
        #pragma unroll
        for (int r = 0; r < NR; r++) { t0[r] = 0ull; t1[r] = 0ull; }
        #pragma unroll
        for (int i = 0; i < 8; i++) {
            double2 kd = kp[i];
            u64t ka = d2u(kd.x), kb = d2u(kd.y);
            #pragma unroll
            for (int r = 0; r < NR; r++) {
                fma2(t0[r], q[r][2 * i],     ka);
                fma2(t1[r], q[r][2 * i + 1], kb);
            }
        }
        u64t pb[NR];
        #pragma unroll
        for (int r = 0; r < NR; r++) {
            float2 f = upk(add2(t0[r], t1[r]));
            float p = __expf(f.x + f.y);
            l[r] += p;
            pb[r] = pk2(p, p);
        }
        const double2* vp = (const double2*)&Vs[s * HDc];
        #pragma unroll
        for (int i = 0; i < 8; i++) {
            double2 vd = vp[i];
            u64t va = d2u(vd.x), vb = d2u(vd.y);
            #pragma unroll
            for (int r = 0; r < NR; r++) {
                fma2(acc[r][2 * i],     pb[r], va);
                fma2(acc[r][2 * i + 1], pb[r], vb);
            }
        }
    }
    #pragma unroll
    for (int r = 0; r < NR; r++) {
        float inv = 1.f / l[r];
        float* op = d_o + ((size_t)(b * Sc + sq0 + r * 256)) * Dc + h * HDc;
        #pragma unroll
        for (int i = 0; i < 8; i++) {
            float2 ra = upk(acc[r][2 * i]);
            float2 rbv = upk(acc[r][2 * i + 1]);
            *(float4*)(op + i * 4) = make_float4(ra.x * inv, ra.y * inv, rbv.x * inv, rbv.y * inv);
        }
    }
}

__global__ __launch_bounds__(256, 1) void attn_kernel()
{
    extern __shared__ float sm[];
    float* Ks = sm;               // Sc * 32
    float* Vs = sm + Sc * HDc;    // Sc * 32
    int bh = blockIdx.x;
    int b = bh >> 3;
    int h = bh & 7;
    int tid = threadIdx.x;
    const float* base = d_qkv + (size_t)b * Sc * (3 * Dc);

    for (int i = tid; i < Sc * 8; i += 256) {
        int s = i >> 3, d4 = i & 7;
        const float* row = base + (size_t)s * (3 * Dc) + h * HDc + d4 * 4;
        *(float4*)&Ks[s * HDc + d4 * 4] = *(const float4*)(row + Dc);
        *(float4*)&Vs[s * HDc + d4 * 4] = *(const float4*)(row + 2 * Dc);
    }
    __syncthreads();

    attn_body<2>(base, Ks, Vs, b, h, tid);        // rows tid, tid+256
    attn_body<1>(base, Ks, Vs, b, h, tid + 512);  // row  tid+512
}

// ---------------- final weighted combine -> out = [gene | img] --------------
__global__ __launch_bounds__(256) void combine_kernel(
    const float* __restrict__ x1, const float* __restrict__ x2,
    float* __restrict__ out)
{
    int idx = blockIdx.x * 256 + threadIdx.x;
    const int GENE4 = Bb * N1c * Dc / 4;
    const int TOT4  = GENE4 + Bb * N2c * Dc / 4;
    if (idx >= TOT4) return;
    const float4* lf4 = (const float4*)d_lf;
    const float4* xo4 = (const float4*)d_xout;
    const float4* op4 = (const float4*)d_op;

    float4 r;
    if (idx < GENE4) {
        int d4 = idx & 63;
        int rem = idx >> 6;
        int p = rem & (N1c - 1);
        int b = rem >> 9;
        const float* w = &d_wts[b * 4];
        float4 g0 = lf4[(size_t)(b * Sc + p) * 64 + d4];
        float4 g1 = xo4[(size_t)(b * N1c + p) * 64 + d4];
        float4 g2 = op4[(size_t)(b * Sc + p) * 64 + d4];
        float4 g3 = ((const float4*)x1)[(size_t)(b * N1c + p) * 64 + d4];
        r.x = w[0] * g0.x + w[1] * g1.x + w[2] * g2.x + w[3] * g3.x;
        r.y = w[0] * g0.y + w[1] * g1.y + w[2] * g2.y + w[3] * g3.y;
        r.z = w[0] * g0.z + w[1] * g1.z + w[2] * g2.z + w[3] * g3.z;
        r.w = w[0] * g0.w + w[1] * g1.w + w[2] * g2.w + w[3] * g3.w;
    } else {
        int i2 = idx - GENE4;
        int d4 = i2 & 63;
        int rem = i2 >> 6;
        int s = rem & (N2c - 1);
        int b = rem >> 8;
        const float* w = &d_wts[b * 4];
        float4 v0 = lf4[(size_t)(b * Sc + N1c + s) * 64 + d4];
        float4 v1 = xo4[(size_t)(b * N1c + s) * 64 + d4];
        float4 v2 = op4[(size_t)(b * Sc + N1c + s) * 64 + d4];
        float4 v3 = ((const float4*)x2)[(size_t)(b * N2c + s) * 64 + d4];
        r.x = w[0] * v0.x + w[1] * v1.x + w[2] * v2.x + w[3] * v3.x;
        r.y = w[0] * v0.y + w[1] * v1.y + w[2] * v2.y + w[3] * v3.y;
        r.z = w[0] * v0.z + w[1] * v1.z + w[2] * v2.z + w[3] * v3.z;
        r.w = w[0] * v0.w + w[1] * v1.w + w[2] * v2.w + w[3] * v3.w;
    }
    ((float4*)out)[idx] = r;
}

// ---------------- launch ----------------------------------------------------
extern "C" void kernel_launch(void* const* d_in, const int* in_sizes, int n_in,
                              void* d_out, int out_size)
{
    const float* x1        = (const float*)d_in[0];
    const float* x2        = (const float*)d_in[1];
    const float* r_w1      = (const float*)d_in[2];
    const float* r_b1      = (const float*)d_in[3];
    const float* ln_g      = (const float*)d_in[4];
    const float* ln_b      = (const float*)d_in[5];
    const float* r_w2      = (const float*)d_in[6];
    const float* r_b2      = (const float*)d_in[7];
    const float* lf_w      = (const float*)d_in[8];
    const float* lf_b      = (const float*)d_in[9];
    const float* af2_w     = (const float*)d_in[10];
    const float* af2_b     = (const float*)d_in[11];
    const float* af3_w     = (const float*)d_in[12];
    const float* af3_b     = (const float*)d_in[13];
    const float* attn_in_w = (const float*)d_in[14];
    const float* attn_in_b = (const float*)d_in[15];
    const float* attn_out_w= (const float*)d_in[16];
    const float* attn_out_b= (const float*)d_in[17];
    float* out = (float*)d_out;

    float *qkv, *lf, *xout, *o, *op;
    cudaGetSymbolAddress((void**)&qkv,  d_qkv);
    cudaGetSymbolAddress((void**)&lf,   d_lf);
    cudaGetSymbolAddress((void**)&xout, d_xout);
    cudaGetSymbolAddress((void**)&o,    d_o);
    cudaGetSymbolAddress((void**)&op,   d_op);

    const int ATTN_SMEM = 2 * Sc * HDc * (int)sizeof(float);  // 196608
    cudaFuncSetAttribute(attn_kernel, cudaFuncAttributeMaxDynamicSharedMemorySize, ATTN_SMEM);

    const int BIGR = 1 << 30;

    // 1. router weights
    router_kernel<<<Bb, 256>>>(x1, x2, r_w1, r_b1, ln_g, ln_b, r_w2, r_b2);

    // 2. merged GEMMs with A = x1: qkv(6 n-blocks) | lf(2) | a1(2)
    {
        SegP s0 = { attn_in_w, attn_in_b, qkv, 3 * Dc, N1c, Sc, 0,   0 };
        SegP s1 = { lf_w,      lf_b,      lf,  Dc,     N1c, Sc, 0,   1 };
        SegP s2 = { af2_w,     af2_b,     xout,Dc,     BIGR, 0, 0,   1 };
        gemm_ms<<<dim3(10, 64), 256>>>(x1, Dc, s0, s1, s2, 6, 8);
    }
    // 3. merged GEMMs with A = x2: qkv(6) | lf(2)
    {
        SegP s0 = { attn_in_w, attn_in_b, qkv, 3 * Dc, N2c, Sc, N1c, 0 };
        SegP s1 = { lf_w,      lf_b,      lf,  Dc,     N2c, Sc, N1c, 1 };
        gemm_ms<<<dim3(8, 32), 256>>>(x2, Dc, s0, s1, s1, 6, 8);
    }

    // 4. xout += elu(af3_w @ x2[b] + af3_b)   (per-batch NN GEMM, row bias)
    gemm1<1, true, true, true><<<dim3(2, 2, Bb), 256>>>(
        af3_w, x2, af3_b, xout, N2c, Dc, Dc, BIGR, 0, 0,
        0, (size_t)N2c * Dc, (size_t)N1c * Dc);

    // 5. attention (reads d_qkv, writes d_o)
    attn_kernel<<<Bb * Hc, 256, ATTN_SMEM>>>();

    // 6. o @ attn_out_w.T + attn_out_b -> d_op
    gemm1<0, false, false, false><<<dim3(2, 96, 1), 256>>>(
        o, attn_out_w, attn_out_b, op, Dc, 0, Dc, BIGR, 0, 0, 0, 0, 0);

    // 7. weighted combine -> out
    combine_kernel<<<6144, 256>>>(x1, x2, out);
}

// round 4
// speedup vs baseline: 1.9562x; 1.1151x over previous
#include <cuda_runtime.h>
#include <math.h>

// Shapes (fixed by the problem)
#define Bb   32
#define N1c  512
#define N2c  256
#define Dc   256
#define Hc   8
#define HDc  32
#define Sc   768   // N1 + N2

typedef unsigned long long u64t;

// ---------------- f32x2 packed-FMA helpers ----------------------------------
__device__ __forceinline__ u64t pk2(float x, float y) {
    u64t r; asm("mov.b64 %0,{%1,%2};" : "=l"(r) : "f"(x), "f"(y)); return r;
}
__device__ __forceinline__ float2 upk(u64t v) {
    float2 r; asm("mov.b64 {%0,%1},%2;" : "=f"(r.x), "=f"(r.y) : "l"(v)); return r;
}
__device__ __forceinline__ void fma2(u64t& d, u64t a, u64t b) {
    asm("fma.rn.f32x2 %0,%1,%2,%0;" : "+l"(d) : "l"(a), "l"(b));
}
__device__ __forceinline__ u64t mul2(u64t a, u64t b) {
    u64t d; asm("mul.rn.f32x2 %0,%1,%2;" : "=l"(d) : "l"(a), "l"(b)); return d;
}
__device__ __forceinline__ u64t d2u(double d) { return __double_as_longlong(d); }

// ---------------- scratch (device globals; no allocations allowed) ----------
__device__ __align__(16) float d_qkv [Bb * Sc * 3 * Dc];
__device__ __align__(16) float d_lf  [Bb * Sc * Dc];
__device__ __align__(16) float d_xout[Bb * N1c * Dc];
__device__ __align__(16) float d_o   [Bb * Sc * Dc];
__device__ float d_wts [Bb * 4];

// ---------------- router ----------------------------------------------------
__global__ __launch_bounds__(256) void router_kernel(
    const float* __restrict__ x1, const float* __restrict__ x2,
    const float* __restrict__ r_w1, const float* __restrict__ r_b1,
    const float* __restrict__ ln_g, const float* __restrict__ ln_b,
    const float* __restrict__ r_w2, const float* __restrict__ r_b2)
{
    __shared__ float m[2 * Dc];
    __shared__ float4 ps[4][64];
    __shared__ float hb[Dc];
    __shared__ float red[8];
    __shared__ float lg[4];
    int b = blockIdx.x, t = threadIdx.x;
    int c4 = t & 63, rq = t >> 6;

    // ---- column means of x1[b] (float4, 4-way row split) ----
    {
        const float4* p = (const float4*)(x1 + (size_t)b * N1c * Dc) + (size_t)rq * 128 * 64 + c4;
        float4 s = make_float4(0.f, 0.f, 0.f, 0.f);
        for (int n = 0; n < 128; n++) {
            float4 v = p[(size_t)n * 64];
            s.x += v.x; s.y += v.y; s.z += v.z; s.w += v.w;
        }
        ps[rq][c4] = s;
    }
    __syncthreads();
    if (t < 64) {
        float4 a = ps[0][t], b1 = ps[1][t], c = ps[2][t], d = ps[3][t];
        m[t * 4 + 0] = (a.x + b1.x + c.x + d.x) * (1.f / N1c);
        m[t * 4 + 1] = (a.y + b1.y + c.y + d.y) * (1.f / N1c);
        m[t * 4 + 2] = (a.z + b1.z + c.z + d.z) * (1.f / N1c);
        m[t * 4 + 3] = (a.w + b1.w + c.w + d.w) * (1.f / N1c);
    }
    __syncthreads();
    // ---- column means of x2[b] ----
    {
        const float4* p = (const float4*)(x2 + (size_t)b * N2c * Dc) + (size_t)rq * 64 * 64 + c4;
        float4 s = make_float4(0.f, 0.f, 0.f, 0.f);
        for (int n = 0; n < 64; n++) {
            float4 v = p[(size_t)n * 64];
            s.x += v.x; s.y += v.y; s.z += v.z; s.w += v.w;
        }
        ps[rq][c4] = s;
    }
    __syncthreads();
    if (t < 64) {
        float4 a = ps[0][t], b1 = ps[1][t], c = ps[2][t], d = ps[3][t];
        m[Dc + t * 4 + 0] = (a.x + b1.x + c.x + d.x) * (1.f / N2c);
        m[Dc + t * 4 + 1] = (a.y + b1.y + c.y + d.y) * (1.f / N2c);
        m[Dc + t * 4 + 2] = (a.z + b1.z + c.z + d.z) * (1.f / N2c);
        m[Dc + t * 4 + 3] = (a.w + b1.w + c.w + d.w) * (1.f / N2c);
    }
    __syncthreads();

    float acc = r_b1[t];
    const float* wr = r_w1 + (size_t)t * (2 * Dc);
    #pragma unroll 4
    for (int k = 0; k < 2 * Dc; k++) acc += m[k] * wr[k];

    float v = acc;
    for (int o = 16; o; o >>= 1) v += __shfl_down_sync(0xffffffffu, v, o);
    if ((t & 31) == 0) red[t >> 5] = v;
    __syncthreads();
    if (t < 8) {
        v = red[t];
        for (int o = 4; o; o >>= 1) v += __shfl_down_sync(0xffu, v, o);
        if (t == 0) red[0] = v;
    }
    __syncthreads();
    float mu = red[0] * (1.f / Dc);
    __syncthreads();
    float dd = acc - mu;
    v = dd * dd;
    for (int o = 16; o; o >>= 1) v += __shfl_down_sync(0xffffffffu, v, o);
    if ((t & 31) == 0) red[t >> 5] = v;
    __syncthreads();
    if (t < 8) {
        v = red[t];
        for (int o = 4; o; o >>= 1) v += __shfl_down_sync(0xffu, v, o);
        if (t == 0) red[0] = v;
    }
    __syncthreads();
    float var = red[0] * (1.f / Dc);
    float y = dd * rsqrtf(var + 1e-5f) * ln_g[t] + ln_b[t];
    float g = 0.5f * y * (1.f + erff(y * 0.70710678118654752f));
    hb[t] = g;
    __syncthreads();

    if (t < 4) {
        float a = r_b2[t];
        const float* w2 = r_w2 + (size_t)t * Dc;
        for (int k = 0; k < Dc; k++) a += hb[k] * w2[k];
        lg[t] = a;
    }
    __syncthreads();
    if (t == 0) {
        float mx = fmaxf(fmaxf(lg[0], lg[1]), fmaxf(lg[2], lg[3]));
        float e0 = expf(lg[0] - mx), e1 = expf(lg[1] - mx);
        float e2 = expf(lg[2] - mx), e3 = expf(lg[3] - mx);
        float inv = 1.f / (e0 + e1 + e2 + e3);
        d_wts[b * 4 + 0] = e0 * inv; d_wts[b * 4 + 1] = e1 * inv;
        d_wts[b * 4 + 2] = e2 * inv; d_wts[b * 4 + 3] = e3 * inv;
    }
}

// ---------------- GEMM mainloop: BM=128, BN=128, BK=16, 8x8 tile ------------
// Double-buffered. acc: 4 u64 pairs (M) x 8 (N).
// BT=false: W is [N,K] row-major. BT=true: W is [K,N] row-major, ldB = N stride.
typedef float SmemA[2][16][128];

template<bool BT>
__device__ __forceinline__ void gemm_mainloop(
    SmemA& As, SmemA& Bs,
    const float* __restrict__ A, const float* __restrict__ W,
    int K, int ldB, int m0, int n0, u64t (&acc)[4][8])
{
    const int tid = threadIdx.x;
    const int tx = tid & 15, ty = tid >> 4;
    const int ar = tid >> 1, ac = (tid & 1) * 8;

    #pragma unroll
    for (int i = 0; i < 4; i++)
        #pragma unroll
        for (int j = 0; j < 8; j++) acc[i][j] = 0ull;

    const float* aP = A + (size_t)(m0 + ar) * K + ac;
    const float* bP;
    if (BT) bP = W + (size_t)(tid >> 4) * ldB + n0 + (tid & 15) * 8;
    else    bP = W + (size_t)(n0 + ar) * K + ac;

    float4 a0, a1, b0, b1;
    a0 = *(const float4*)(aP);
    a1 = *(const float4*)(aP + 4);
    b0 = *(const float4*)(bP);
    b1 = *(const float4*)(bP + 4);

    {
        As[0][ac + 0][ar] = a0.x; As[0][ac + 1][ar] = a0.y;
        As[0][ac + 2][ar] = a0.z; As[0][ac + 3][ar] = a0.w;
        As[0][ac + 4][ar] = a1.x; As[0][ac + 5][ar] = a1.y;
        As[0][ac + 6][ar] = a1.z; As[0][ac + 7][ar] = a1.w;
        if (BT) {
            *(float4*)&Bs[0][tid >> 4][(tid & 15) * 8] = b0;
            *(float4*)&Bs[0][tid >> 4][(tid & 15) * 8 + 4] = b1;
        } else {
            Bs[0][ac + 0][ar] = b0.x; Bs[0][ac + 1][ar] = b0.y;
            Bs[0][ac + 2][ar] = b0.z; Bs[0][ac + 3][ar] = b0.w;
            Bs[0][ac + 4][ar] = b1.x; Bs[0][ac + 5][ar] = b1.y;
            Bs[0][ac + 6][ar] = b1.z; Bs[0][ac + 7][ar] = b1.w;
        }
    }
    __syncthreads();

    int buf = 0;
    for (int k0 = 0; k0 < K; k0 += 16) {
        int kn = k0 + 16;
        bool more = kn < K;
        if (more) {
            a0 = *(const float4*)(aP + kn);
            a1 = *(const float4*)(aP + kn + 4);
            if (BT) {
                b0 = *(const float4*)(bP + (size_t)kn * ldB);
                b1 = *(const float4*)(bP + (size_t)kn * ldB + 4);
            } else {
                b0 = *(const float4*)(bP + kn);
                b1 = *(const float4*)(bP + kn + 4);
            }
        }
        #pragma unroll
        for (int kk = 0; kk < 16; kk++) {
            const double2* ap2 = (const double2*)&As[buf][kk][ty * 8];
            double2 da = ap2[0], db = ap2[1];
            u64t ap[4] = { d2u(da.x), d2u(da.y), d2u(db.x), d2u(db.y) };
            const float4* bp4 = (const float4*)&Bs[buf][kk][tx * 8];
            float4 f0 = bp4[0], f1 = bp4[1];
            u64t bb[8] = { pk2(f0.x, f0.x), pk2(f0.y, f0.y), pk2(f0.z, f0.z), pk2(f0.w, f0.w),
                           pk2(f1.x, f1.x), pk2(f1.y, f1.y), pk2(f1.z, f1.z), pk2(f1.w, f1.w) };
            #pragma unroll
            for (int i = 0; i < 4; i++)
                #pragma unroll
                for (int j = 0; j < 8; j++) fma2(acc[i][j], ap[i], bb[j]);
        }
        if (more) {
            int nb = buf ^ 1;
            As[nb][ac + 0][ar] = a0.x; As[nb][ac + 1][ar] = a0.y;
            As[nb][ac + 2][ar] = a0.z; As[nb][ac + 3][ar] = a0.w;
            As[nb][ac + 4][ar] = a1.x; As[nb][ac + 5][ar] = a1.y;
            As[nb][ac + 6][ar] = a1.z; As[nb][ac + 7][ar] = a1.w;
            if (BT) {
                *(float4*)&Bs[nb][tid >> 4][(tid & 15) * 8] = b0;
                *(float4*)&Bs[nb][tid >> 4][(tid & 15) * 8 + 4] = b1;
            } else {
                Bs[nb][ac + 0][ar] = b0.x; Bs[nb][ac + 1][ar] = b0.y;
                Bs[nb][ac + 2][ar] = b0.z; Bs[nb][ac + 3][ar] = b0.w;
                Bs[nb][ac + 4][ar] = b1.x; Bs[nb][ac + 5][ar] = b1.y;
                Bs[nb][ac + 6][ar] = b1.z; Bs[nb][ac + 7][ar] = b1.w;
            }
        }
        __syncthreads();
        buf ^= 1;
    }
}

// ---------------- standard epilogue -----------------------------------------
template<bool ACCUM, bool RB>
__device__ __forceinline__ void epilogue_std(
    u64t (&acc)[4][8], const float* __restrict__ bias, float* __restrict__ C,
    int ldC, int m0, int n0, int rpb, int ostride, int ooff, int act)
{
    const int tx = threadIdx.x & 15, ty = threadIdx.x >> 4;
    int cb = n0 + tx * 8;
    float bj[8];
    if (!RB) {
        float4 b0v = *(const float4*)(bias + cb);
        float4 b1v = *(const float4*)(bias + cb + 4);
        bj[0] = b0v.x; bj[1] = b0v.y; bj[2] = b0v.z; bj[3] = b0v.w;
        bj[4] = b1v.x; bj[5] = b1v.y; bj[6] = b1v.z; bj[7] = b1v.w;
    }
    #pragma unroll
    for (int i2 = 0; i2 < 4; i2++) {
        float vl[8], vh[8];
        #pragma unroll
        for (int j = 0; j < 8; j++) {
            float2 p = upk(acc[i2][j]);
            vl[j] = p.x; vh[j] = p.y;
        }
        #pragma unroll
        for (int hh = 0; hh < 2; hh++) {
            float* v = hh ? vh : vl;
            int r = m0 + ty * 8 + i2 * 2 + hh;
            float rb = RB ? bias[r] : 0.f;
            int grow = (r / rpb) * ostride + ooff + (r % rpb);
            float o8[8];
            #pragma unroll
            for (int j = 0; j < 8; j++) {
                float x = v[j] + (RB ? rb : bj[j]);
                if (act) x = x > 0.f ? x : expm1f(x);
                o8[j] = x;
            }
            float* dst = C + (size_t)grow * ldC + cb;
            if (ACCUM) {
                float4 c0 = *(float4*)dst, c1 = *(float4*)(dst + 4);
                o8[0] += c0.x; o8[1] += c0.y; o8[2] += c0.z; o8[3] += c0.w;
                o8[4] += c1.x; o8[5] += c1.y; o8[6] += c1.z; o8[7] += c1.w;
            }
            *(float4*)dst       = make_float4(o8[0], o8[1], o8[2], o8[3]);
            *(float4*)(dst + 4) = make_float4(o8[4], o8[5], o8[6], o8[7]);
        }
    }
}

// ---------------- segmented multi-output GEMM (shared A) --------------------
struct SegP {
    const float* W; const float* bias; float* C;
    int ldC; int rpb; int ostride; int ooff; int act;
};

__global__ __launch_bounds__(256, 2) void gemm_ms(
    const float* __restrict__ A, int K,
    SegP s0, SegP s1, SegP s2, int t1, int t2)
{
    __shared__ __align__(16) float As[2][16][128];
    __shared__ __align__(16) float Bs[2][16][128];
    int bx = blockIdx.x;
    SegP sp; int nb;
    if (bx < t1)      { sp = s0; nb = bx; }
    else if (bx < t2) { sp = s1; nb = bx - t1; }
    else              { sp = s2; nb = bx - t2; }
    u64t acc[4][8];
    gemm_mainloop<false>(As, Bs, A, sp.W, K, 0, blockIdx.y * 128, nb * 128, acc);
    epilogue_std<false, false>(acc, sp.bias, sp.C, sp.ldC,
        blockIdx.y * 128, nb * 128, sp.rpb, sp.ostride, sp.ooff, sp.act);
}

// ---------------- standalone (batched) GEMM ---------------------------------
template<int ACT, bool BT, bool ACCUM, bool RB>
__global__ __launch_bounds__(256, 2) void gemm1(
    const float* __restrict__ A, const float* __restrict__ W,
    const float* __restrict__ bias, float* __restrict__ C,
    int K, int ldB, int ldC, int rpb, int ostride, int ooff,
    size_t aB, size_t bB, size_t cB)
{
    __shared__ __align__(16) float As[2][16][128];
    __shared__ __align__(16) float Bs[2][16][128];
    int bz = blockIdx.z;
    u64t acc[4][8];
    gemm_mainloop<BT>(As, Bs, A + (size_t)bz * aB, W + (size_t)bz * bB,
                      K, ldB, blockIdx.y * 128, blockIdx.x * 128, acc);
    epilogue_std<ACCUM, RB>(acc, bias, C + (size_t)bz * cB, ldC,
        blockIdx.y * 128, blockIdx.x * 128, rpb, ostride, ooff, ACT);
}

// ---------------- final GEMM: attn_out + weighted combine fused -------------
__global__ __launch_bounds__(256, 2) void gemm_final(
    const float* __restrict__ W, const float* __restrict__ bias,
    const float* __restrict__ x1, const float* __restrict__ x2,
    float* __restrict__ out)
{
    __shared__ __align__(16) float As[2][16][128];
    __shared__ __align__(16) float Bs[2][16][128];
    int m0 = blockIdx.y * 128, n0 = blockIdx.x * 128;
    u64t acc[4][8];
    gemm_mainloop<false>(As, Bs, d_o, W, Dc, 0, m0, n0, acc);

    const int tx = threadIdx.x & 15, ty = threadIdx.x >> 4;
    int cb = n0 + tx * 8;
    float4 b0v = *(const float4*)(bias + cb);
    float4 b1v = *(const float4*)(bias + cb + 4);
    float bj[8] = { b0v.x, b0v.y, b0v.z, b0v.w, b1v.x, b1v.y, b1v.z, b1v.w };

    #pragma unroll
    for (int i2 = 0; i2 < 4; i2++) {
        float vl[8], vh[8];
        #pragma unroll
        for (int j = 0; j < 8; j++) {
            float2 p = upk(acc[i2][j]);
            vl[j] = p.x; vh[j] = p.y;
        }
        #pragma unroll
        for (int hh = 0; hh < 2; hh++) {
            float* v = hh ? vh : vl;
            int r = m0 + ty * 8 + i2 * 2 + hh;
            int b = r / Sc;
            int s = r - b * Sc;
            const float* w = d_wts + b * 4;
            float w0 = w[0], w1 = w[1], w2 = w[2], w3 = w[3];
            const float* lfr = d_lf + (size_t)r * Dc + cb;
            const float* xo; const float* xv; float* dst;
            if (s < N1c) {
                size_t rr = (size_t)b * N1c + s;
                xo = d_xout + rr * Dc + cb;
                xv = x1 + rr * Dc + cb;
                dst = out + rr * Dc + cb;
            } else {
                int s2 = s - N1c;
                xo = d_xout + ((size_t)b * N1c + s2) * Dc + cb;
                xv = x2 + ((size_t)b * N2c + s2) * Dc + cb;
                dst = out + (size_t)Bb * N1c * Dc + ((size_t)b * N2c + s2) * Dc + cb;
            }
            float4 l0 = *(const float4*)lfr,       l1 = *(const float4*)(lfr + 4);
            float4 g0 = *(const float4*)xo,        g1 = *(const float4*)(xo + 4);
            float4 y0 = *(const float4*)xv,        y1 = *(const float4*)(xv + 4);
            float lf8[8] = { l0.x, l0.y, l0.z, l0.w, l1.x, l1.y, l1.z, l1.w };
            float xo8[8] = { g0.x, g0.y, g0.z, g0.w, g1.x, g1.y, g1.z, g1.w };
            float xv8[8] = { y0.x, y0.y, y0.z, y0.w, y1.x, y1.y, y1.z, y1.w };
            float o8[8];
            #pragma unroll
            for (int j = 0; j < 8; j++) {
                float op = v[j] + bj[j];
                o8[j] = w0 * lf8[j] + w1 * xo8[j] + w2 * op + w3 * xv8[j];
            }
            *(float4*)dst       = make_float4(o8[0], o8[1], o8[2], o8[3]);
            *(float4*)(dst + 4) = make_float4(o8[4], o8[5], o8[6], o8[7]);
        }
    }
}

// ---------------- attention: one block per (b,h); NR=3 single pass ----------
__global__ __launch_bounds__(256, 1) void attn_kernel()
{
    extern __shared__ float sm[];
    float* Ks = sm;               // Sc * 32
    float* Vs = sm + Sc * HDc;    // Sc * 32
    int bh = blockIdx.x;
    int b = bh >> 3;
    int h = bh & 7;
    int tid = threadIdx.x;
    const float* base = d_qkv + (size_t)b * Sc * (3 * Dc);

    for (int i = tid; i < Sc * 8; i += 256) {
        int s = i >> 3, d4 = i & 7;
        const float* row = base + (size_t)s * (3 * Dc) + h * HDc + d4 * 4;
        *(float4*)&Ks[s * HDc + d4 * 4] = *(const float4*)(row + Dc);
        *(float4*)&Vs[s * HDc + d4 * 4] = *(const float4*)(row + 2 * Dc);
    }
    __syncthreads();

    const float scale = 0.17677669529663688f;  // 1/sqrt(32)
    u64t sc2 = pk2(scale, scale);

    u64t q[3][16], acc[3][16];
    float l[3];
    #pragma unroll
    for (int r = 0; r < 3; r++) {
        const double2* qp = (const double2*)(base + (size_t)(tid + r * 256) * (3 * Dc) + h * HDc);
        #pragma unroll
        for (int i = 0; i < 8; i++) {
            double2 qd = qp[i];
            q[r][2 * i]     = mul2(d2u(qd.x), sc2);
            q[r][2 * i + 1] = mul2(d2u(qd.y), sc2);
        }
        #pragma unroll
        for (int i = 0; i < 16; i++) acc[r][i] = 0ull;
        l[r] = 0.f;
    }

    for (int s = 0; s < Sc; s++) {
        const double2* kp = (const double2*)&Ks[s * HDc];
        u64t t0[3] = { 0ull, 0ull, 0ull };
        #pragma unroll
        for (int i = 0; i < 8; i++) {
            double2 kd = kp[i];
            u64t ka = d2u(kd.x), kb = d2u(kd.y);
            #pragma unroll
            for (int r = 0; r < 3; r++) {
                fma2(t0[r], q[r][2 * i],     ka);
                fma2(t0[r], q[r][2 * i + 1], kb);
            }
        }
        u64t pb[3];
        #pragma unroll
        for (int r = 0; r < 3; r++) {
            float2 f = upk(t0[r]);
            float p = __expf(f.x + f.y);
            l[r] += p;
            pb[r] = pk2(p, p);
        }
        const double2* vp = (const double2*)&Vs[s * HDc];
        #pragma unroll
        for (int i = 0; i < 8; i++) {
            double2 vd = vp[i];
            u64t va = d2u(vd.x), vb = d2u(vd.y);
            #pragma unroll
            for (int r = 0; r < 3; r++) {
                fma2(acc[r][2 * i],     pb[r], va);
                fma2(acc[r][2 * i + 1], pb[r], vb);
            }
        }
    }
    #pragma unroll
    for (int r = 0; r < 3; r++) {
        float inv = 1.f / l[r];
        float* op = d_o + ((size_t)(b * Sc + tid + r * 256)) * Dc + h * HDc;
        #pragma unroll
        for (int i = 0; i < 8; i++) {
            float2 ra = upk(acc[r][2 * i]);
            float2 rb = upk(acc[r][2 * i + 1]);
            *(float4*)(op + i * 4) = make_float4(ra.x * inv, ra.y * inv, rb.x * inv, rb.y * inv);
        }
    }
}

// ---------------- launch ----------------------------------------------------
extern "C" void kernel_launch(void* const* d_in, const int* in_sizes, int n_in,
                              void* d_out, int out_size)
{
    const float* x1        = (const float*)d_in[0];
    const float* x2        = (const float*)d_in[1];
    const float* r_w1      = (const float*)d_in[2];
    const float* r_b1      = (const float*)d_in[3];
    const float* ln_g      = (const float*)d_in[4];
    const float* ln_b      = (const float*)d_in[5];
    const float* r_w2      = (const float*)d_in[6];
    const float* r_b2      = (const float*)d_in[7];
    const float* lf_w      = (const float*)d_in[8];
    const float* lf_b      = (const float*)d_in[9];
    const float* af2_w     = (const float*)d_in[10];
    const float* af2_b     = (const float*)d_in[11];
    const float* af3_w     = (const float*)d_in[12];
    const float* af3_b     = (const float*)d_in[13];
    const float* attn_in_w = (const float*)d_in[14];
    const float* attn_in_b = (const float*)d_in[15];
    const float* attn_out_w= (const float*)d_in[16];
    const float* attn_out_b= (const float*)d_in[17];
    float* out = (float*)d_out;

    float *qkv, *lf, *xout;
    cudaGetSymbolAddress((void**)&qkv,  d_qkv);
    cudaGetSymbolAddress((void**)&lf,   d_lf);
    cudaGetSymbolAddress((void**)&xout, d_xout);

    const int ATTN_SMEM = 2 * Sc * HDc * (int)sizeof(float);  // 196608
    cudaFuncSetAttribute(attn_kernel, cudaFuncAttributeMaxDynamicSharedMemorySize, ATTN_SMEM);

    const int BIGR = 1 << 30;

    // 1. router weights
    router_kernel<<<Bb, 256>>>(x1, x2, r_w1, r_b1, ln_g, ln_b, r_w2, r_b2);

    // 2. merged GEMMs with A = x1: qkv(6 n-blocks) | lf(2) | a1(2)
    {
        SegP s0 = { attn_in_w, attn_in_b, qkv, 3 * Dc, N1c, Sc, 0,   0 };
        SegP s1 = { lf_w,      lf_b,      lf,  Dc,     N1c, Sc, 0,   1 };
        SegP s2 = { af2_w,     af2_b,     xout,Dc,     BIGR, 0, 0,   1 };
        gemm_ms<<<dim3(10, 128), 256>>>(x1, Dc, s0, s1, s2, 6, 8);
    }
    // 3. merged GEMMs with A = x2: qkv(6) | lf(2)
    {
        SegP s0 = { attn_in_w, attn_in_b, qkv, 3 * Dc, N2c, Sc, N1c, 0 };
        SegP s1 = { lf_w,      lf_b,      lf,  Dc,     N2c, Sc, N1c, 1 };
        gemm_ms<<<dim3(8, 64), 256>>>(x2, Dc, s0, s1, s1, 6, 8);
    }

    // 4. xout += elu(af3_w @ x2[b] + af3_b)   (per-batch NN GEMM, row bias)
    gemm1<1, true, true, true><<<dim3(2, 4, Bb), 256>>>(
        af3_w, x2, af3_b, xout, N2c, Dc, Dc, BIGR, 0, 0,
        0, (size_t)N2c * Dc, (size_t)N1c * Dc);

    // 5. attention (reads d_qkv, writes d_o)
    attn_kernel<<<Bb * Hc, 256, ATTN_SMEM>>>();

    // 6. fused: (d_o @ attn_out_w.T + b) combined with lf/xout/x -> out
    gemm_final<<<dim3(2, 192), 256>>>(attn_out_w, attn_out_b, x1, x2, out);
}

// round 5
// speedup vs baseline: 2.5346x; 1.2957x over previous
#include <cuda_runtime.h>
#include <math.h>

// Shapes (fixed by the problem)
#define Bb   32
#define N1c  512
#define N2c  256
#define Dc   256
#define Hc   8
#define HDc  32
#define Sc   768   // N1 + N2

typedef unsigned long long u64t;

// ---------------- f32x2 packed-FMA helpers (attention) -----------------------
__device__ __forceinline__ u64t pk2(float x, float y) {
    u64t r; asm("mov.b64 %0,{%1,%2};" : "=l"(r) : "f"(x), "f"(y)); return r;
}
__device__ __forceinline__ float2 upk(u64t v) {
    float2 r; asm("mov.b64 {%0,%1},%2;" : "=f"(r.x), "=f"(r.y) : "l"(v)); return r;
}
__device__ __forceinline__ void fma2(u64t& d, u64t a, u64t b) {
    asm("fma.rn.f32x2 %0,%1,%2,%0;" : "+l"(d) : "l"(a), "l"(b));
}
__device__ __forceinline__ u64t mul2(u64t a, u64t b) {
    u64t d; asm("mul.rn.f32x2 %0,%1,%2;" : "=l"(d) : "l"(a), "l"(b)); return d;
}
__device__ __forceinline__ u64t d2u(double d) { return __double_as_longlong(d); }

// ---------------- tf32 helpers ----------------------------------------------
__device__ __forceinline__ float tf32f(float x) {
    unsigned r; asm("cvt.rna.tf32.f32 %0,%1;" : "=r"(r) : "f"(x));
    return __uint_as_float(r);
}
__device__ __forceinline__ void mma_tf32(float (&c)[4], const unsigned (&a)[4],
                                         const unsigned (&b)[2]) {
    asm("mma.sync.aligned.m16n8k8.row.col.f32.tf32.tf32.f32 "
        "{%0,%1,%2,%3},{%4,%5,%6,%7},{%8,%9},{%0,%1,%2,%3};"
        : "+f"(c[0]), "+f"(c[1]), "+f"(c[2]), "+f"(c[3])
        : "r"(a[0]), "r"(a[1]), "r"(a[2]), "r"(a[3]), "r"(b[0]), "r"(b[1]));
}

// ---------------- scratch (device globals; no allocations allowed) ----------
__device__ __align__(16) float d_qkv [Bb * Sc * 3 * Dc];
__device__ __align__(16) float d_lf  [Bb * Sc * Dc];
__device__ __align__(16) float d_xout[Bb * N1c * Dc];
__device__ __align__(16) float d_o   [Bb * Sc * Dc];
__device__ float d_wts [Bb * 4];

// ---------------- router ----------------------------------------------------
__global__ __launch_bounds__(256) void router_kernel(
    const float* __restrict__ x1, const float* __restrict__ x2,
    const float* __restrict__ r_w1, const float* __restrict__ r_b1,
    const float* __restrict__ ln_g, const float* __restrict__ ln_b,
    const float* __restrict__ r_w2, const float* __restrict__ r_b2)
{
    __shared__ float m[2 * Dc];
    __shared__ float4 ps[4][64];
    __shared__ float hb[Dc];
    __shared__ float red[8];
    __shared__ float lg[4];
    int b = blockIdx.x, t = threadIdx.x;
    int c4 = t & 63, rq = t >> 6;

    {
        const float4* p = (const float4*)(x1 + (size_t)b * N1c * Dc) + (size_t)rq * 128 * 64 + c4;
        float4 s = make_float4(0.f, 0.f, 0.f, 0.f);
        for (int n = 0; n < 128; n++) {
            float4 v = p[(size_t)n * 64];
            s.x += v.x; s.y += v.y; s.z += v.z; s.w += v.w;
        }
        ps[rq][c4] = s;
    }
    __syncthreads();
    if (t < 64) {
        float4 a = ps[0][t], b1 = ps[1][t], c = ps[2][t], d = ps[3][t];
        m[t * 4 + 0] = (a.x + b1.x + c.x + d.x) * (1.f / N1c);
        m[t * 4 + 1] = (a.y + b1.y + c.y + d.y) * (1.f / N1c);
        m[t * 4 + 2] = (a.z + b1.z + c.z + d.z) * (1.f / N1c);
        m[t * 4 + 3] = (a.w + b1.w + c.w + d.w) * (1.f / N1c);
    }
    __syncthreads();
    {
        const float4* p = (const float4*)(x2 + (size_t)b * N2c * Dc) + (size_t)rq * 64 * 64 + c4;
        float4 s = make_float4(0.f, 0.f, 0.f, 0.f);
        for (int n = 0; n < 64; n++) {
            float4 v = p[(size_t)n * 64];
            s.x += v.x; s.y += v.y; s.z += v.z; s.w += v.w;
        }
        ps[rq][c4] = s;
    }
    __syncthreads();
    if (t < 64) {
        float4 a = ps[0][t], b1 = ps[1][t], c = ps[2][t], d = ps[3][t];
        m[Dc + t * 4 + 0] = (a.x + b1.x + c.x + d.x) * (1.f / N2c);
        m[Dc + t * 4 + 1] = (a.y + b1.y + c.y + d.y) * (1.f / N2c);
        m[Dc + t * 4 + 2] = (a.z + b1.z + c.z + d.z) * (1.f / N2c);
        m[Dc + t * 4 + 3] = (a.w + b1.w + c.w + d.w) * (1.f / N2c);
    }
    __syncthreads();

    float acc = r_b1[t];
    const float* wr = r_w1 + (size_t)t * (2 * Dc);
    #pragma unroll 4
    for (int k = 0; k < 2 * Dc; k++) acc += m[k] * wr[k];

    float v = acc;
    for (int o = 16; o; o >>= 1) v += __shfl_down_sync(0xffffffffu, v, o);
    if ((t & 31) == 0) red[t >> 5] = v;
    __syncthreads();
    if (t < 8) {
        v = red[t];
        for (int o = 4; o; o >>= 1) v += __shfl_down_sync(0xffu, v, o);
        if (t == 0) red[0] = v;
    }
    __syncthreads();
    float mu = red[0] * (1.f / Dc);
    __syncthreads();
    float dd = acc - mu;
    v = dd * dd;
    for (int o = 16; o; o >>= 1) v += __shfl_down_sync(0xffffffffu, v, o);
    if ((t & 31) == 0) red[t >> 5] = v;
    __syncthreads();
    if (t < 8) {
        v = red[t];
        for (int o = 4; o; o >>= 1) v += __shfl_down_sync(0xffu, v, o);
        if (t == 0) red[0] = v;
    }
    __syncthreads();
    float var = red[0] * (1.f / Dc);
    float y = dd * rsqrtf(var + 1e-5f) * ln_g[t] + ln_b[t];
    float g = 0.5f * y * (1.f + erff(y * 0.70710678118654752f));
    hb[t] = g;
    __syncthreads();

    if (t < 4) {
        float a = r_b2[t];
        const float* w2 = r_w2 + (size_t)t * Dc;
        for (int k = 0; k < Dc; k++) a += hb[k] * w2[k];
        lg[t] = a;
    }
    __syncthreads();
    if (t == 0) {
        float mx = fmaxf(fmaxf(lg[0], lg[1]), fmaxf(lg[2], lg[3]));
        float e0 = expf(lg[0] - mx), e1 = expf(lg[1] - mx);
        float e2 = expf(lg[2] - mx), e3 = expf(lg[3] - mx);
        float inv = 1.f / (e0 + e1 + e2 + e3);
        d_wts[b * 4 + 0] = e0 * inv; d_wts[b * 4 + 1] = e1 * inv;
        d_wts[b * 4 + 2] = e2 * inv; d_wts[b * 4 + 3] = e3 * inv;
    }
}

// ---------------- tf32 MMA GEMM: BM=128, BN=128, BK=16 ----------------------
// 8 warps: warp tile 32(M) x 64(N) -> 2 m16 frags x 8 n8 frags.
// Smem: [k][m or n] with row pad 136 (stride = 8 mod 32 -> conflict-free frag LDS.32).
// BT=false: W is [N,K] row-major.  BT=true: W is [K,N] row-major (ldB = row stride).
typedef float SmemT[2][16][136];

template<bool BT>
__device__ __forceinline__ void mma_mainloop(
    SmemT& As, SmemT& Bs,
    const float* __restrict__ A, const float* __restrict__ W,
    int K, int ldB, int m0, int n0, float (&acc)[2][8][4])
{
    const int tid = threadIdx.x, lane = tid & 31, warp = tid >> 5;
    const int wm = warp >> 1, wn = warp & 1;
    const int gid = lane >> 2, tig = lane & 3;
    const int ar = tid >> 1, ac = (tid & 1) * 8;

    #pragma unroll
    for (int i = 0; i < 2; i++)
        #pragma unroll
        for (int j = 0; j < 8; j++)
            #pragma unroll
            for (int c = 0; c < 4; c++) acc[i][j][c] = 0.f;

    const float* aP = A + (size_t)(m0 + ar) * K + ac;
    const float* bP;
    if (BT) bP = W + (size_t)(tid >> 4) * ldB + n0 + (tid & 15) * 8;
    else    bP = W + (size_t)(n0 + ar) * K + ac;

    float4 a0v, a1v, b0v, b1v;
    a0v = *(const float4*)aP;       a1v = *(const float4*)(aP + 4);
    b0v = *(const float4*)bP;       b1v = *(const float4*)(bP + 4);

    // stage tile 0
    {
        float av[8] = { a0v.x, a0v.y, a0v.z, a0v.w, a1v.x, a1v.y, a1v.z, a1v.w };
        #pragma unroll
        for (int j = 0; j < 8; j++) As[0][ac + j][ar] = tf32f(av[j]);
        float bv[8] = { b0v.x, b0v.y, b0v.z, b0v.w, b1v.x, b1v.y, b1v.z, b1v.w };
        if (BT) {
            int kr = tid >> 4, nc = (tid & 15) * 8;
            #pragma unroll
            for (int j = 0; j < 8; j++) Bs[0][kr][nc + j] = tf32f(bv[j]);
        } else {
            #pragma unroll
            for (int j = 0; j < 8; j++) Bs[0][ac + j][ar] = tf32f(bv[j]);
        }
    }
    __syncthreads();

    int buf = 0;
    for (int k0 = 0; k0 < K; k0 += 16) {
        int kn = k0 + 16;
        bool more = kn < K;
        if (more) {
            a0v = *(const float4*)(aP + kn);
            a1v = *(const float4*)(aP + kn + 4);
            if (BT) {
                b0v = *(const float4*)(bP + (size_t)kn * ldB);
                b1v = *(const float4*)(bP + (size_t)kn * ldB + 4);
            } else {
                b0v = *(const float4*)(bP + kn);
                b1v = *(const float4*)(bP + kn + 4);
            }
        }
        #pragma unroll
        for (int ks = 0; ks < 16; ks += 8) {
            unsigned af[2][4], bf[8][2];
            #pragma unroll
            for (int mt = 0; mt < 2; mt++) {
                int mb = wm * 32 + mt * 16 + gid;
                af[mt][0] = __float_as_uint(As[buf][ks + tig][mb]);
                af[mt][1] = __float_as_uint(As[buf][ks + tig][mb + 8]);
                af[mt][2] = __float_as_uint(As[buf][ks + tig + 4][mb]);
                af[mt][3] = __float_as_uint(As[buf][ks + tig + 4][mb + 8]);
            }
            #pragma unroll
            for (int nt = 0; nt < 8; nt++) {
                int nb = wn * 64 + nt * 8 + gid;
                bf[nt][0] = __float_as_uint(Bs[buf][ks + tig][nb]);
                bf[nt][1] = __float_as_uint(Bs[buf][ks + tig + 4][nb]);
            }
            #pragma unroll
            for (int mt = 0; mt < 2; mt++)
                #pragma unroll
                for (int nt = 0; nt < 8; nt++)
                    mma_tf32(acc[mt][nt], af[mt], bf[nt]);
        }
        if (more) {
            int nb2 = buf ^ 1;
            float av[8] = { a0v.x, a0v.y, a0v.z, a0v.w, a1v.x, a1v.y, a1v.z, a1v.w };
            #pragma unroll
            for (int j = 0; j < 8; j++) As[nb2][ac + j][ar] = tf32f(av[j]);
            float bv[8] = { b0v.x, b0v.y, b0v.z, b0v.w, b1v.x, b1v.y, b1v.z, b1v.w };
            if (BT) {
                int kr = tid >> 4, nc = (tid & 15) * 8;
                #pragma unroll
                for (int j = 0; j < 8; j++) Bs[nb2][kr][nc + j] = tf32f(bv[j]);
            } else {
                #pragma unroll
                for (int j = 0; j < 8; j++) Bs[nb2][ac + j][ar] = tf32f(bv[j]);
            }
        }
        __syncthreads();
        buf ^= 1;
    }
}

// ---------------- standard epilogue (fragment layout) ------------------------
template<bool ACCUM, bool RB>
__device__ __forceinline__ void epi_std(
    float (&acc)[2][8][4], const float* __restrict__ bias, float* __restrict__ C,
    int ldC, int m0, int n0, int rpb, int ostride, int ooff, int act)
{
    const int tid = threadIdx.x, lane = tid & 31, warp = tid >> 5;
    const int wm = warp >> 1, wn = warp & 1;
    const int gid = lane >> 2, tig = lane & 3;

    #pragma unroll
    for (int mt = 0; mt < 2; mt++) {
        #pragma unroll
        for (int rh = 0; rh < 2; rh++) {
            int r = m0 + wm * 32 + mt * 16 + gid + rh * 8;
            float rbv = RB ? bias[r] : 0.f;
            int grow = (r / rpb) * ostride + ooff + (r % rpb);
            float* dst = C + (size_t)grow * ldC;
            #pragma unroll
            for (int nt = 0; nt < 8; nt++) {
                int col = n0 + wn * 64 + nt * 8 + tig * 2;
                float v0 = acc[mt][nt][rh * 2 + 0];
                float v1 = acc[mt][nt][rh * 2 + 1];
                if (RB) { v0 += rbv; v1 += rbv; }
                else {
                    float2 bc = *(const float2*)(bias + col);
                    v0 += bc.x; v1 += bc.y;
                }
                if (act) {
                    v0 = v0 > 0.f ? v0 : expm1f(v0);
                    v1 = v1 > 0.f ? v1 : expm1f(v1);
                }
                if (ACCUM) {
                    float2 c = *(float2*)(dst + col);
                    v0 += c.x; v1 += c.y;
                }
                *(float2*)(dst + col) = make_float2(v0, v1);
            }
        }
    }
}

// ---------------- segmented multi-output GEMM (shared A) --------------------
struct SegP {
    const float* W; const float* bias; float* C;
    int ldC; int rpb; int ostride; int ooff; int act;
};

__global__ __launch_bounds__(256, 2) void gemm_ms(
    const float* __restrict__ A, int K,
    SegP s0, SegP s1, SegP s2, int t1, int t2)
{
    __shared__ __align__(16) float As[2][16][136];
    __shared__ __align__(16) float Bs[2][16][136];
    int bx = blockIdx.x;
    SegP sp; int nb;
    if (bx < t1)      { sp = s0; nb = bx; }
    else if (bx < t2) { sp = s1; nb = bx - t1; }
    else              { sp = s2; nb = bx - t2; }
    float acc[2][8][4];
    mma_mainloop<false>(As, Bs, A, sp.W, K, 0, blockIdx.y * 128, nb * 128, acc);
    epi_std<false, false>(acc, sp.bias, sp.C, sp.ldC,
        blockIdx.y * 128, nb * 128, sp.rpb, sp.ostride, sp.ooff, sp.act);
}

// ---------------- standalone (batched) GEMM ---------------------------------
template<int ACT, bool BT, bool ACCUM, bool RB>
__global__ __launch_bounds__(256, 2) void gemm1(
    const float* __restrict__ A, const float* __restrict__ W,
    const float* __restrict__ bias, float* __restrict__ C,
    int K, int ldB, int ldC, int rpb, int ostride, int ooff,
    size_t aB, size_t bB, size_t cB)
{
    __shared__ __align__(16) float As[2][16][136];
    __shared__ __align__(16) float Bs[2][16][136];
    int bz = blockIdx.z;
    float acc[2][8][4];
    mma_mainloop<BT>(As, Bs, A + (size_t)bz * aB, W + (size_t)bz * bB,
                     K, ldB, blockIdx.y * 128, blockIdx.x * 128, acc);
    epi_std<ACCUM, RB>(acc, bias, C + (size_t)bz * cB, ldC,
        blockIdx.y * 128, blockIdx.x * 128, rpb, ostride, ooff, ACT);
}

// ---------------- final GEMM: attn_out + weighted combine fused -------------
__global__ __launch_bounds__(256, 2) void gemm_final(
    const float* __restrict__ W, const float* __restrict__ bias,
    const float* __restrict__ x1, const float* __restrict__ x2,
    float* __restrict__ out)
{
    __shared__ __align__(16) float As[2][16][136];
    __shared__ __align__(16) float Bs[2][16][136];
    int m0 = blockIdx.y * 128, n0 = blockIdx.x * 128;
    float acc[2][8][4];
    mma_mainloop<false>(As, Bs, d_o, W, Dc, 0, m0, n0, acc);

    const int tid = threadIdx.x, lane = tid & 31, warp = tid >> 5;
    const int wm = warp >> 1, wn = warp & 1;
    const int gid = lane >> 2, tig = lane & 3;

    #pragma unroll
    for (int mt = 0; mt < 2; mt++) {
        #pragma unroll
        for (int rh = 0; rh < 2; rh++) {
            int r = m0 + wm * 32 + mt * 16 + gid + rh * 8;
            int b = r / Sc;
            int s = r - b * Sc;
            const float* w = d_wts + b * 4;
            float w0 = w[0], w1 = w[1], w2 = w[2], w3 = w[3];
            const float* lfr = d_lf + (size_t)r * Dc;
            const float* xo; const float* xv; float* dst;
            if (s < N1c) {
                size_t rr = (size_t)b * N1c + s;
                xo = d_xout + rr * Dc;
                xv = x1 + rr * Dc;
                dst = out + rr * Dc;
            } else {
                int s2 = s - N1c;
                xo = d_xout + ((size_t)b * N1c + s2) * Dc;
                xv = x2 + ((size_t)b * N2c + s2) * Dc;
                dst = out + (size_t)Bb * N1c * Dc + ((size_t)b * N2c + s2) * Dc;
            }
            #pragma unroll
            for (int nt = 0; nt < 8; nt++) {
                int col = n0 + wn * 64 + nt * 8 + tig * 2;
                float2 bc = *(const float2*)(bias + col);
                float op0 = acc[mt][nt][rh * 2 + 0] + bc.x;
                float op1 = acc[mt][nt][rh * 2 + 1] + bc.y;
                float2 l = *(const float2*)(lfr + col);
                float2 g = *(const float2*)(xo + col);
                float2 y = *(const float2*)(xv + col);
                float o0 = w0 * l.x + w1 * g.x + w2 * op0 + w3 * y.x;
                float o1 = w0 * l.y + w1 * g.y + w2 * op1 + w3 * y.y;
                *(float2*)(dst + col) = make_float2(o0, o1);
            }
        }
    }
}

// ---------------- attention: one block per (b,h); NR=3 single pass ----------
__global__ __launch_bounds__(256, 1) void attn_kernel()
{
    extern __shared__ float sm[];
    float* Ks = sm;               // Sc * 32
    float* Vs = sm + Sc * HDc;    // Sc * 32
    int bh = blockIdx.x;
    int b = bh >> 3;
    int h = bh & 7;
    int tid = threadIdx.x;
    const float* base = d_qkv + (size_t)b * Sc * (3 * Dc);

    for (int i = tid; i < Sc * 8; i += 256) {
        int s = i >> 3, d4 = i & 7;
        const float* row = base + (size_t)s * (3 * Dc) + h * HDc + d4 * 4;
        *(float4*)&Ks[s * HDc + d4 * 4] = *(const float4*)(row + Dc);
        *(float4*)&Vs[s * HDc + d4 * 4] = *(const float4*)(row + 2 * Dc);
    }
    __syncthreads();

    const float scale = 0.17677669529663688f;  // 1/sqrt(32)
    u64t sc2 = pk2(scale, scale);

    u64t q[3][16], acc[3][16];
    float l[3];
    #pragma unroll
    for (int r = 0; r < 3; r++) {
        const double2* qp = (const double2*)(base + (size_t)(tid + r * 256) * (3 * Dc) + h * HDc);
        #pragma unroll
        for (int i = 0; i < 8; i++) {
            double2 qd = qp[i];
            q[r][2 * i]     = mul2(d2u(qd.x), sc2);
            q[r][2 * i + 1] = mul2(d2u(qd.y), sc2);
        }
        #pragma unroll
        for (int i = 0; i < 16; i++) acc[r][i] = 0ull;
        l[r] = 0.f;
    }

    for (int s = 0; s < Sc; s++) {
        const double2* kp = (const double2*)&Ks[s * HDc];
        u64t t0[3] = { 0ull, 0ull, 0ull };
        #pragma unroll
        for (int i = 0; i < 8; i++) {
            double2 kd = kp[i];
            u64t ka = d2u(kd.x), kb = d2u(kd.y);
            #pragma unroll
            for (int r = 0; r < 3; r++) {
                fma2(t0[r], q[r][2 * i],     ka);
                fma2(t0[r], q[r][2 * i + 1], kb);
            }
        }
        u64t pb[3];
        #pragma unroll
        for (int r = 0; r < 3; r++) {
            float2 f = upk(t0[r]);
            float p = __expf(f.x + f.y);
            l[r] += p;
            pb[r] = pk2(p, p);
        }
        const double2* vp = (const double2*)&Vs[s * HDc];
        #pragma unroll
        for (int i = 0; i < 8; i++) {
            double2 vd = vp[i];
            u64t va = d2u(vd.x), vb = d2u(vd.y);
            #pragma unroll
            for (int r = 0; r < 3; r++) {
                fma2(acc[r][2 * i],     pb[r], va);
                fma2(acc[r][2 * i + 1], pb[r], vb);
            }
        }
    }
    #pragma unroll
    for (int r = 0; r < 3; r++) {
        float inv = 1.f / l[r];
        float* op = d_o + ((size_t)(b * Sc + tid + r * 256)) * Dc + h * HDc;
        #pragma unroll
        for (int i = 0; i < 8; i++) {
            float2 ra = upk(acc[r][2 * i]);
            float2 rb = upk(acc[r][2 * i + 1]);
            *(float4*)(op + i * 4) = make_float4(ra.x * inv, ra.y * inv, rb.x * inv, rb.y * inv);
        }
    }
}

// ---------------- launch ----------------------------------------------------
extern "C" void kernel_launch(void* const* d_in, const int* in_sizes, int n_in,
                              void* d_out, int out_size)
{
    const float* x1        = (const float*)d_in[0];
    const float* x2        = (const float*)d_in[1];
    const float* r_w1      = (const float*)d_in[2];
    const float* r_b1      = (const float*)d_in[3];
    const float* ln_g      = (const float*)d_in[4];
    const float* ln_b      = (const float*)d_in[5];
    const float* r_w2      = (const float*)d_in[6];
    const float* r_b2      = (const float*)d_in[7];
    const float* lf_w      = (const float*)d_in[8];
    const float* lf_b      = (const float*)d_in[9];
    const float* af2_w     = (const float*)d_in[10];
    const float* af2_b     = (const float*)d_in[11];
    const float* af3_w     = (const float*)d_in[12];
    const float* af3_b     = (const float*)d_in[13];
    const float* attn_in_w = (const float*)d_in[14];
    const float* attn_in_b = (const float*)d_in[15];
    const float* attn_out_w= (const float*)d_in[16];
    const float* attn_out_b= (const float*)d_in[17];
    float* out = (float*)d_out;

    float *qkv, *lf, *xout;
    cudaGetSymbolAddress((void**)&qkv,  d_qkv);
    cudaGetSymbolAddress((void**)&lf,   d_lf);
    cudaGetSymbolAddress((void**)&xout, d_xout);

    const int ATTN_SMEM = 2 * Sc * HDc * (int)sizeof(float);  // 196608
    cudaFuncSetAttribute(attn_kernel, cudaFuncAttributeMaxDynamicSharedMemorySize, ATTN_SMEM);

    const int BIGR = 1 << 30;

    // 1. router weights
    router_kernel<<<Bb, 256>>>(x1, x2, r_w1, r_b1, ln_g, ln_b, r_w2, r_b2);

    // 2. merged GEMMs with A = x1: qkv(6 n-blocks) | lf(2) | a1(2)
    {
        SegP s0 = { attn_in_w, attn_in_b, qkv, 3 * Dc, N1c, Sc, 0,   0 };
        SegP s1 = { lf_w,      lf_b,      lf,  Dc,     N1c, Sc, 0,   1 };
        SegP s2 = { af2_w,     af2_b,     xout,Dc,     BIGR, 0, 0,   1 };
        gemm_ms<<<dim3(10, 128), 256>>>(x1, Dc, s0, s1, s2, 6, 8);
    }
    // 3. merged GEMMs with A = x2: qkv(6) | lf(2)
    {
        SegP s0 = { attn_in_w, attn_in_b, qkv, 3 * Dc, N2c, Sc, N1c, 0 };
        SegP s1 = { lf_w,      lf_b,      lf,  Dc,     N2c, Sc, N1c, 1 };
        gemm_ms<<<dim3(8, 64), 256>>>(x2, Dc, s0, s1, s1, 6, 8);
    }

    // 4. xout += elu(af3_w @ x2[b] + af3_b)   (per-batch NN GEMM, row bias)
    gemm1<1, true, true, true><<<dim3(2, 4, Bb), 256>>>(
        af3_w, x2, af3_b, xout, N2c, Dc, Dc, BIGR, 0, 0,
        0, (size_t)N2c * Dc, (size_t)N1c * Dc);

    // 5. attention (reads d_qkv, writes d_o)
    attn_kernel<<<Bb * Hc, 256, ATTN_SMEM>>>();

    // 6. fused: (d_o @ attn_out_w.T + b) combined with lf/xout/x -> out
    gemm_final<<<dim3(2, 192), 256>>>(attn_out_w, attn_out_b, x1, x2, out);
}

// round 6
// speedup vs baseline: 3.2570x; 1.2850x over previous
#include <cuda_runtime.h>
#include <math.h>

// Shapes (fixed by the problem)
#define Bb   32
#define N1c  512
#define N2c  256
#define Dc   256
#define Hc   8
#define HDc  32
#define Sc   768   // N1 + N2

typedef unsigned long long u64t;

// ---------------- tf32 helpers ----------------------------------------------
__device__ __forceinline__ float tf32f(float x) {
    unsigned r; asm("cvt.rna.tf32.f32 %0,%1;" : "=r"(r) : "f"(x));
    return __uint_as_float(r);
}
__device__ __forceinline__ void mma_tf32(float (&c)[4], const unsigned (&a)[4],
                                         const unsigned (&b)[2]) {
    asm("mma.sync.aligned.m16n8k8.row.col.f32.tf32.tf32.f32 "
        "{%0,%1,%2,%3},{%4,%5,%6,%7},{%8,%9},{%0,%1,%2,%3};"
        : "+f"(c[0]), "+f"(c[1]), "+f"(c[2]), "+f"(c[3])
        : "r"(a[0]), "r"(a[1]), "r"(a[2]), "r"(a[3]), "r"(b[0]), "r"(b[1]));
}

// ---------------- scratch (device globals; no allocations allowed) ----------
__device__ __align__(16) float d_qkv [Bb * Sc * 3 * Dc];
__device__ __align__(16) float d_lf  [Bb * Sc * Dc];
__device__ __align__(16) float d_xout[Bb * N1c * Dc];
__device__ __align__(16) float d_o   [Bb * Sc * Dc];
__device__ float d_wts [Bb * 4];

// ---------------- router ----------------------------------------------------
__global__ __launch_bounds__(256) void router_kernel(
    const float* __restrict__ x1, const float* __restrict__ x2,
    const float* __restrict__ r_w1, const float* __restrict__ r_b1,
    const float* __restrict__ ln_g, const float* __restrict__ ln_b,
    const float* __restrict__ r_w2, const float* __restrict__ r_b2)
{
    __shared__ float m[2 * Dc];
    __shared__ float4 ps[4][64];
    __shared__ float hb[Dc];
    __shared__ float red[8];
    __shared__ float lg[4];
    int b = blockIdx.x, t = threadIdx.x;
    int c4 = t & 63, rq = t >> 6;

    {
        const float4* p = (const float4*)(x1 + (size_t)b * N1c * Dc) + (size_t)rq * 128 * 64 + c4;
        float4 s = make_float4(0.f, 0.f, 0.f, 0.f);
        for (int n = 0; n < 128; n++) {
            float4 v = p[(size_t)n * 64];
            s.x += v.x; s.y += v.y; s.z += v.z; s.w += v.w;
        }
        ps[rq][c4] = s;
    }
    __syncthreads();
    if (t < 64) {
        float4 a = ps[0][t], b1 = ps[1][t], c = ps[2][t], d = ps[3][t];
        m[t * 4 + 0] = (a.x + b1.x + c.x + d.x) * (1.f / N1c);
        m[t * 4 + 1] = (a.y + b1.y + c.y + d.y) * (1.f / N1c);
        m[t * 4 + 2] = (a.z + b1.z + c.z + d.z) * (1.f / N1c);
        m[t * 4 + 3] = (a.w + b1.w + c.w + d.w) * (1.f / N1c);
    }
    __syncthreads();
    {
        const float4* p = (const float4*)(x2 + (size_t)b * N2c * Dc) + (size_t)rq * 64 * 64 + c4;
        float4 s = make_float4(0.f, 0.f, 0.f, 0.f);
        for (int n = 0; n < 64; n++) {
            float4 v = p[(size_t)n * 64];
            s.x += v.x; s.y += v.y; s.z += v.z; s.w += v.w;
        }
        ps[rq][c4] = s;
    }
    __syncthreads();
    if (t < 64) {
        float4 a = ps[0][t], b1 = ps[1][t], c = ps[2][t], d = ps[3][t];
        m[Dc + t * 4 + 0] = (a.x + b1.x + c.x + d.x) * (1.f / N2c);
        m[Dc + t * 4 + 1] = (a.y + b1.y + c.y + d.y) * (1.f / N2c);
        m[Dc + t * 4 + 2] = (a.z + b1.z + c.z + d.z) * (1.f / N2c);
        m[Dc + t * 4 + 3] = (a.w + b1.w + c.w + d.w) * (1.f / N2c);
    }
    __syncthreads();

    float acc = r_b1[t];
    const float* wr = r_w1 + (size_t)t * (2 * Dc);
    #pragma unroll 4
    for (int k = 0; k < 2 * Dc; k++) acc += m[k] * wr[k];

    float v = acc;
    for (int o = 16; o; o >>= 1) v += __shfl_down_sync(0xffffffffu, v, o);
    if ((t & 31) == 0) red[t >> 5] = v;
    __syncthreads();
    if (t < 8) {
        v = red[t];
        for (int o = 4; o; o >>= 1) v += __shfl_down_sync(0xffu, v, o);
        if (t == 0) red[0] = v;
    }
    __syncthreads();
    float mu = red[0] * (1.f / Dc);
    __syncthreads();
    float dd = acc - mu;
    v = dd * dd;
    for (int o = 16; o; o >>= 1) v += __shfl_down_sync(0xffffffffu, v, o);
    if ((t & 31) == 0) red[t >> 5] = v;
    __syncthreads();
    if (t < 8) {
        v = red[t];
        for (int o = 4; o; o >>= 1) v += __shfl_down_sync(0xffu, v, o);
        if (t == 0) red[0] = v;
    }
    __syncthreads();
    float var = red[0] * (1.f / Dc);
    float y = dd * rsqrtf(var + 1e-5f) * ln_g[t] + ln_b[t];
    float g = 0.5f * y * (1.f + erff(y * 0.70710678118654752f));
    hb[t] = g;
    __syncthreads();

    if (t < 4) {
        float a = r_b2[t];
        const float* w2 = r_w2 + (size_t)t * Dc;
        for (int k = 0; k < Dc; k++) a += hb[k] * w2[k];
        lg[t] = a;
    }
    __syncthreads();
    if (t == 0) {
        float mx = fmaxf(fmaxf(lg[0], lg[1]), fmaxf(lg[2], lg[3]));
        float e0 = expf(lg[0] - mx), e1 = expf(lg[1] - mx);
        float e2 = expf(lg[2] - mx), e3 = expf(lg[3] - mx);
        float inv = 1.f / (e0 + e1 + e2 + e3);
        d_wts[b * 4 + 0] = e0 * inv; d_wts[b * 4 + 1] = e1 * inv;
        d_wts[b * 4 + 2] = e2 * inv; d_wts[b * 4 + 3] = e3 * inv;
    }
}

// ---------------- tf32 MMA GEMM: BM=128, BN=128, BK=16 ----------------------
typedef float SmemT[2][16][136];

template<bool BT>
__device__ __forceinline__ void mma_mainloop(
    SmemT& As, SmemT& Bs,
    const float* __restrict__ A, const float* __restrict__ W,
    int K, int ldB, int m0, int n0, float (&acc)[2][8][4])
{
    const int tid = threadIdx.x, lane = tid & 31, warp = tid >> 5;
    const int wm = warp >> 1, wn = warp & 1;
    const int gid = lane >> 2, tig = lane & 3;
    const int ar = tid >> 1, ac = (tid & 1) * 8;

    #pragma unroll
    for (int i = 0; i < 2; i++)
        #pragma unroll
        for (int j = 0; j < 8; j++)
            #pragma unroll
            for (int c = 0; c < 4; c++) acc[i][j][c] = 0.f;

    const float* aP = A + (size_t)(m0 + ar) * K + ac;
    const float* bP;
    if (BT) bP = W + (size_t)(tid >> 4) * ldB + n0 + (tid & 15) * 8;
    else    bP = W + (size_t)(n0 + ar) * K + ac;

    float4 a0v, a1v, b0v, b1v;
    a0v = *(const float4*)aP;       a1v = *(const float4*)(aP + 4);
    b0v = *(const float4*)bP;       b1v = *(const float4*)(bP + 4);

    {
        float av[8] = { a0v.x, a0v.y, a0v.z, a0v.w, a1v.x, a1v.y, a1v.z, a1v.w };
        #pragma unroll
        for (int j = 0; j < 8; j++) As[0][ac + j][ar] = tf32f(av[j]);
        float bv[8] = { b0v.x, b0v.y, b0v.z, b0v.w, b1v.x, b1v.y, b1v.z, b1v.w };
        if (BT) {
            int kr = tid >> 4, nc = (tid & 15) * 8;
            #pragma unroll
            for (int j = 0; j < 8; j++) Bs[0][kr][nc + j] = tf32f(bv[j]);
        } else {
            #pragma unroll
            for (int j = 0; j < 8; j++) Bs[0][ac + j][ar] = tf32f(bv[j]);
        }
    }
    __syncthreads();

    int buf = 0;
    for (int k0 = 0; k0 < K; k0 += 16) {
        int kn = k0 + 16;
        bool more = kn < K;
        if (more) {
            a0v = *(const float4*)(aP + kn);
            a1v = *(const float4*)(aP + kn + 4);
            if (BT) {
                b0v = *(const float4*)(bP + (size_t)kn * ldB);
                b1v = *(const float4*)(bP + (size_t)kn * ldB + 4);
            } else {
                b0v = *(const float4*)(bP + kn);
                b1v = *(const float4*)(bP + kn + 4);
            }
        }
        #pragma unroll
        for (int ks = 0; ks < 16; ks += 8) {
            unsigned af[2][4], bf[8][2];
            #pragma unroll
            for (int mt = 0; mt < 2; mt++) {
                int mb = wm * 32 + mt * 16 + gid;
                af[mt][0] = __float_as_uint(As[buf][ks + tig][mb]);
                af[mt][1] = __float_as_uint(As[buf][ks + tig][mb + 8]);
                af[mt][2] = __float_as_uint(As[buf][ks + tig + 4][mb]);
                af[mt][3] = __float_as_uint(As[buf][ks + tig + 4][mb + 8]);
            }
            #pragma unroll
            for (int nt = 0; nt < 8; nt++) {
                int nb = wn * 64 + nt * 8 + gid;
                bf[nt][0] = __float_as_uint(Bs[buf][ks + tig][nb]);
                bf[nt][1] = __float_as_uint(Bs[buf][ks + tig + 4][nb]);
            }
            #pragma unroll
            for (int mt = 0; mt < 2; mt++)
                #pragma unroll
                for (int nt = 0; nt < 8; nt++)
                    mma_tf32(acc[mt][nt], af[mt], bf[nt]);
        }
        if (more) {
            int nb2 = buf ^ 1;
            float av[8] = { a0v.x, a0v.y, a0v.z, a0v.w, a1v.x, a1v.y, a1v.z, a1v.w };
            #pragma unroll
            for (int j = 0; j < 8; j++) As[nb2][ac + j][ar] = tf32f(av[j]);
            float bv[8] = { b0v.x, b0v.y, b0v.z, b0v.w, b1v.x, b1v.y, b1v.z, b1v.w };
            if (BT) {
                int kr = tid >> 4, nc = (tid & 15) * 8;
                #pragma unroll
                for (int j = 0; j < 8; j++) Bs[nb2][kr][nc + j] = tf32f(bv[j]);
            } else {
                #pragma unroll
                for (int j = 0; j < 8; j++) Bs[nb2][ac + j][ar] = tf32f(bv[j]);
            }
        }
        __syncthreads();
        buf ^= 1;
    }
}

// ---------------- standard epilogue (fragment layout) ------------------------
template<bool ACCUM, bool RB>
__device__ __forceinline__ void epi_std(
    float (&acc)[2][8][4], const float* __restrict__ bias, float* __restrict__ C,
    int ldC, int m0, int n0, int rpb, int ostride, int ooff, int act)
{
    const int tid = threadIdx.x, lane = tid & 31, warp = tid >> 5;
    const int wm = warp >> 1, wn = warp & 1;
    const int gid = lane >> 2, tig = lane & 3;

    #pragma unroll
    for (int mt = 0; mt < 2; mt++) {
        #pragma unroll
        for (int rh = 0; rh < 2; rh++) {
            int r = m0 + wm * 32 + mt * 16 + gid + rh * 8;
            float rbv = RB ? bias[r] : 0.f;
            int grow = (r / rpb) * ostride + ooff + (r % rpb);
            float* dst = C + (size_t)grow * ldC;
            #pragma unroll
            for (int nt = 0; nt < 8; nt++) {
                int col = n0 + wn * 64 + nt * 8 + tig * 2;
                float v0 = acc[mt][nt][rh * 2 + 0];
                float v1 = acc[mt][nt][rh * 2 + 1];
                if (RB) { v0 += rbv; v1 += rbv; }
                else {
                    float2 bc = *(const float2*)(bias + col);
                    v0 += bc.x; v1 += bc.y;
                }
                if (act) {
                    v0 = v0 > 0.f ? v0 : expm1f(v0);
                    v1 = v1 > 0.f ? v1 : expm1f(v1);
                }
                if (ACCUM) {
                    float2 c = *(float2*)(dst + col);
                    v0 += c.x; v1 += c.y;
                }
                *(float2*)(dst + col) = make_float2(v0, v1);
            }
        }
    }
}

// ---------------- segmented multi-output GEMM (shared A) --------------------
struct SegP {
    const float* W; const float* bias; float* C;
    int ldC; int rpb; int ostride; int ooff; int act;
};

__global__ __launch_bounds__(256, 2) void gemm_ms(
    const float* __restrict__ A, int K,
    SegP s0, SegP s1, SegP s2, int t1, int t2)
{
    __shared__ __align__(16) float As[2][16][136];
    __shared__ __align__(16) float Bs[2][16][136];
    int bx = blockIdx.x;
    SegP sp; int nb;
    if (bx < t1)      { sp = s0; nb = bx; }
    else if (bx < t2) { sp = s1; nb = bx - t1; }
    else              { sp = s2; nb = bx - t2; }
    float acc[2][8][4];
    mma_mainloop<false>(As, Bs, A, sp.W, K, 0, blockIdx.y * 128, nb * 128, acc);
    epi_std<false, false>(acc, sp.bias, sp.C, sp.ldC,
        blockIdx.y * 128, nb * 128, sp.rpb, sp.ostride, sp.ooff, sp.act);
}

// ---------------- standalone (batched) GEMM ---------------------------------
template<int ACT, bool BT, bool ACCUM, bool RB>
__global__ __launch_bounds__(256, 2) void gemm1(
    const float* __restrict__ A, const float* __restrict__ W,
    const float* __restrict__ bias, float* __restrict__ C,
    int K, int ldB, int ldC, int rpb, int ostride, int ooff,
    size_t aB, size_t bB, size_t cB)
{
    __shared__ __align__(16) float As[2][16][136];
    __shared__ __align__(16) float Bs[2][16][136];
    int bz = blockIdx.z;
    float acc[2][8][4];
    mma_mainloop<BT>(As, Bs, A + (size_t)bz * aB, W + (size_t)bz * bB,
                     K, ldB, blockIdx.y * 128, blockIdx.x * 128, acc);
    epi_std<ACCUM, RB>(acc, bias, C + (size_t)bz * cB, ldC,
        blockIdx.y * 128, blockIdx.x * 128, rpb, ostride, ooff, ACT);
}

// ---------------- final GEMM: attn_out + weighted combine fused -------------
__global__ __launch_bounds__(256, 2) void gemm_final(
    const float* __restrict__ W, const float* __restrict__ bias,
    const float* __restrict__ x1, const float* __restrict__ x2,
    float* __restrict__ out)
{
    __shared__ __align__(16) float As[2][16][136];
    __shared__ __align__(16) float Bs[2][16][136];
    int m0 = blockIdx.y * 128, n0 = blockIdx.x * 128;
    float acc[2][8][4];
    mma_mainloop<false>(As, Bs, d_o, W, Dc, 0, m0, n0, acc);

    const int tid = threadIdx.x, lane = tid & 31, warp = tid >> 5;
    const int wm = warp >> 1, wn = warp & 1;
    const int gid = lane >> 2, tig = lane & 3;

    #pragma unroll
    for (int mt = 0; mt < 2; mt++) {
        #pragma unroll
        for (int rh = 0; rh < 2; rh++) {
            int r = m0 + wm * 32 + mt * 16 + gid + rh * 8;
            int b = r / Sc;
            int s = r - b * Sc;
            const float* w = d_wts + b * 4;
            float w0 = w[0], w1 = w[1], w2 = w[2], w3 = w[3];
            const float* lfr = d_lf + (size_t)r * Dc;
            const float* xo; const float* xv; float* dst;
            if (s < N1c) {
                size_t rr = (size_t)b * N1c + s;
                xo = d_xout + rr * Dc;
                xv = x1 + rr * Dc;
                dst = out + rr * Dc;
            } else {
                int s2 = s - N1c;
                xo = d_xout + ((size_t)b * N1c + s2) * Dc;
                xv = x2 + ((size_t)b * N2c + s2) * Dc;
                dst = out + (size_t)Bb * N1c * Dc + ((size_t)b * N2c + s2) * Dc;
            }
            #pragma unroll
            for (int nt = 0; nt < 8; nt++) {
                int col = n0 + wn * 64 + nt * 8 + tig * 2;
                float2 bc = *(const float2*)(bias + col);
                float op0 = acc[mt][nt][rh * 2 + 0] + bc.x;
                float op1 = acc[mt][nt][rh * 2 + 1] + bc.y;
                float2 l = *(const float2*)(lfr + col);
                float2 g = *(const float2*)(xo + col);
                float2 y = *(const float2*)(xv + col);
                float o0 = w0 * l.x + w1 * g.x + w2 * op0 + w3 * y.x;
                float o1 = w0 * l.y + w1 * g.y + w2 * op1 + w3 * y.y;
                *(float2*)(dst + col) = make_float2(o0, o1);
            }
        }
    }
}

// ---------------- attention via tf32 MMA -------------------------------------
// One block per (q-tile 128, b, h). KV chunks of 128, no max-subtract.
// Smem: Ks[32][136] (K^T, tf32), Vs[128][40] (tf32), Ps[128][132] (tf32 P).
#define LDK 136
#define LDV 40
#define LDP 132
#define ATTN_SMEM_FLOATS (32 * LDK + 128 * LDV + 128 * LDP)

__global__ __launch_bounds__(256, 2) void attn_mma()
{
    extern __shared__ float sm[];
    float* Ks = sm;                    // [32][LDK]
    float* Vs = Ks + 32 * LDK;         // [128][LDV]
    float* Ps = Vs + 128 * LDV;        // [128][LDP]

    const int qt = blockIdx.x;         // 0..5
    const int bh = blockIdx.y;         // 0..255
    const int b = bh >> 3, h = bh & 7;
    const int tid = threadIdx.x, lane = tid & 31, warp = tid >> 5;
    const int gid = lane >> 2, tig = lane & 3;
    const int m0 = qt * 128;
    const float* base = d_qkv + (size_t)b * Sc * (3 * Dc);
    const float scale = 0.17677669529663688f;   // 1/sqrt(32)

    // Q fragments (scaled + tf32), rows warp*16 + gid (+8), held all kernel
    unsigned qf[4][4];
    {
        const float* q0 = base + (size_t)(m0 + warp * 16 + gid) * (3 * Dc) + h * HDc;
        const float* q1 = q0 + (size_t)8 * (3 * Dc);
        #pragma unroll
        for (int ks = 0; ks < 4; ks++) {
            qf[ks][0] = __float_as_uint(tf32f(q0[ks * 8 + tig] * scale));
            qf[ks][1] = __float_as_uint(tf32f(q1[ks * 8 + tig] * scale));
            qf[ks][2] = __float_as_uint(tf32f(q0[ks * 8 + tig + 4] * scale));
            qf[ks][3] = __float_as_uint(tf32f(q1[ks * 8 + tig + 4] * scale));
        }
    }

    float oc[4][4];
    #pragma unroll
    for (int i = 0; i < 4; i++)
        #pragma unroll
        for (int j = 0; j < 4; j++) oc[i][j] = 0.f;
    float lacc0 = 0.f, lacc1 = 0.f;

    for (int c = 0; c < 6; c++) {
        const int kv0 = c * 128;
        __syncthreads();   // prev PV done: Ks/Vs/Ps reusable

        // stage K chunk transposed: Ks[col][row]; thread map r=i&127 (rows
        // consecutive within warp -> STS banks r mod 32, conflict-free)
        #pragma unroll
        for (int it = 0; it < 4; it++) {
            int i = tid + it * 256;
            int r = i & 127, cg = (i >> 7) * 4;
            const float* src = base + (size_t)(kv0 + r) * (3 * Dc) + Dc + h * HDc + cg;
            float4 v = *(const float4*)src;
            Ks[(cg + 0) * LDK + r] = tf32f(v.x);
            Ks[(cg + 1) * LDK + r] = tf32f(v.y);
            Ks[(cg + 2) * LDK + r] = tf32f(v.z);
            Ks[(cg + 3) * LDK + r] = tf32f(v.w);
        }
        // stage V chunk natural: Vs[row][col]
        #pragma unroll
        for (int it = 0; it < 4; it++) {
            int i = tid + it * 256;
            int r = i & 127, cg = (i >> 7) * 4;
            const float* src = base + (size_t)(kv0 + r) * (3 * Dc) + 2 * Dc + h * HDc + cg;
            float4 v = *(const float4*)src;
            *(float4*)&Vs[r * LDV + cg] =
                make_float4(tf32f(v.x), tf32f(v.y), tf32f(v.z), tf32f(v.w));
        }
        __syncthreads();

        // S = Q @ K^T, exp, write P  (two n-halves of 64 to cap live regs)
        float* prow0 = Ps + (size_t)(warp * 16 + gid) * LDP;
        float* prow1 = prow0 + 8 * LDP;
        #pragma unroll
        for (int half = 0; half < 2; half++) {
            float sc_[8][4];
            #pragma unroll
            for (int nt = 0; nt < 8; nt++)
                #pragma unroll
                for (int j = 0; j < 4; j++) sc_[nt][j] = 0.f;
            #pragma unroll
            for (int ks = 0; ks < 4; ks++) {
                unsigned bf[8][2];
                #pragma unroll
                for (int nt = 0; nt < 8; nt++) {
                    int nb = half * 64 + nt * 8 + gid;
                    bf[nt][0] = __float_as_uint(Ks[(ks * 8 + tig) * LDK + nb]);
                    bf[nt][1] = __float_as_uint(Ks[(ks * 8 + tig + 4) * LDK + nb]);
                }
                #pragma unroll
                for (int nt = 0; nt < 8; nt++) mma_tf32(sc_[nt], qf[ks], bf[nt]);
            }
            #pragma unroll
            for (int nt = 0; nt < 8; nt++) {
                int col = half * 64 + nt * 8 + tig * 2;
                float p0 = __expf(sc_[nt][0]);
                float p1 = __expf(sc_[nt][1]);
                float p2 = __expf(sc_[nt][2]);
                float p3 = __expf(sc_[nt][3]);
                lacc0 += p0 + p1;
                lacc1 += p2 + p3;
                *(float2*)&prow0[col] = make_float2(tf32f(p0), tf32f(p1));
                *(float2*)&prow1[col] = make_float2(tf32f(p2), tf32f(p3));
            }
        }
        __syncthreads();

        // O += P @ V
        const float* pr0 = prow0;
        const float* pr1 = prow1;
        #pragma unroll
        for (int ks = 0; ks < 16; ks++) {
            unsigned a[4];
            a[0] = __float_as_uint(pr0[ks * 8 + tig]);
            a[1] = __float_as_uint(pr1[ks * 8 + tig]);
            a[2] = __float_as_uint(pr0[ks * 8 + tig + 4]);
            a[3] = __float_as_uint(pr1[ks * 8 + tig + 4]);
            #pragma unroll
            for (int nf = 0; nf < 4; nf++) {
                unsigned bv[2];
                bv[0] = __float_as_uint(Vs[(ks * 8 + tig) * LDV + nf * 8 + gid]);
                bv[1] = __float_as_uint(Vs[(ks * 8 + tig + 4) * LDV + nf * 8 + gid]);
                mma_tf32(oc[nf], a, bv);
            }
        }
    }

    // row-sum reduce across the quad (lanes sharing gid)
    lacc0 += __shfl_xor_sync(0xffffffffu, lacc0, 1);
    lacc0 += __shfl_xor_sync(0xffffffffu, lacc0, 2);
    lacc1 += __shfl_xor_sync(0xffffffffu, lacc1, 1);
    lacc1 += __shfl_xor_sync(0xffffffffu, lacc1, 2);
    float inv0 = 1.f / lacc0, inv1 = 1.f / lacc1;

    float* o0 = d_o + (size_t)(b * Sc + m0 + warp * 16 + gid) * Dc + h * HDc;
    float* o1 = o0 + 8 * Dc;
    #pragma unroll
    for (int nf = 0; nf < 4; nf++) {
        int col = nf * 8 + tig * 2;
        *(float2*)&o0[col] = make_float2(oc[nf][0] * inv0, oc[nf][1] * inv0);
        *(float2*)&o1[col] = make_float2(oc[nf][2] * inv1, oc[nf][3] * inv1);
    }
}

// ---------------- launch ----------------------------------------------------
extern "C" void kernel_launch(void* const* d_in, const int* in_sizes, int n_in,
                              void* d_out, int out_size)
{
    const float* x1        = (const float*)d_in[0];
    const float* x2        = (const float*)d_in[1];
    const float* r_w1      = (const float*)d_in[2];
    const float* r_b1      = (const float*)d_in[3];
    const float* ln_g      = (const float*)d_in[4];
    const float* ln_b      = (const float*)d_in[5];
    const float* r_w2      = (const float*)d_in[6];
    const float* r_b2      = (const float*)d_in[7];
    const float* lf_w      = (const float*)d_in[8];
    const float* lf_b      = (const float*)d_in[9];
    const float* af2_w     = (const float*)d_in[10];
    const float* af2_b     = (const float*)d_in[11];
    const float* af3_w     = (const float*)d_in[12];
    const float* af3_b     = (const float*)d_in[13];
    const float* attn_in_w = (const float*)d_in[14];
    const float* attn_in_b = (const float*)d_in[15];
    const float* attn_out_w= (const float*)d_in[16];
    const float* attn_out_b= (const float*)d_in[17];
    float* out = (float*)d_out;

    float *qkv, *lf, *xout;
    cudaGetSymbolAddress((void**)&qkv,  d_qkv);
    cudaGetSymbolAddress((void**)&lf,   d_lf);
    cudaGetSymbolAddress((void**)&xout, d_xout);

    const int ATTN_SMEM = ATTN_SMEM_FLOATS * (int)sizeof(float);  // 105472
    cudaFuncSetAttribute(attn_mma, cudaFuncAttributeMaxDynamicSharedMemorySize, ATTN_SMEM);

    const int BIGR = 1 << 30;

    // 1. router weights
    router_kernel<<<Bb, 256>>>(x1, x2, r_w1, r_b1, ln_g, ln_b, r_w2, r_b2);

    // 2. merged GEMMs with A = x1: qkv(6 n-blocks) | lf(2) | a1(2)
    {
        SegP s0 = { attn_in_w, attn_in_b, qkv, 3 * Dc, N1c, Sc, 0,   0 };
        SegP s1 = { lf_w,      lf_b,      lf,  Dc,     N1c, Sc, 0,   1 };
        SegP s2 = { af2_w,     af2_b,     xout,Dc,     BIGR, 0, 0,   1 };
        gemm_ms<<<dim3(10, 128), 256>>>(x1, Dc, s0, s1, s2, 6, 8);
    }
    // 3. merged GEMMs with A = x2: qkv(6) | lf(2)
    {
        SegP s0 = { attn_in_w, attn_in_b, qkv, 3 * Dc, N2c, Sc, N1c, 0 };
        SegP s1 = { lf_w,      lf_b,      lf,  Dc,     N2c, Sc, N1c, 1 };
        gemm_ms<<<dim3(8, 64), 256>>>(x2, Dc, s0, s1, s1, 6, 8);
    }

    // 4. xout += elu(af3_w @ x2[b] + af3_b)   (per-batch NN GEMM, row bias)
    gemm1<1, true, true, true><<<dim3(2, 4, Bb), 256>>>(
        af3_w, x2, af3_b, xout, N2c, Dc, Dc, BIGR, 0, 0,
        0, (size_t)N2c * Dc, (size_t)N1c * Dc);

    // 5. attention via tensor cores (reads d_qkv, writes d_o)
    attn_mma<<<dim3(6, 256), 256, ATTN_SMEM>>>();

    // 6. fused: (d_o @ attn_out_w.T + b) combined with lf/xout/x -> out
    gemm_final<<<dim3(2, 192), 256>>>(attn_out_w, attn_out_b, x1, x2, out);
}

// round 8
// speedup vs baseline: 3.3682x; 1.0341x over previous
#include <cuda_runtime.h>
#include <math.h>

// Shapes (fixed by the problem)
#define Bb   32
#define N1c  512
#define N2c  256
#define Dc   256
#define Hc   8
#define HDc  32
#define Sc   768   // N1 + N2

// ---------------- tf32 MMA (raw fp32 operands; HW truncates to tf32) --------
__device__ __forceinline__ void mma_tf32(float (&c)[4], const unsigned (&a)[4],
                                         const unsigned (&b)[2]) {
    asm("mma.sync.aligned.m16n8k8.row.col.f32.tf32.tf32.f32 "
        "{%0,%1,%2,%3},{%4,%5,%6,%7},{%8,%9},{%0,%1,%2,%3};"
        : "+f"(c[0]), "+f"(c[1]), "+f"(c[2]), "+f"(c[3])
        : "r"(a[0]), "r"(a[1]), "r"(a[2]), "r"(a[3]), "r"(b[0]), "r"(b[1]));
}

// ---------------- scratch (device globals; no allocations allowed) ----------
__device__ __align__(16) float d_qkv [Bb * Sc * 3 * Dc];
__device__ __align__(16) float d_lf  [Bb * Sc * Dc];
__device__ __align__(16) float d_xout[Bb * N1c * Dc];
__device__ __align__(16) float d_o   [Bb * Sc * Dc];
__device__ float d_wts [Bb * 4];

// ---------------- router ----------------------------------------------------
__global__ __launch_bounds__(256) void router_kernel(
    const float* __restrict__ x1, const float* __restrict__ x2,
    const float* __restrict__ r_w1, const float* __restrict__ r_b1,
    const float* __restrict__ ln_g, const float* __restrict__ ln_b,
    const float* __restrict__ r_w2, const float* __restrict__ r_b2)
{
    __shared__ float m[2 * Dc];
    __shared__ float4 ps[4][64];
    __shared__ float hb[Dc];
    __shared__ float red[8];
    __shared__ float lg[4];
    int b = blockIdx.x, t = threadIdx.x;
    int c4 = t & 63, rq = t >> 6;

    {
        const float4* p = (const float4*)(x1 + (size_t)b * N1c * Dc) + (size_t)rq * 128 * 64 + c4;
        float4 s = make_float4(0.f, 0.f, 0.f, 0.f);
        for (int n = 0; n < 128; n++) {
            float4 v = p[(size_t)n * 64];
            s.x += v.x; s.y += v.y; s.z += v.z; s.w += v.w;
        }
        ps[rq][c4] = s;
    }
    __syncthreads();
    if (t < 64) {
        float4 a = ps[0][t], b1 = ps[1][t], c = ps[2][t], d = ps[3][t];
        m[t * 4 + 0] = (a.x + b1.x + c.x + d.x) * (1.f / N1c);
        m[t * 4 + 1] = (a.y + b1.y + c.y + d.y) * (1.f / N1c);
        m[t * 4 + 2] = (a.z + b1.z + c.z + d.z) * (1.f / N1c);
        m[t * 4 + 3] = (a.w + b1.w + c.w + d.w) * (1.f / N1c);
    }
    __syncthreads();
    {
        const float4* p = (const float4*)(x2 + (size_t)b * N2c * Dc) + (size_t)rq * 64 * 64 + c4;
        float4 s = make_float4(0.f, 0.f, 0.f, 0.f);
        for (int n = 0; n < 64; n++) {
            float4 v = p[(size_t)n * 64];
            s.x += v.x; s.y += v.y; s.z += v.z; s.w += v.w;
        }
        ps[rq][c4] = s;
    }
    __syncthreads();
    if (t < 64) {
        float4 a = ps[0][t], b1 = ps[1][t], c = ps[2][t], d = ps[3][t];
        m[Dc + t * 4 + 0] = (a.x + b1.x + c.x + d.x) * (1.f / N2c);
        m[Dc + t * 4 + 1] = (a.y + b1.y + c.y + d.y) * (1.f / N2c);
        m[Dc + t * 4 + 2] = (a.z + b1.z + c.z + d.z) * (1.f / N2c);
        m[Dc + t * 4 + 3] = (a.w + b1.w + c.w + d.w) * (1.f / N2c);
    }
    __syncthreads();

    float acc = r_b1[t];
    const float* wr = r_w1 + (size_t)t * (2 * Dc);
    #pragma unroll 4
    for (int k = 0; k < 2 * Dc; k++) acc += m[k] * wr[k];

    float v = acc;
    for (int o = 16; o; o >>= 1) v += __shfl_down_sync(0xffffffffu, v, o);
    if ((t & 31) == 0) red[t >> 5] = v;
    __syncthreads();
    if (t < 8) {
        v = red[t];
        for (int o = 4; o; o >>= 1) v += __shfl_down_sync(0xffu, v, o);
        if (t == 0) red[0] = v;
    }
    __syncthreads();
    float mu = red[0] * (1.f / Dc);
    __syncthreads();
    float dd = acc - mu;
    v = dd * dd;
    for (int o = 16; o; o >>= 1) v += __shfl_down_sync(0xffffffffu, v, o);
    if ((t & 31) == 0) red[t >> 5] = v;
    __syncthreads();
    if (t < 8) {
        v = red[t];
        for (int o = 4; o; o >>= 1) v += __shfl_down_sync(0xffu, v, o);
        if (t == 0) red[0] = v;
    }
    __syncthreads();
    float var = red[0] * (1.f / Dc);
    float y = dd * rsqrtf(var + 1e-5f) * ln_g[t] + ln_b[t];
    float g = 0.5f * y * (1.f + erff(y * 0.70710678118654752f));
    hb[t] = g;
    __syncthreads();

    if (t < 4) {
        float a = r_b2[t];
        const float* w2 = r_w2 + (size_t)t * Dc;
        for (int k = 0; k < Dc; k++) a += hb[k] * w2[k];
        lg[t] = a;
    }
    __syncthreads();
    if (t == 0) {
        float mx = fmaxf(fmaxf(lg[0], lg[1]), fmaxf(lg[2], lg[3]));
        float e0 = expf(lg[0] - mx), e1 = expf(lg[1] - mx);
        float e2 = expf(lg[2] - mx), e3 = expf(lg[3] - mx);
        float inv = 1.f / (e0 + e1 + e2 + e3);
        d_wts[b * 4 + 0] = e0 * inv; d_wts[b * 4 + 1] = e1 * inv;
        d_wts[b * 4 + 2] = e2 * inv; d_wts[b * 4 + 3] = e3 * inv;
    }
}

// ---------------- tf32 MMA GEMM: BM=128, BN=128, BK=16 ----------------------
// A smem: [k][m] pad 136 (conflict-free LDS.32 a-frags).
// B smem: k-pair interleaved [ksBlk][n][8]: word = (k&3)*2 + ((k>>2)&1) so each
// b-frag pair {k=tig, k=tig+4} is one aligned LDS.64 (conflict-free phases).
typedef float SmemA[2][16][136];
typedef float SmemB[2][2][128][8];

template<bool BT>
__device__ __forceinline__ void mma_mainloop(
    SmemA& As, SmemB& Bs,
    const float* __restrict__ A, const float* __restrict__ W,
    int K, int ldB, int m0, int n0, float (&acc)[2][8][4])
{
    const int tid = threadIdx.x, lane = tid & 31, warp = tid >> 5;
    const int wm = warp >> 1, wn = warp & 1;
    const int gid = lane >> 2, tig = lane & 3;
    const int ar = tid >> 1, ac = (tid & 1) * 8;

    #pragma unroll
    for (int i = 0; i < 2; i++)
        #pragma unroll
        for (int j = 0; j < 8; j++)
            #pragma unroll
            for (int c = 0; c < 4; c++) acc[i][j][c] = 0.f;

    const float* aP = A + (size_t)(m0 + ar) * K + ac;
    const float* bP;
    if (BT) bP = W + (size_t)(tid >> 4) * ldB + n0 + (tid & 15) * 8;
    else    bP = W + (size_t)(n0 + ar) * K + ac;

    float4 a0v, a1v, b0v, b1v;
    a0v = *(const float4*)aP;      a1v = *(const float4*)(aP + 4);
    b0v = *(const float4*)bP;      b1v = *(const float4*)(bP + 4);

    // stage tile 0
    {
        As[0][ac + 0][ar] = a0v.x; As[0][ac + 1][ar] = a0v.y;
        As[0][ac + 2][ar] = a0v.z; As[0][ac + 3][ar] = a0v.w;
        As[0][ac + 4][ar] = a1v.x; As[0][ac + 5][ar] = a1v.y;
        As[0][ac + 6][ar] = a1v.z; As[0][ac + 7][ar] = a1v.w;
        if (BT) {
            int kr = tid >> 4, kk = kr & 7, ksb = kr >> 3;
            int w = (kk & 3) * 2 + ((kk >> 2) & 1);
            int nc = (tid & 15) * 8;
            Bs[0][ksb][nc + 0][w] = b0v.x; Bs[0][ksb][nc + 1][w] = b0v.y;
            Bs[0][ksb][nc + 2][w] = b0v.z; Bs[0][ksb][nc + 3][w] = b0v.w;
            Bs[0][ksb][nc + 4][w] = b1v.x; Bs[0][ksb][nc + 5][w] = b1v.y;
            Bs[0][ksb][nc + 6][w] = b1v.z; Bs[0][ksb][nc + 7][w] = b1v.w;
        } else {
            int n = tid >> 1, kb = tid & 1;
            *(float4*)&Bs[0][kb][n][0] = make_float4(b0v.x, b1v.x, b0v.y, b1v.y);
            *(float4*)&Bs[0][kb][n][4] = make_float4(b0v.z, b1v.z, b0v.w, b1v.w);
        }
    }
    __syncthreads();

    int buf = 0;
    for (int k0 = 0; k0 < K; k0 += 16) {
        int kn = k0 + 16;
        bool more = kn < K;
        if (more) {
            a0v = *(const float4*)(aP + kn);
            a1v = *(const float4*)(aP + kn + 4);
            if (BT) {
                b0v = *(const float4*)(bP + (size_t)kn * ldB);
                b1v = *(const float4*)(bP + (size_t)kn * ldB + 4);
            } else {
                b0v = *(const float4*)(bP + kn);
                b1v = *(const float4*)(bP + kn + 4);
            }
        }
        #pragma unroll
        for (int ks8 = 0; ks8 < 2; ks8++) {
            unsigned af[2][4];
            #pragma unroll
            for (int mt = 0; mt < 2; mt++) {
                int mb = wm * 32 + mt * 16 + gid;
                af[mt][0] = __float_as_uint(As[buf][ks8 * 8 + tig][mb]);
                af[mt][1] = __float_as_uint(As[buf][ks8 * 8 + tig][mb + 8]);
                af[mt][2] = __float_as_uint(As[buf][ks8 * 8 + tig + 4][mb]);
                af[mt][3] = __float_as_uint(As[buf][ks8 * 8 + tig + 4][mb + 8]);
            }
            #pragma unroll
            for (int nt = 0; nt < 8; nt++) {
                float2 b2 = *(const float2*)&Bs[buf][ks8][wn * 64 + nt * 8 + gid][tig * 2];
                unsigned bf[2] = { __float_as_uint(b2.x), __float_as_uint(b2.y) };
                mma_tf32(acc[0][nt], af[0], bf);
                mma_tf32(acc[1][nt], af[1], bf);
            }
        }
        if (more) {
            int nb2 = buf ^ 1;
            As[nb2][ac + 0][ar] = a0v.x; As[nb2][ac + 1][ar] = a0v.y;
            As[nb2][ac + 2][ar] = a0v.z; As[nb2][ac + 3][ar] = a0v.w;
            As[nb2][ac + 4][ar] = a1v.x; As[nb2][ac + 5][ar] = a1v.y;
            As[nb2][ac + 6][ar] = a1v.z; As[nb2][ac + 7][ar] = a1v.w;
            if (BT) {
                int kr = tid >> 4, kk = kr & 7, ksb = kr >> 3;
                int w = (kk & 3) * 2 + ((kk >> 2) & 1);
                int nc = (tid & 15) * 8;
                Bs[nb2][ksb][nc + 0][w] = b0v.x; Bs[nb2][ksb][nc + 1][w] = b0v.y;
                Bs[nb2][ksb][nc + 2][w] = b0v.z; Bs[nb2][ksb][nc + 3][w] = b0v.w;
                Bs[nb2][ksb][nc + 4][w] = b1v.x; Bs[nb2][ksb][nc + 5][w] = b1v.y;
                Bs[nb2][ksb][nc + 6][w] = b1v.z; Bs[nb2][ksb][nc + 7][w] = b1v.w;
            } else {
                int n = tid >> 1, kb = tid & 1;
                *(float4*)&Bs[nb2][kb][n][0] = make_float4(b0v.x, b1v.x, b0v.y, b1v.y);
                *(float4*)&Bs[nb2][kb][n][4] = make_float4(b0v.z, b1v.z, b0v.w, b1v.w);
            }
        }
        __syncthreads();
        buf ^= 1;
    }
}

// ---------------- standard epilogue (fragment layout) ------------------------
template<bool ACCUM, bool RB>
__device__ __forceinline__ void epi_std(
    float (&acc)[2][8][4], const float* __restrict__ bias, float* __restrict__ C,
    int ldC, int m0, int n0, int rpb, int ostride, int ooff, int act)
{
    const int tid = threadIdx.x, lane = tid & 31, warp = tid >> 5;
    const int wm = warp >> 1, wn = warp & 1;
    const int gid = lane >> 2, tig = lane & 3;

    #pragma unroll
    for (int mt = 0; mt < 2; mt++) {
        #pragma unroll
        for (int rh = 0; rh < 2; rh++) {
            int r = m0 + wm * 32 + mt * 16 + gid + rh * 8;
            float rbv = RB ? bias[r] : 0.f;
            int grow = (r / rpb) * ostride + ooff + (r % rpb);
            float* dst = C + (size_t)grow * ldC;
            #pragma unroll
            for (int nt = 0; nt < 8; nt++) {
                int col = n0 + wn * 64 + nt * 8 + tig * 2;
                float v0 = acc[mt][nt][rh * 2 + 0];
                float v1 = acc[mt][nt][rh * 2 + 1];
                if (RB) { v0 += rbv; v1 += rbv; }
                else {
                    float2 bc = *(const float2*)(bias + col);
                    v0 += bc.x; v1 += bc.y;
                }
                if (act) {
                    v0 = v0 > 0.f ? v0 : expm1f(v0);
                    v1 = v1 > 0.f ? v1 : expm1f(v1);
                }
                if (ACCUM) {
                    float2 c = *(float2*)(dst + col);
                    v0 += c.x; v1 += c.y;
                }
                *(float2*)(dst + col) = make_float2(v0, v1);
            }
        }
    }
}

// ---------------- segmented multi-output GEMM (shared A) --------------------
struct SegP {
    const float* W; const float* bias; float* C;
    int ldC; int rpb; int ostride; int ooff; int act;
};

__global__ __launch_bounds__(256, 2) void gemm_ms(
    const float* __restrict__ A, int K,
    SegP s0, SegP s1, SegP s2, int t1, int t2)
{
    __shared__ __align__(16) float As[2][16][136];
    __shared__ __align__(16) float Bs[2][2][128][8];
    int bx = blockIdx.x;
    SegP sp; int nb;
    if (bx < t1)      { sp = s0; nb = bx; }
    else if (bx < t2) { sp = s1; nb = bx - t1; }
    else              { sp = s2; nb = bx - t2; }
    float acc[2][8][4];
    mma_mainloop<false>(As, Bs, A, sp.W, K, 0, blockIdx.y * 128, nb * 128, acc);
    epi_std<false, false>(acc, sp.bias, sp.C, sp.ldC,
        blockIdx.y * 128, nb * 128, sp.rpb, sp.ostride, sp.ooff, sp.act);
}

// ---------------- standalone (batched) GEMM ---------------------------------
template<int ACT, bool BT, bool ACCUM, bool RB>
__global__ __launch_bounds__(256, 2) void gemm1(
    const float* __restrict__ A, const float* __restrict__ W,
    const float* __restrict__ bias, float* __restrict__ C,
    int K, int ldB, int ldC, int rpb, int ostride, int ooff,
    size_t aB, size_t bB, size_t cB)
{
    __shared__ __align__(16) float As[2][16][136];
    __shared__ __align__(16) float Bs[2][2][128][8];
    int bz = blockIdx.z;
    float acc[2][8][4];
    mma_mainloop<BT>(As, Bs, A + (size_t)bz * aB, W + (size_t)bz * bB,
                     K, ldB, blockIdx.y * 128, blockIdx.x * 128, acc);
    epi_std<ACCUM, RB>(acc, bias, C + (size_t)bz * cB, ldC,
        blockIdx.y * 128, blockIdx.x * 128, rpb, ostride, ooff, ACT);
}

// ---------------- final GEMM: attn_out + weighted combine fused -------------
__global__ __launch_bounds__(256, 2) void gemm_final(
    const float* __restrict__ W, const float* __restrict__ bias,
    const float* __restrict__ x1, const float* __restrict__ x2,
    float* __restrict__ out)
{
    __shared__ __align__(16) float As[2][16][136];
    __shared__ __align__(16) float Bs[2][2][128][8];
    int m0 = blockIdx.y * 128, n0 = blockIdx.x * 128;
    float acc[2][8][4];
    mma_mainloop<false>(As, Bs, d_o, W, Dc, 0, m0, n0, acc);

    const int tid = threadIdx.x, lane = tid & 31, warp = tid >> 5;
    const int wm = warp >> 1, wn = warp & 1;
    const int gid = lane >> 2, tig = lane & 3;

    #pragma unroll
    for (int mt = 0; mt < 2; mt++) {
        #pragma unroll
        for (int rh = 0; rh < 2; rh++) {
            int r = m0 + wm * 32 + mt * 16 + gid + rh * 8;
            int b = r / Sc;
            int s = r - b * Sc;
            const float* w = d_wts + b * 4;
            float w0 = w[0], w1 = w[1], w2 = w[2], w3 = w[3];
            const float* lfr = d_lf + (size_t)r * Dc;
            const float* xo; const float* xv; float* dst;
            if (s < N1c) {
                size_t rr = (size_t)b * N1c + s;
                xo = d_xout + rr * Dc;
                xv = x1 + rr * Dc;
                dst = out + rr * Dc;
            } else {
                int s2 = s - N1c;
                xo = d_xout + ((size_t)b * N1c + s2) * Dc;
                xv = x2 + ((size_t)b * N2c + s2) * Dc;
                dst = out + (size_t)Bb * N1c * Dc + ((size_t)b * N2c + s2) * Dc;
            }
            #pragma unroll
            for (int nt = 0; nt < 8; nt++) {
                int col = n0 + wn * 64 + nt * 8 + tig * 2;
                float2 bc = *(const float2*)(bias + col);
                float op0 = acc[mt][nt][rh * 2 + 0] + bc.x;
                float op1 = acc[mt][nt][rh * 2 + 1] + bc.y;
                float2 l = *(const float2*)(lfr + col);
                float2 g = *(const float2*)(xo + col);
                float2 y = *(const float2*)(xv + col);
                float o0 = w0 * l.x + w1 * g.x + w2 * op0 + w3 * y.x;
                float o1 = w0 * l.y + w1 * g.y + w2 * op1 + w3 * y.y;
                *(float2*)(dst + col) = make_float2(o0, o1);
            }
        }
    }
}

// ---------------- attention via tf32 MMA (interleaved smem) ------------------
// Ks: [c8blk(4)][r(128)][8] word=((c&3)^(r&3))*2+((c>>2)&1)  (LDS.64 b-frags)
// Vs: [k8blk(16)][c(32)][8] word=(k&3)*2+((k>>2)&1)          (LDS.64 b-frags)
// Ps: per-warp frag quads [ks(16)][gid(8)][tq^gidswz(4)][4]  (LDS.128 a-frags)
#define ATTN_SMEM_FLOATS (4096 + 4096 + 16384)

__global__ __launch_bounds__(256, 2) void attn_mma()
{
    extern __shared__ float sm[];
    float* Ks = sm;            // 4096
    float* Vs = sm + 4096;     // 4096
    float* Ps = sm + 8192;     // 16384 (8 warps x 2048)

    const int qt = blockIdx.x;
    const int bh = blockIdx.y;
    const int b = bh >> 3, h = bh & 7;
    const int tid = threadIdx.x, lane = tid & 31, warp = tid >> 5;
    const int gid = lane >> 2, tig = lane & 3;
    const int gsw = gid & 3;
    const int m0 = qt * 128;
    const float* base = d_qkv + (size_t)b * Sc * (3 * Dc);
    const float scale = 0.17677669529663688f;   // 1/sqrt(32)
    float* Pw = Ps + warp * 2048;

    // Q fragments (scaled, raw fp32 bits), rows warp*16 + gid (+8)
    unsigned qf[4][4];
    {
        const float* q0 = base + (size_t)(m0 + warp * 16 + gid) * (3 * Dc) + h * HDc;
        const float* q1 = q0 + (size_t)8 * (3 * Dc);
        #pragma unroll
        for (int ks = 0; ks < 4; ks++) {
            qf[ks][0] = __float_as_uint(q0[ks * 8 + tig] * scale);
            qf[ks][1] = __float_as_uint(q1[ks * 8 + tig] * scale);
            qf[ks][2] = __float_as_uint(q0[ks * 8 + tig + 4] * scale);
            qf[ks][3] = __float_as_uint(q1[ks * 8 + tig + 4] * scale);
        }
    }

    float oc[4][4];
    #pragma unroll
    for (int i = 0; i < 4; i++)
        #pragma unroll
        for (int j = 0; j < 4; j++) oc[i][j] = 0.f;
    float lacc0 = 0.f, lacc1 = 0.f;

    for (int c = 0; c < 6; c++) {
        const int kv0 = c * 128;
        __syncthreads();   // all warps done reading Ks/Vs of prev chunk

        // stage K (c-fast map; 4-way-bounded STS.32)
        #pragma unroll
        for (int it = 0; it < 4; it++) {
            int i = tid + it * 256;
            int cc = (i & 7) * 4, r = i >> 3;
            const float* src = base + (size_t)(kv0 + r) * (3 * Dc) + Dc + h * HDc + cc;
            float4 v = *(const float4*)src;
            float vv[4] = { v.x, v.y, v.z, v.w };
            #pragma unroll
            for (int j = 0; j < 4; j++) {
                int cq = cc + j;
                Ks[(((cq >> 3) * 128 + r) * 8) + (((cq & 3) ^ (r & 3)) * 2) + ((cq >> 2) & 1)] = vv[j];
            }
        }
        // stage V (r-fast map)
        #pragma unroll
        for (int it = 0; it < 4; it++) {
            int i = tid + it * 256;
            int r = i & 127, cg = (i >> 7) * 4;
            const float* src = base + (size_t)(kv0 + r) * (3 * Dc) + 2 * Dc + h * HDc + cg;
            float4 v = *(const float4*)src;
            int w = (r & 3) * 2 + ((r >> 2) & 1);
            int qb = (r >> 3) * 32 + cg;
            Vs[(qb + 0) * 8 + w] = v.x; Vs[(qb + 1) * 8 + w] = v.y;
            Vs[(qb + 2) * 8 + w] = v.z; Vs[(qb + 3) * 8 + w] = v.w;
        }
        __syncthreads();

        // S = Q @ K^T, exp, write P (frag-quad layout, warp-private)
        #pragma unroll
        for (int half = 0; half < 2; half++) {
            float sc_[8][4];
            #pragma unroll
            for (int nt = 0; nt < 8; nt++)
                #pragma unroll
                for (int j = 0; j < 4; j++) sc_[nt][j] = 0.f;
            #pragma unroll
            for (int ks = 0; ks < 4; ks++) {
                #pragma unroll
                for (int nt = 0; nt < 8; nt++) {
                    int nb = half * 64 + nt * 8 + gid;
                    float2 k2 = *(const float2*)&Ks[((ks * 128 + nb) * 8) + ((tig ^ gsw) * 2)];
                    unsigned bf[2] = { __float_as_uint(k2.x), __float_as_uint(k2.y) };
                    mma_tf32(sc_[nt], qf[ks], bf);
                }
            }
            #pragma unroll
            for (int nt = 0; nt < 8; nt++) {
                float p0 = __expf(sc_[nt][0]);
                float p1 = __expf(sc_[nt][1]);
                float p2 = __expf(sc_[nt][2]);
                float p3 = __expf(sc_[nt][3]);
                lacc0 += p0 + p1;
                lacc1 += p2 + p3;
                int ksq = half * 8 + nt;
                int tc0 = tig * 2, tc1 = tc0 + 1;
                float* pb = Pw + ksq * 128 + gid * 16;
                *(float2*)&pb[((tc0 & 3) ^ gsw) * 4 + (tc0 >> 2) * 2] = make_float2(p0, p2);
                *(float2*)&pb[((tc1 & 3) ^ gsw) * 4 + (tc1 >> 2) * 2] = make_float2(p1, p3);
            }
        }
        __syncwarp();

        // O += P @ V  (a-frags: one LDS.128 per k8; bv: LDS.64 pairs)
        #pragma unroll
        for (int ks = 0; ks < 16; ks++) {
            float4 aq = *(const float4*)&Pw[ks * 128 + gid * 16 + ((tig ^ gsw) * 4)];
            unsigned a[4] = { __float_as_uint(aq.x), __float_as_uint(aq.y),
                              __float_as_uint(aq.z), __float_as_uint(aq.w) };
            #pragma unroll
            for (int nf = 0; nf < 4; nf++) {
                float2 v2 = *(const float2*)&Vs[((ks * 32 + nf * 8 + gid) * 8) + tig * 2];
                unsigned bv[2] = { __float_as_uint(v2.x), __float_as_uint(v2.y) };
                mma_tf32(oc[nf], a, bv);
            }
        }
        __syncwarp();   // P reads done before next chunk rewrites
    }

    // row-sum reduce across the quad (lanes sharing gid)
    lacc0 += __shfl_xor_sync(0xffffffffu, lacc0, 1);
    lacc0 += __shfl_xor_sync(0xffffffffu, lacc0, 2);
    lacc1 += __shfl_xor_sync(0xffffffffu, lacc1, 1);
    lacc1 += __shfl_xor_sync(0xffffffffu, lacc1, 2);
    float inv0 = 1.f / lacc0, inv1 = 1.f / lacc1;

    float* o0 = d_o + (size_t)(b * Sc + m0 + warp * 16 + gid) * Dc + h * HDc;
    float* o1 = o0 + 8 * Dc;
    #pragma unroll
    for (int nf = 0; nf < 4; nf++) {
        int col = nf * 8 + tig * 2;
        *(float2*)&o0[col] = make_float2(oc[nf][0] * inv0, oc[nf][1] * inv0);
        *(float2*)&o1[col] = make_float2(oc[nf][2] * inv1, oc[nf][3] * inv1);
    }
}

// ---------------- launch ----------------------------------------------------
extern "C" void kernel_launch(void* const* d_in, const int* in_sizes, int n_in,
                              void* d_out, int out_size)
{
    const float* x1        = (const float*)d_in[0];
    const float* x2        = (const float*)d_in[1];
    const float* r_w1      = (const float*)d_in[2];
    const float* r_b1      = (const float*)d_in[3];
    const float* ln_g      = (const float*)d_in[4];
    const float* ln_b      = (const float*)d_in[5];
    const float* r_w2      = (const float*)d_in[6];
    const float* r_b2      = (const float*)d_in[7];
    const float* lf_w      = (const float*)d_in[8];
    const float* lf_b      = (const float*)d_in[9];
    const float* af2_w     = (const float*)d_in[10];
    const float* af2_b     = (const float*)d_in[11];
    const float* af3_w     = (const float*)d_in[12];
    const float* af3_b     = (const float*)d_in[13];
    const float* attn_in_w = (const float*)d_in[14];
    const float* attn_in_b = (const float*)d_in[15];
    const float* attn_out_w= (const float*)d_in[16];
    const float* attn_out_b= (const float*)d_in[17];
    float* out = (float*)d_out;

    float *qkv, *lf, *xout;
    cudaGetSymbolAddress((void**)&qkv,  d_qkv);
    cudaGetSymbolAddress((void**)&lf,   d_lf);
    cudaGetSymbolAddress((void**)&xout, d_xout);

    const int ATTN_SMEM = ATTN_SMEM_FLOATS * (int)sizeof(float);  // 98304
    cudaFuncSetAttribute(attn_mma, cudaFuncAttributeMaxDynamicSharedMemorySize, ATTN_SMEM);

    const int BIGR = 1 << 30;

    // 1. router weights
    router_kernel<<<Bb, 256>>>(x1, x2, r_w1, r_b1, ln_g, ln_b, r_w2, r_b2);

    // 2. merged GEMMs with A = x1: qkv(6 n-blocks) | lf(2) | a1(2)
    {
        SegP s0 = { attn_in_w, attn_in_b, qkv, 3 * Dc, N1c, Sc, 0,   0 };
        SegP s1 = { lf_w,      lf_b,      lf,  Dc,     N1c, Sc, 0,   1 };
        SegP s2 = { af2_w,     af2_b,     xout,Dc,     BIGR, 0, 0,   1 };
        gemm_ms<<<dim3(10, 128), 256>>>(x1, Dc, s0, s1, s2, 6, 8);
    }
    // 3. merged GEMMs with A = x2: qkv(6) | lf(2)
    {
        SegP s0 = { attn_in_w, attn_in_b, qkv, 3 * Dc, N2c, Sc, N1c, 0 };
        SegP s1 = { lf_w,      lf_b,      lf,  Dc,     N2c, Sc, N1c, 1 };
        gemm_ms<<<dim3(8, 64), 256>>>(x2, Dc, s0, s1, s1, 6, 8);
    }

    // 4. xout += elu(af3_w @ x2[b] + af3_b)   (per-batch NN GEMM, row bias)
    gemm1<1, true, true, true><<<dim3(2, 4, Bb), 256>>>(
        af3_w, x2, af3_b, xout, N2c, Dc, Dc, BIGR, 0, 0,
        0, (size_t)N2c * Dc, (size_t)N1c * Dc);

    // 5. attention via tensor cores (reads d_qkv, writes d_o)
    attn_mma<<<dim3(6, 256), 256, ATTN_SMEM>>>();

    // 6. fused: (d_o @ attn_out_w.T + b) combined with lf/xout/x -> out
    gemm_final<<<dim3(2, 192), 256>>>(attn_out_w, attn_out_b, x1, x2, out);
}

// round 9
// speedup vs baseline: 3.7150x; 1.1030x over previous
#include <cuda_runtime.h>
#include <math.h>

// Shapes (fixed by the problem)
#define Bb   32
#define N1c  512
#define N2c  256
#define Dc   256
#define Hc   8
#define HDc  32
#define Sc   768   // N1 + N2

// ---------------- tf32 MMA (raw fp32 operands; HW truncates to tf32) --------
__device__ __forceinline__ void mma_tf32(float (&c)[4], const unsigned (&a)[4],
                                         const unsigned (&b)[2]) {
    asm("mma.sync.aligned.m16n8k8.row.col.f32.tf32.tf32.f32 "
        "{%0,%1,%2,%3},{%4,%5,%6,%7},{%8,%9},{%0,%1,%2,%3};"
        : "+f"(c[0]), "+f"(c[1]), "+f"(c[2]), "+f"(c[3])
        : "r"(a[0]), "r"(a[1]), "r"(a[2]), "r"(a[3]), "r"(b[0]), "r"(b[1]));
}

__device__ __forceinline__ void cp16(float* dst, const float* src) {
    unsigned ds = (unsigned)__cvta_generic_to_shared(dst);
    asm volatile("cp.async.cg.shared.global [%0], [%1], 16;" :: "r"(ds), "l"(src));
}
__device__ __forceinline__ void cp_commit() {
    asm volatile("cp.async.commit_group;" ::: "memory");
}

// ---------------- scratch (device globals; no allocations allowed) ----------
__device__ __align__(16) float d_qkv [Bb * Sc * 3 * Dc];
__device__ __align__(16) float d_lf  [Bb * Sc * Dc];
__device__ __align__(16) float d_xout[Bb * N1c * Dc];
__device__ __align__(16) float d_o   [Bb * Sc * Dc];
__device__ float d_wts [Bb * 4];

// ---------------- router ----------------------------------------------------
__global__ __launch_bounds__(256) void router_kernel(
    const float* __restrict__ x1, const float* __restrict__ x2,
    const float* __restrict__ r_w1, const float* __restrict__ r_b1,
    const float* __restrict__ ln_g, const float* __restrict__ ln_b,
    const float* __restrict__ r_w2, const float* __restrict__ r_b2)
{
    __shared__ float m[2 * Dc];
    __shared__ float4 ps[4][64];
    __shared__ float hb[Dc];
    __shared__ float red[8];
    __shared__ float lg[4];
    int b = blockIdx.x, t = threadIdx.x;
    int c4 = t & 63, rq = t >> 6;

    {
        const float4* p = (const float4*)(x1 + (size_t)b * N1c * Dc) + (size_t)rq * 128 * 64 + c4;
        float4 s = make_float4(0.f, 0.f, 0.f, 0.f);
        for (int n = 0; n < 128; n++) {
            float4 v = p[(size_t)n * 64];
            s.x += v.x; s.y += v.y; s.z += v.z; s.w += v.w;
        }
        ps[rq][c4] = s;
    }
    __syncthreads();
    if (t < 64) {
        float4 a = ps[0][t], b1 = ps[1][t], c = ps[2][t], d = ps[3][t];
        m[t * 4 + 0] = (a.x + b1.x + c.x + d.x) * (1.f / N1c);
        m[t * 4 + 1] = (a.y + b1.y + c.y + d.y) * (1.f / N1c);
        m[t * 4 + 2] = (a.z + b1.z + c.z + d.z) * (1.f / N1c);
        m[t * 4 + 3] = (a.w + b1.w + c.w + d.w) * (1.f / N1c);
    }
    __syncthreads();
    {
        const float4* p = (const float4*)(x2 + (size_t)b * N2c * Dc) + (size_t)rq * 64 * 64 + c4;
        float4 s = make_float4(0.f, 0.f, 0.f, 0.f);
        for (int n = 0; n < 64; n++) {
            float4 v = p[(size_t)n * 64];
            s.x += v.x; s.y += v.y; s.z += v.z; s.w += v.w;
        }
        ps[rq][c4] = s;
    }
    __syncthreads();
    if (t < 64) {
        float4 a = ps[0][t], b1 = ps[1][t], c = ps[2][t], d = ps[3][t];
        m[Dc + t * 4 + 0] = (a.x + b1.x + c.x + d.x) * (1.f / N2c);
        m[Dc + t * 4 + 1] = (a.y + b1.y + c.y + d.y) * (1.f / N2c);
        m[Dc + t * 4 + 2] = (a.z + b1.z + c.z + d.z) * (1.f / N2c);
        m[Dc + t * 4 + 3] = (a.w + b1.w + c.w + d.w) * (1.f / N2c);
    }
    __syncthreads();

    float acc = r_b1[t];
    const float* wr = r_w1 + (size_t)t * (2 * Dc);
    #pragma unroll 4
    for (int k = 0; k < 2 * Dc; k++) acc += m[k] * wr[k];

    float v = acc;
    for (int o = 16; o; o >>= 1) v += __shfl_down_sync(0xffffffffu, v, o);
    if ((t & 31) == 0) red[t >> 5] = v;
    __syncthreads();
    if (t < 8) {
        v = red[t];
        for (int o = 4; o; o >>= 1) v += __shfl_down_sync(0xffu, v, o);
        if (t == 0) red[0] = v;
    }
    __syncthreads();
    float mu = red[0] * (1.f / Dc);
    __syncthreads();
    float dd = acc - mu;
    v = dd * dd;
    for (int o = 16; o; o >>= 1) v += __shfl_down_sync(0xffffffffu, v, o);
    if ((t & 31) == 0) red[t >> 5] = v;
    __syncthreads();
    if (t < 8) {
        v = red[t];
        for (int o = 4; o; o >>= 1) v += __shfl_down_sync(0xffu, v, o);
        if (t == 0) red[0] = v;
    }
    __syncthreads();
    float var = red[0] * (1.f / Dc);
    float y = dd * rsqrtf(var + 1e-5f) * ln_g[t] + ln_b[t];
    float g = 0.5f * y * (1.f + erff(y * 0.70710678118654752f));
    hb[t] = g;
    __syncthreads();

    if (t < 4) {
        float a = r_b2[t];
        const float* w2 = r_w2 + (size_t)t * Dc;
        for (int k = 0; k < Dc; k++) a += hb[k] * w2[k];
        lg[t] = a;
    }
    __syncthreads();
    if (t == 0) {
        float mx = fmaxf(fmaxf(lg[0], lg[1]), fmaxf(lg[2], lg[3]));
        float e0 = expf(lg[0] - mx), e1 = expf(lg[1] - mx);
        float e2 = expf(lg[2] - mx), e3 = expf(lg[3] - mx);
        float inv = 1.f / (e0 + e1 + e2 + e3);
        d_wts[b * 4 + 0] = e0 * inv; d_wts[b * 4 + 1] = e1 * inv;
        d_wts[b * 4 + 2] = e2 * inv; d_wts[b * 4 + 3] = e3 * inv;
    }
}

// ---------------- tf32 MMA GEMM: BM=128, BN=128, BK=16, cp.async x4 stages --
// K is always 256 (16 tiles). Prefetch distance 3.
// non-BT: A [row][20], B [row][20] natural (pad 20 -> conflict-free LDS.32).
// BT:     A [row][20], B [k][136] (R5-proven padded layout).
// Stage float strides: non-BT 5120 (A 2560 + B 2560); BT 4736 (A 2560 + B 2176).

template<bool BT>
__device__ __forceinline__ void issue_tile(
    float* sm, const float* __restrict__ A, const float* __restrict__ W,
    int ldB, int m0, int n0, int t)
{
    const int tid = threadIdx.x;
    const int STG = BT ? 4736 : 5120;
    const int k0 = t * 16;
    float* As = sm + (t & 3) * STG;
    float* Bs = As + 2560;
    #pragma unroll
    for (int h = 0; h < 2; h++) {
        int c = tid + h * 256;
        int mm = c >> 2, ko = (c & 3) * 4;
        cp16(As + mm * 20 + ko, A + (size_t)(m0 + mm) * 256 + k0 + ko);
    }
    if (BT) {
        #pragma unroll
        for (int h = 0; h < 2; h++) {
            int c = tid + h * 256;
            int k = c >> 5, nq = (c & 31) * 4;
            cp16(Bs + k * 136 + nq, W + (size_t)(k0 + k) * ldB + n0 + nq);
        }
    } else {
        #pragma unroll
        for (int h = 0; h < 2; h++) {
            int c = tid + h * 256;
            int n = c >> 2, ko = (c & 3) * 4;
            cp16(Bs + n * 20 + ko, W + (size_t)(n0 + n) * 256 + k0 + ko);
        }
    }
    cp_commit();
}

template<bool BT>
__device__ __forceinline__ void mma_mainloop_ca(
    float* sm, const float* __restrict__ A, const float* __restrict__ W,
    int ldB, int m0, int n0, float (&acc)[2][8][4])
{
    const int tid = threadIdx.x, lane = tid & 31, warp = tid >> 5;
    const int wm = warp >> 1, wn = warp & 1;
    const int gid = lane >> 2, tig = lane & 3;
    const int STG = BT ? 4736 : 5120;

    #pragma unroll
    for (int i = 0; i < 2; i++)
        #pragma unroll
        for (int j = 0; j < 8; j++)
            #pragma unroll
            for (int c = 0; c < 4; c++) acc[i][j][c] = 0.f;

    issue_tile<BT>(sm, A, W, ldB, m0, n0, 0);
    issue_tile<BT>(sm, A, W, ldB, m0, n0, 1);
    issue_tile<BT>(sm, A, W, ldB, m0, n0, 2);

    for (int t = 0; t < 16; t++) {
        if (t < 14)      asm volatile("cp.async.wait_group 2;" ::: "memory");
        else if (t == 14) asm volatile("cp.async.wait_group 1;" ::: "memory");
        else              asm volatile("cp.async.wait_group 0;" ::: "memory");
        __syncthreads();
        if (t + 3 < 16) issue_tile<BT>(sm, A, W, ldB, m0, n0, t + 3);

        const float* As = sm + (t & 3) * STG;
        const float* Bs = As + 2560;
        #pragma unroll
        for (int ks8 = 0; ks8 < 2; ks8++) {
            unsigned af[2][4];
            #pragma unroll
            for (int mt = 0; mt < 2; mt++) {
                int mb = wm * 32 + mt * 16 + gid;
                af[mt][0] = __float_as_uint(As[mb * 20 + ks8 * 8 + tig]);
                af[mt][1] = __float_as_uint(As[(mb + 8) * 20 + ks8 * 8 + tig]);
                af[mt][2] = __float_as_uint(As[mb * 20 + ks8 * 8 + tig + 4]);
                af[mt][3] = __float_as_uint(As[(mb + 8) * 20 + ks8 * 8 + tig + 4]);
            }
            #pragma unroll
            for (int nt = 0; nt < 8; nt++) {
                int nb = wn * 64 + nt * 8 + gid;
                unsigned bf[2];
                if (BT) {
                    bf[0] = __float_as_uint(Bs[(ks8 * 8 + tig) * 136 + nb]);
                    bf[1] = __float_as_uint(Bs[(ks8 * 8 + tig + 4) * 136 + nb]);
                } else {
                    bf[0] = __float_as_uint(Bs[nb * 20 + ks8 * 8 + tig]);
                    bf[1] = __float_as_uint(Bs[nb * 20 + ks8 * 8 + tig + 4]);
                }
                mma_tf32(acc[0][nt], af[0], bf);
                mma_tf32(acc[1][nt], af[1], bf);
            }
        }
    }
}

// ---------------- standard epilogue (fragment layout) ------------------------
template<bool ACCUM, bool RB>
__device__ __forceinline__ void epi_std(
    float (&acc)[2][8][4], const float* __restrict__ bias, float* __restrict__ C,
    int ldC, int m0, int n0, int rpb, int ostride, int ooff, int act)
{
    const int tid = threadIdx.x, lane = tid & 31, warp = tid >> 5;
    const int wm = warp >> 1, wn = warp & 1;
    const int gid = lane >> 2, tig = lane & 3;

    #pragma unroll
    for (int mt = 0; mt < 2; mt++) {
        #pragma unroll
        for (int rh = 0; rh < 2; rh++) {
            int r = m0 + wm * 32 + mt * 16 + gid + rh * 8;
            float rbv = RB ? bias[r] : 0.f;
            int grow = (r / rpb) * ostride + ooff + (r % rpb);
            float* dst = C + (size_t)grow * ldC;
            #pragma unroll
            for (int nt = 0; nt < 8; nt++) {
                int col = n0 + wn * 64 + nt * 8 + tig * 2;
                float v0 = acc[mt][nt][rh * 2 + 0];
                float v1 = acc[mt][nt][rh * 2 + 1];
                if (RB) { v0 += rbv; v1 += rbv; }
                else {
                    float2 bc = *(const float2*)(bias + col);
                    v0 += bc.x; v1 += bc.y;
                }
                if (act) {
                    v0 = v0 > 0.f ? v0 : expm1f(v0);
                    v1 = v1 > 0.f ? v1 : expm1f(v1);
                }
                if (ACCUM) {
                    float2 c = *(float2*)(dst + col);
                    v0 += c.x; v1 += c.y;
                }
                *(float2*)(dst + col) = make_float2(v0, v1);
            }
        }
    }
}

// ---------------- segmented multi-output GEMM (shared A) --------------------
struct SegP {
    const float* W; const float* bias; float* C;
    int ldC; int rpb; int ostride; int ooff; int act;
};

__global__ __launch_bounds__(256, 2) void gemm_ms(
    const float* __restrict__ A,
    SegP s0, SegP s1, SegP s2, int t1, int t2)
{
    extern __shared__ float sm[];
    int bx = blockIdx.x;
    SegP sp; int nb;
    if (bx < t1)      { sp = s0; nb = bx; }
    else if (bx < t2) { sp = s1; nb = bx - t1; }
    else              { sp = s2; nb = bx - t2; }
    float acc[2][8][4];
    mma_mainloop_ca<false>(sm, A, sp.W, 0, blockIdx.y * 128, nb * 128, acc);
    epi_std<false, false>(acc, sp.bias, sp.C, sp.ldC,
        blockIdx.y * 128, nb * 128, sp.rpb, sp.ostride, sp.ooff, sp.act);
}

// ---------------- standalone (batched) GEMM ---------------------------------
template<int ACT, bool BT, bool ACCUM, bool RB>
__global__ __launch_bounds__(256, 2) void gemm1(
    const float* __restrict__ A, const float* __restrict__ W,
    const float* __restrict__ bias, float* __restrict__ C,
    int ldB, int ldC, int rpb, int ostride, int ooff,
    size_t aB, size_t bB, size_t cB)
{
    extern __shared__ float sm[];
    int bz = blockIdx.z;
    float acc[2][8][4];
    mma_mainloop_ca<BT>(sm, A + (size_t)bz * aB, W + (size_t)bz * bB,
                        ldB, blockIdx.y * 128, blockIdx.x * 128, acc);
    epi_std<ACCUM, RB>(acc, bias, C + (size_t)bz * cB, ldC,
        blockIdx.y * 128, blockIdx.x * 128, rpb, ostride, ooff, ACT);
}

// ---------------- final GEMM: attn_out + weighted combine fused -------------
__global__ __launch_bounds__(256, 2) void gemm_final(
    const float* __restrict__ W, const float* __restrict__ bias,
    const float* __restrict__ x1, const float* __restrict__ x2,
    float* __restrict__ out)
{
    extern __shared__ float sm[];
    int m0 = blockIdx.y * 128, n0 = blockIdx.x * 128;
    float acc[2][8][4];
    mma_mainloop_ca<false>(sm, d_o, W, 0, m0, n0, acc);

    const int tid = threadIdx.x, lane = tid & 31, warp = tid >> 5;
    const int wm = warp >> 1, wn = warp & 1;
    const int gid = lane >> 2, tig = lane & 3;

    #pragma unroll
    for (int mt = 0; mt < 2; mt++) {
        #pragma unroll
        for (int rh = 0; rh < 2; rh++) {
            int r = m0 + wm * 32 + mt * 16 + gid + rh * 8;
            int b = r / Sc;
            int s = r - b * Sc;
            const float* w = d_wts + b * 4;
            float w0 = w[0], w1 = w[1], w2 = w[2], w3 = w[3];
            const float* lfr = d_lf + (size_t)r * Dc;
            const float* xo; const float* xv; float* dst;
            if (s < N1c) {
                size_t rr = (size_t)b * N1c + s;
                xo = d_xout + rr * Dc;
                xv = x1 + rr * Dc;
                dst = out + rr * Dc;
            } else {
                int s2 = s - N1c;
                xo = d_xout + ((size_t)b * N1c + s2) * Dc;
                xv = x2 + ((size_t)b * N2c + s2) * Dc;
                dst = out + (size_t)Bb * N1c * Dc + ((size_t)b * N2c + s2) * Dc;
            }
            #pragma unroll
            for (int nt = 0; nt < 8; nt++) {
                int col = n0 + wn * 64 + nt * 8 + tig * 2;
                float2 bc = *(const float2*)(bias + col);
                float op0 = acc[mt][nt][rh * 2 + 0] + bc.x;
                float op1 = acc[mt][nt][rh * 2 + 1] + bc.y;
                float2 l = *(const float2*)(lfr + col);
                float2 g = *(const float2*)(xo + col);
                float2 y = *(const float2*)(xv + col);
                float o0 = w0 * l.x + w1 * g.x + w2 * op0 + w3 * y.x;
                float o1 = w0 * l.y + w1 * g.y + w2 * op1 + w3 * y.y;
                *(float2*)(dst + col) = make_float2(o0, o1);
            }
        }
    }
}

// ---------------- attention via tf32 MMA (interleaved smem) ------------------
// Ks: [c8blk(4)][r(128)][8] word=((c&3)^(r&3))*2+((c>>2)&1)  (LDS.64 b-frags)
// Vs: [k8blk(16)][c(32)][8] word=(k&3)*2+((k>>2)&1)          (LDS.64 b-frags)
// Ps: per-warp frag quads [ks(16)][gid(8)][tq^gidswz(4)][4]  (LDS.128 a-frags)
#define ATTN_SMEM_FLOATS (4096 + 4096 + 16384)

__global__ __launch_bounds__(256, 2) void attn_mma()
{
    extern __shared__ float sm[];
    float* Ks = sm;            // 4096
    float* Vs = sm + 4096;     // 4096
    float* Ps = sm + 8192;     // 16384 (8 warps x 2048)

    const int qt = blockIdx.x;
    const int bh = blockIdx.y;
    const int b = bh >> 3, h = bh & 7;
    const int tid = threadIdx.x, lane = tid & 31, warp = tid >> 5;
    const int gid = lane >> 2, tig = lane & 3;
    const int gsw = gid & 3;
    const int m0 = qt * 128;
    const float* base = d_qkv + (size_t)b * Sc * (3 * Dc);
    const float scale = 0.17677669529663688f;   // 1/sqrt(32)
    float* Pw = Ps + warp * 2048;

    // Q fragments (scaled, raw fp32 bits), rows warp*16 + gid (+8)
    unsigned qf[4][4];
    {
        const float* q0 = base + (size_t)(m0 + warp * 16 + gid) * (3 * Dc) + h * HDc;
        const float* q1 = q0 + (size_t)8 * (3 * Dc);
        #pragma unroll
        for (int ks = 0; ks < 4; ks++) {
            qf[ks][0] = __float_as_uint(q0[ks * 8 + tig] * scale);
            qf[ks][1] = __float_as_uint(q1[ks * 8 + tig] * scale);
            qf[ks][2] = __float_as_uint(q0[ks * 8 + tig + 4] * scale);
            qf[ks][3] = __float_as_uint(q1[ks * 8 + tig + 4] * scale);
        }
    }

    float oc[4][4];
    #pragma unroll
    for (int i = 0; i < 4; i++)
        #pragma unroll
        for (int j = 0; j < 4; j++) oc[i][j] = 0.f;
    float lacc0 = 0.f, lacc1 = 0.f;

    for (int c = 0; c < 6; c++) {
        const int kv0 = c * 128;
        __syncthreads();   // all warps done reading Ks/Vs of prev chunk

        // stage K (c-fast map; 4-way-bounded STS.32)
        #pragma unroll
        for (int it = 0; it < 4; it++) {
            int i = tid + it * 256;
            int cc = (i & 7) * 4, r = i >> 3;
            const float* src = base + (size_t)(kv0 + r) * (3 * Dc) + Dc + h * HDc + cc;
            float4 v = *(const float4*)src;
            float vv[4] = { v.x, v.y, v.z, v.w };
            #pragma unroll
            for (int j = 0; j < 4; j++) {
                int cq = cc + j;
                Ks[(((cq >> 3) * 128 + r) * 8) + (((cq & 3) ^ (r & 3)) * 2) + ((cq >> 2) & 1)] = vv[j];
            }
        }
        // stage V (r-fast map)
        #pragma unroll
        for (int it = 0; it < 4; it++) {
            int i = tid + it * 256;
            int r = i & 127, cg = (i >> 7) * 4;
            const float* src = base + (size_t)(kv0 + r) * (3 * Dc) + 2 * Dc + h * HDc + cg;
            float4 v = *(const float4*)src;
            int w = (r & 3) * 2 + ((r >> 2) & 1);
            int qb = (r >> 3) * 32 + cg;
            Vs[(qb + 0) * 8 + w] = v.x; Vs[(qb + 1) * 8 + w] = v.y;
            Vs[(qb + 2) * 8 + w] = v.z; Vs[(qb + 3) * 8 + w] = v.w;
        }
        __syncthreads();

        // S = Q @ K^T, exp, write P (frag-quad layout, warp-private)
        #pragma unroll
        for (int half = 0; half < 2; half++) {
            float sc_[8][4];
            #pragma unroll
            for (int nt = 0; nt < 8; nt++)
                #pragma unroll
                for (int j = 0; j < 4; j++) sc_[nt][j] = 0.f;
            #pragma unroll
            for (int ks = 0; ks < 4; ks++) {
                #pragma unroll
                for (int nt = 0; nt < 8; nt++) {
                    int nb = half * 64 + nt * 8 + gid;
                    float2 k2 = *(const float2*)&Ks[((ks * 128 + nb) * 8) + ((tig ^ gsw) * 2)];
                    unsigned bf[2] = { __float_as_uint(k2.x), __float_as_uint(k2.y) };
                    mma_tf32(sc_[nt], qf[ks], bf);
                }
            }
            #pragma unroll
            for (int nt = 0; nt < 8; nt++) {
                float p0 = __expf(sc_[nt][0]);
                float p1 = __expf(sc_[nt][1]);
                float p2 = __expf(sc_[nt][2]);
                float p3 = __expf(sc_[nt][3]);
                lacc0 += p0 + p1;
                lacc1 += p2 + p3;
                int ksq = half * 8 + nt;
                int tc0 = tig * 2, tc1 = tc0 + 1;
                float* pb = Pw + ksq * 128 + gid * 16;
                *(float2*)&pb[((tc0 & 3) ^ gsw) * 4 + (tc0 >> 2) * 2] = make_float2(p0, p2);
                *(float2*)&pb[((tc1 & 3) ^ gsw) * 4 + (tc1 >> 2) * 2] = make_float2(p1, p3);
            }
        }
        __syncwarp();

        // O += P @ V  (a-frags: one LDS.128 per k8; bv: LDS.64 pairs)
        #pragma unroll
        for (int ks = 0; ks < 16; ks++) {
            float4 aq = *(const float4*)&Pw[ks * 128 + gid * 16 + ((tig ^ gsw) * 4)];
            unsigned a[4] = { __float_as_uint(aq.x), __float_as_uint(aq.y),
                              __float_as_uint(aq.z), __float_as_uint(aq.w) };
            #pragma unroll
            for (int nf = 0; nf < 4; nf++) {
                float2 v2 = *(const float2*)&Vs[((ks * 32 + nf * 8 + gid) * 8) + tig * 2];
                unsigned bv[2] = { __float_as_uint(v2.x), __float_as_uint(v2.y) };
                mma_tf32(oc[nf], a, bv);
            }
        }
        __syncwarp();   // P reads done before next chunk rewrites
    }

    // row-sum reduce across the quad (lanes sharing gid)
    lacc0 += __shfl_xor_sync(0xffffffffu, lacc0, 1);
    lacc0 += __shfl_xor_sync(0xffffffffu, lacc0, 2);
    lacc1 += __shfl_xor_sync(0xffffffffu, lacc1, 1);
    lacc1 += __shfl_xor_sync(0xffffffffu, lacc1, 2);
    float inv0 = 1.f / lacc0, inv1 = 1.f / lacc1;

    float* o0 = d_o + (size_t)(b * Sc + m0 + warp * 16 + gid) * Dc + h * HDc;
    float* o1 = o0 + 8 * Dc;
    #pragma unroll
    for (int nf = 0; nf < 4; nf++) {
        int col = nf * 8 + tig * 2;
        *(float2*)&o0[col] = make_float2(oc[nf][0] * inv0, oc[nf][1] * inv0);
        *(float2*)&o1[col] = make_float2(oc[nf][2] * inv1, oc[nf][3] * inv1);
    }
}

// ---------------- launch ----------------------------------------------------
extern "C" void kernel_launch(void* const* d_in, const int* in_sizes, int n_in,
                              void* d_out, int out_size)
{
    const float* x1        = (const float*)d_in[0];
    const float* x2        = (const float*)d_in[1];
    const float* r_w1      = (const float*)d_in[2];
    const float* r_b1      = (const float*)d_in[3];
    const float* ln_g      = (const float*)d_in[4];
    const float* ln_b      = (const float*)d_in[5];
    const float* r_w2      = (const float*)d_in[6];
    const float* r_b2      = (const float*)d_in[7];
    const float* lf_w      = (const float*)d_in[8];
    const float* lf_b      = (const float*)d_in[9];
    const float* af2_w     = (const float*)d_in[10];
    const float* af2_b     = (const float*)d_in[11];
    const float* af3_w     = (const float*)d_in[12];
    const float* af3_b     = (const float*)d_in[13];
    const float* attn_in_w = (const float*)d_in[14];
    const float* attn_in_b = (const float*)d_in[15];
    const float* attn_out_w= (const float*)d_in[16];
    const float* attn_out_b= (const float*)d_in[17];
    float* out = (float*)d_out;

    float *qkv, *lf, *xout;
    cudaGetSymbolAddress((void**)&qkv,  d_qkv);
    cudaGetSymbolAddress((void**)&lf,   d_lf);
    cudaGetSymbolAddress((void**)&xout, d_xout);

    const int ATTN_SMEM = ATTN_SMEM_FLOATS * (int)sizeof(float);  // 98304
    const int GEMM_SMEM_NBT = 4 * 5120 * (int)sizeof(float);      // 81920
    const int GEMM_SMEM_BT  = 4 * 4736 * (int)sizeof(float);      // 75776
    cudaFuncSetAttribute(attn_mma, cudaFuncAttributeMaxDynamicSharedMemorySize, ATTN_SMEM);
    cudaFuncSetAttribute(gemm_ms, cudaFuncAttributeMaxDynamicSharedMemorySize, GEMM_SMEM_NBT);
    cudaFuncSetAttribute(gemm_final, cudaFuncAttributeMaxDynamicSharedMemorySize, GEMM_SMEM_NBT);
    cudaFuncSetAttribute(gemm1<1, true, true, true>,
                         cudaFuncAttributeMaxDynamicSharedMemorySize, GEMM_SMEM_BT);

    const int BIGR = 1 << 30;

    // 1. router weights
    router_kernel<<<Bb, 256>>>(x1, x2, r_w1, r_b1, ln_g, ln_b, r_w2, r_b2);

    // 2. merged GEMMs with A = x1: qkv(6 n-blocks) | lf(2) | a1(2)
    {
        SegP s0 = { attn_in_w, attn_in_b, qkv, 3 * Dc, N1c, Sc, 0,   0 };
        SegP s1 = { lf_w,      lf_b,      lf,  Dc,     N1c, Sc, 0,   1 };
        SegP s2 = { af2_w,     af2_b,     xout,Dc,     BIGR, 0, 0,   1 };
        gemm_ms<<<dim3(10, 128), 256, GEMM_SMEM_NBT>>>(x1, s0, s1, s2, 6, 8);
    }
    // 3. merged GEMMs with A = x2: qkv(6) | lf(2)
    {
        SegP s0 = { attn_in_w, attn_in_b, qkv, 3 * Dc, N2c, Sc, N1c, 0 };
        SegP s1 = { lf_w,      lf_b,      lf,  Dc,     N2c, Sc, N1c, 1 };
        gemm_ms<<<dim3(8, 64), 256, GEMM_SMEM_NBT>>>(x2, s0, s1, s1, 6, 8);
    }

    // 4. xout += elu(af3_w @ x2[b] + af3_b)   (per-batch NN GEMM, row bias)
    gemm1<1, true, true, true><<<dim3(2, 4, Bb), 256, GEMM_SMEM_BT>>>(
        af3_w, x2, af3_b, xout, Dc, Dc, BIGR, 0, 0,
        0, (size_t)N2c * Dc, (size_t)N1c * Dc);

    // 5. attention via tensor cores (reads d_qkv, writes d_o)
    attn_mma<<<dim3(6, 256), 256, ATTN_SMEM>>>();

    // 6. fused: (d_o @ attn_out_w.T + b) combined with lf/xout/x -> out
    gemm_final<<<dim3(2, 192), 256, GEMM_SMEM_NBT>>>(attn_out_w, attn_out_b, x1, x2, out);
}

// round 10
// speedup vs baseline: 4.0706x; 1.0957x over previous
#include <cuda_runtime.h>
#include <math.h>

// Shapes (fixed by the problem)
#define Bb   32
#define N1c  512
#define N2c  256
#define Dc   256
#define Hc   8
#define HDc  32
#define Sc   768   // N1 + N2

// ---------------- tf32 MMA (raw fp32 operands; HW truncates to tf32) --------
__device__ __forceinline__ void mma_tf32(float (&c)[4], const unsigned (&a)[4],
                                         const unsigned (&b)[2]) {
    asm("mma.sync.aligned.m16n8k8.row.col.f32.tf32.tf32.f32 "
        "{%0,%1,%2,%3},{%4,%5,%6,%7},{%8,%9},{%0,%1,%2,%3};"
        : "+f"(c[0]), "+f"(c[1]), "+f"(c[2]), "+f"(c[3])
        : "r"(a[0]), "r"(a[1]), "r"(a[2]), "r"(a[3]), "r"(b[0]), "r"(b[1]));
}

__device__ __forceinline__ void cp16(float* dst, const float* src) {
    unsigned ds = (unsigned)__cvta_generic_to_shared(dst);
    asm volatile("cp.async.cg.shared.global [%0], [%1], 16;" :: "r"(ds), "l"(src));
}
__device__ __forceinline__ void cp_commit() {
    asm volatile("cp.async.commit_group;" ::: "memory");
}

// ---------------- scratch (device globals; no allocations allowed) ----------
__device__ __align__(16) float d_qkv [Bb * Sc * 3 * Dc];
__device__ __align__(16) float d_lf  [Bb * Sc * Dc];
__device__ __align__(16) float d_xout[Bb * N1c * Dc];   // a1 = elu(x1@af2^T+b)
__device__ __align__(16) float d_x2o [Bb * N1c * Dc];   // a2 = elu(af3@x2[b]+b)
__device__ __align__(16) float d_o   [Bb * Sc * Dc];
__device__ float d_wts [Bb * 4];

// ---------------- router ----------------------------------------------------
__global__ __launch_bounds__(256) void router_kernel(
    const float* __restrict__ x1, const float* __restrict__ x2,
    const float* __restrict__ r_w1, const float* __restrict__ r_b1,
    const float* __restrict__ ln_g, const float* __restrict__ ln_b,
    const float* __restrict__ r_w2, const float* __restrict__ r_b2)
{
    __shared__ float m[2 * Dc];
    __shared__ float4 ps[4][64];
    __shared__ float hb[Dc];
    __shared__ float red[8];
    __shared__ float lg[4];
    int b = blockIdx.x, t = threadIdx.x;
    int c4 = t & 63, rq = t >> 6;

    {
        const float4* p = (const float4*)(x1 + (size_t)b * N1c * Dc) + (size_t)rq * 128 * 64 + c4;
        float4 s = make_float4(0.f, 0.f, 0.f, 0.f);
        for (int n = 0; n < 128; n++) {
            float4 v = p[(size_t)n * 64];
            s.x += v.x; s.y += v.y; s.z += v.z; s.w += v.w;
        }
        ps[rq][c4] = s;
    }
    __syncthreads();
    if (t < 64) {
        float4 a = ps[0][t], b1 = ps[1][t], c = ps[2][t], d = ps[3][t];
        m[t * 4 + 0] = (a.x + b1.x + c.x + d.x) * (1.f / N1c);
        m[t * 4 + 1] = (a.y + b1.y + c.y + d.y) * (1.f / N1c);
        m[t * 4 + 2] = (a.z + b1.z + c.z + d.z) * (1.f / N1c);
        m[t * 4 + 3] = (a.w + b1.w + c.w + d.w) * (1.f / N1c);
    }
    __syncthreads();
    {
        const float4* p = (const float4*)(x2 + (size_t)b * N2c * Dc) + (size_t)rq * 64 * 64 + c4;
        float4 s = make_float4(0.f, 0.f, 0.f, 0.f);
        for (int n = 0; n < 64; n++) {
            float4 v = p[(size_t)n * 64];
            s.x += v.x; s.y += v.y; s.z += v.z; s.w += v.w;
        }
        ps[rq][c4] = s;
    }
    __syncthreads();
    if (t < 64) {
        float4 a = ps[0][t], b1 = ps[1][t], c = ps[2][t], d = ps[3][t];
        m[Dc + t * 4 + 0] = (a.x + b1.x + c.x + d.x) * (1.f / N2c);
        m[Dc + t * 4 + 1] = (a.y + b1.y + c.y + d.y) * (1.f / N2c);
        m[Dc + t * 4 + 2] = (a.z + b1.z + c.z + d.z) * (1.f / N2c);
        m[Dc + t * 4 + 3] = (a.w + b1.w + c.w + d.w) * (1.f / N2c);
    }
    __syncthreads();

    float acc = r_b1[t];
    const float* wr = r_w1 + (size_t)t * (2 * Dc);
    #pragma unroll 4
    for (int k = 0; k < 2 * Dc; k++) acc += m[k] * wr[k];

    float v = acc;
    for (int o = 16; o; o >>= 1) v += __shfl_down_sync(0xffffffffu, v, o);
    if ((t & 31) == 0) red[t >> 5] = v;
    __syncthreads();
    if (t < 8) {
        v = red[t];
        for (int o = 4; o; o >>= 1) v += __shfl_down_sync(0xffu, v, o);
        if (t == 0) red[0] = v;
    }
    __syncthreads();
    float mu = red[0] * (1.f / Dc);
    __syncthreads();
    float dd = acc - mu;
    v = dd * dd;
    for (int o = 16; o; o >>= 1) v += __shfl_down_sync(0xffffffffu, v, o);
    if ((t & 31) == 0) red[t >> 5] = v;
    __syncthreads();
    if (t < 8) {
        v = red[t];
        for (int o = 4; o; o >>= 1) v += __shfl_down_sync(0xffu, v, o);
        if (t == 0) red[0] = v;
    }
    __syncthreads();
    float var = red[0] * (1.f / Dc);
    float y = dd * rsqrtf(var + 1e-5f) * ln_g[t] + ln_b[t];
    float g = 0.5f * y * (1.f + erff(y * 0.70710678118654752f));
    hb[t] = g;
    __syncthreads();

    if (t < 4) {
        float a = r_b2[t];
        const float* w2 = r_w2 + (size_t)t * Dc;
        for (int k = 0; k < Dc; k++) a += hb[k] * w2[k];
        lg[t] = a;
    }
    __syncthreads();
    if (t == 0) {
        float mx = fmaxf(fmaxf(lg[0], lg[1]), fmaxf(lg[2], lg[3]));
        float e0 = expf(lg[0] - mx), e1 = expf(lg[1] - mx);
        float e2 = expf(lg[2] - mx), e3 = expf(lg[3] - mx);
        float inv = 1.f / (e0 + e1 + e2 + e3);
        d_wts[b * 4 + 0] = e0 * inv; d_wts[b * 4 + 1] = e1 * inv;
        d_wts[b * 4 + 2] = e2 * inv; d_wts[b * 4 + 3] = e3 * inv;
    }
}

// ---------------- tf32 MMA GEMM: BM=128, BN=128, BK=32, cp.async x3 stages --
// K is always 256 (8 tiles). Prefetch distance 2.
// non-BT: A [row][36], B [row][36] (frag banks gid*4+tig: conflict-free).
// BT:     A [row][36], B [k][136].
// Stage stride 9216 floats (A 4608 + B 4608/4352); smem 3*9216*4 = 110592 B.
#define GSTG 9216

template<bool BT>
__device__ __forceinline__ void issue_tile32(
    float* sm, const float* __restrict__ A, const float* __restrict__ W,
    int ldB, int m0, int n0, int t)
{
    const int tid = threadIdx.x;
    const int k0 = t * 32;
    float* As = sm + (t % 3) * GSTG;
    float* Bs = As + 4608;
    #pragma unroll
    for (int h = 0; h < 4; h++) {
        int c = tid + h * 256;              // 1024 chunks of 16B
        int row = c >> 3, ko = (c & 7) * 4;
        cp16(As + row * 36 + ko, A + (size_t)(m0 + row) * 256 + k0 + ko);
    }
    if (BT) {
        #pragma unroll
        for (int h = 0; h < 4; h++) {
            int c = tid + h * 256;
            int k = c >> 5, nq = (c & 31) * 4;
            cp16(Bs + k * 136 + nq, W + (size_t)(k0 + k) * ldB + n0 + nq);
        }
    } else {
        #pragma unroll
        for (int h = 0; h < 4; h++) {
            int c = tid + h * 256;
            int row = c >> 3, ko = (c & 7) * 4;
            cp16(Bs + row * 36 + ko, W + (size_t)(n0 + row) * 256 + k0 + ko);
        }
    }
    cp_commit();
}

template<bool BT>
__device__ __forceinline__ void mma_mainloop32(
    float* sm, const float* __restrict__ A, const float* __restrict__ W,
    int ldB, int m0, int n0, float (&acc)[2][8][4])
{
    const int tid = threadIdx.x, lane = tid & 31, warp = tid >> 5;
    const int wm = warp >> 1, wn = warp & 1;
    const int gid = lane >> 2, tig = lane & 3;

    #pragma unroll
    for (int i = 0; i < 2; i++)
        #pragma unroll
        for (int j = 0; j < 8; j++)
            #pragma unroll
            for (int c = 0; c < 4; c++) acc[i][j][c] = 0.f;

    issue_tile32<BT>(sm, A, W, ldB, m0, n0, 0);
    issue_tile32<BT>(sm, A, W, ldB, m0, n0, 1);

    for (int t = 0; t < 8; t++) {
        if (t < 7) asm volatile("cp.async.wait_group 1;" ::: "memory");
        else       asm volatile("cp.async.wait_group 0;" ::: "memory");
        __syncthreads();
        if (t + 2 < 8) issue_tile32<BT>(sm, A, W, ldB, m0, n0, t + 2);

        const float* As = sm + (t % 3) * GSTG;
        const float* Bs = As + 4608;
        #pragma unroll
        for (int ks8 = 0; ks8 < 4; ks8++) {
            unsigned af[2][4];
            #pragma unroll
            for (int mt = 0; mt < 2; mt++) {
                int mb = wm * 32 + mt * 16 + gid;
                af[mt][0] = __float_as_uint(As[mb * 36 + ks8 * 8 + tig]);
                af[mt][1] = __float_as_uint(As[(mb + 8) * 36 + ks8 * 8 + tig]);
                af[mt][2] = __float_as_uint(As[mb * 36 + ks8 * 8 + tig + 4]);
                af[mt][3] = __float_as_uint(As[(mb + 8) * 36 + ks8 * 8 + tig + 4]);
            }
            #pragma unroll
            for (int nt = 0; nt < 8; nt++) {
                int nb = wn * 64 + nt * 8 + gid;
                unsigned bf[2];
                if (BT) {
                    bf[0] = __float_as_uint(Bs[(ks8 * 8 + tig) * 136 + nb]);
                    bf[1] = __float_as_uint(Bs[(ks8 * 8 + tig + 4) * 136 + nb]);
                } else {
                    bf[0] = __float_as_uint(Bs[nb * 36 + ks8 * 8 + tig]);
                    bf[1] = __float_as_uint(Bs[nb * 36 + ks8 * 8 + tig + 4]);
                }
                mma_tf32(acc[0][nt], af[0], bf);
                mma_tf32(acc[1][nt], af[1], bf);
            }
        }
    }
}

// ---------------- standard epilogue (fragment layout) ------------------------
template<bool RB>
__device__ __forceinline__ void epi_std(
    float (&acc)[2][8][4], const float* __restrict__ bias, float* __restrict__ C,
    int ldC, int m0, int n0, int rpb, int ostride, int ooff, int act)
{
    const int tid = threadIdx.x, lane = tid & 31, warp = tid >> 5;
    const int wm = warp >> 1, wn = warp & 1;
    const int gid = lane >> 2, tig = lane & 3;

    #pragma unroll
    for (int mt = 0; mt < 2; mt++) {
        #pragma unroll
        for (int rh = 0; rh < 2; rh++) {
            int r = m0 + wm * 32 + mt * 16 + gid + rh * 8;
            float rbv = RB ? bias[r] : 0.f;
            int grow = (r / rpb) * ostride + ooff + (r % rpb);
            float* dst = C + (size_t)grow * ldC;
            #pragma unroll
            for (int nt = 0; nt < 8; nt++) {
                int col = n0 + wn * 64 + nt * 8 + tig * 2;
                float v0 = acc[mt][nt][rh * 2 + 0];
                float v1 = acc[mt][nt][rh * 2 + 1];
                if (RB) { v0 += rbv; v1 += rbv; }
                else {
                    float2 bc = *(const float2*)(bias + col);
                    v0 += bc.x; v1 += bc.y;
                }
                if (act) {
                    v0 = v0 > 0.f ? v0 : expm1f(v0);
                    v1 = v1 > 0.f ? v1 : expm1f(v1);
                }
                *(float2*)(dst + col) = make_float2(v0, v1);
            }
        }
    }
}

// ---------------- ONE merged GEMM launch: qkv/lf/a1 (x1) + qkv/lf (x2) + a2 --
// grid.x = 2048 blocks:
//   [0,1280):    x1 segs; nb = bx/128 (0..9), my = bx%128
//   [1280,1792): x2 segs; nb = idx/64 (0..7), my = idx%64
//   [1792,2048): a2;      b = idx>>3, nb = (idx&7)&1, my = (idx&7)>>1
__global__ __launch_bounds__(256, 2) void gemm_all(
    const float* __restrict__ x1, const float* __restrict__ x2,
    const float* __restrict__ attn_in_w, const float* __restrict__ attn_in_b,
    const float* __restrict__ lf_w, const float* __restrict__ lf_b,
    const float* __restrict__ af2_w, const float* __restrict__ af2_b,
    const float* __restrict__ af3_w, const float* __restrict__ af3_b)
{
    extern __shared__ float sm[];
    const int BIGR = 1 << 30;
    int bx = blockIdx.x;
    float acc[2][8][4];

    if (bx < 1280) {
        int nb = bx / 128, my = bx - nb * 128;
        const float* W; const float* bias; float* C;
        int ldC, rpb, ostride, ooff, act, n0;
        if (nb < 6)      { W = attn_in_w; bias = attn_in_b; C = d_qkv;
                           ldC = 3 * Dc; rpb = N1c; ostride = Sc; ooff = 0; act = 0; n0 = nb * 128; }
        else if (nb < 8) { W = lf_w; bias = lf_b; C = d_lf;
                           ldC = Dc; rpb = N1c; ostride = Sc; ooff = 0; act = 1; n0 = (nb - 6) * 128; }
        else             { W = af2_w; bias = af2_b; C = d_xout;
                           ldC = Dc; rpb = BIGR; ostride = 0; ooff = 0; act = 1; n0 = (nb - 8) * 128; }
        mma_mainloop32<false>(sm, x1, W, 0, my * 128, n0, acc);
        epi_std<false>(acc, bias, C, ldC, my * 128, n0, rpb, ostride, ooff, act);
    } else if (bx < 1792) {
        int idx = bx - 1280;
        int nb = idx / 64, my = idx - nb * 64;
        const float* W; const float* bias; float* C;
        int ldC, rpb, ooff, act, n0;
        if (nb < 6) { W = attn_in_w; bias = attn_in_b; C = d_qkv;
                      ldC = 3 * Dc; rpb = N2c; ooff = N1c; act = 0; n0 = nb * 128; }
        else        { W = lf_w; bias = lf_b; C = d_lf;
                      ldC = Dc; rpb = N2c; ooff = N1c; act = 1; n0 = (nb - 6) * 128; }
        mma_mainloop32<false>(sm, x2, W, 0, my * 128, n0, acc);
        epi_std<false>(acc, bias, C, ldC, my * 128, n0, rpb, Sc, ooff, act);
    } else {
        int idx = bx - 1792;
        int b = idx >> 3, r = idx & 7;
        int nb = r & 1, my = r >> 1;
        const float* W = x2 + (size_t)b * N2c * Dc;
        float* C = d_x2o + (size_t)b * N1c * Dc;
        mma_mainloop32<true>(sm, af3_w, W, Dc, my * 128, nb * 128, acc);
        epi_std<true>(acc, af3_b, C, Dc, my * 128, nb * 128, BIGR, 0, 0, 1);
    }
}

// ---------------- final GEMM: attn_out + weighted combine fused -------------
__global__ __launch_bounds__(256, 2) void gemm_final(
    const float* __restrict__ W, const float* __restrict__ bias,
    const float* __restrict__ x1, const float* __restrict__ x2,
    float* __restrict__ out)
{
    extern __shared__ float sm[];
    int m0 = blockIdx.y * 128, n0 = blockIdx.x * 128;
    float acc[2][8][4];
    mma_mainloop32<false>(sm, d_o, W, 0, m0, n0, acc);

    const int tid = threadIdx.x, lane = tid & 31, warp = tid >> 5;
    const int wm = warp >> 1, wn = warp & 1;
    const int gid = lane >> 2, tig = lane & 3;

    #pragma unroll
    for (int mt = 0; mt < 2; mt++) {
        #pragma unroll
        for (int rh = 0; rh < 2; rh++) {
            int r = m0 + wm * 32 + mt * 16 + gid + rh * 8;
            int b = r / Sc;
            int s = r - b * Sc;
            const float* w = d_wts + b * 4;
            float w0 = w[0], w1 = w[1], w2 = w[2], w3 = w[3];
            const float* lfr = d_lf + (size_t)r * Dc;
            const float* xo; const float* xo2; const float* xv; float* dst;
            if (s < N1c) {
                size_t rr = (size_t)b * N1c + s;
                xo = d_xout + rr * Dc;
                xo2 = d_x2o + rr * Dc;
                xv = x1 + rr * Dc;
                dst = out + rr * Dc;
            } else {
                int s2 = s - N1c;
                xo = d_xout + ((size_t)b * N1c + s2) * Dc;
                xo2 = d_x2o + ((size_t)b * N1c + s2) * Dc;
                xv = x2 + ((size_t)b * N2c + s2) * Dc;
                dst = out + (size_t)Bb * N1c * Dc + ((size_t)b * N2c + s2) * Dc;
            }
            #pragma unroll
            for (int nt = 0; nt < 8; nt++) {
                int col = n0 + wn * 64 + nt * 8 + tig * 2;
                float2 bc = *(const float2*)(bias + col);
                float op0 = acc[mt][nt][rh * 2 + 0] + bc.x;
                float op1 = acc[mt][nt][rh * 2 + 1] + bc.y;
                float2 l = *(const float2*)(lfr + col);
                float2 g = *(const float2*)(xo + col);
                float2 g2 = *(const float2*)(xo2 + col);
                float2 y = *(const float2*)(xv + col);
                float o0 = w0 * l.x + w1 * (g.x + g2.x) + w2 * op0 + w3 * y.x;
                float o1 = w0 * l.y + w1 * (g.y + g2.y) + w2 * op1 + w3 * y.y;
                *(float2*)(dst + col) = make_float2(o0, o1);
            }
        }
    }
}

// ---------------- attention via tf32 MMA (interleaved smem) ------------------
// Ks: [c8blk(4)][r(128)][8] word=((c&3)^(r&3))*2+((c>>2)&1)  (LDS.64 b-frags)
// Vs: [k8blk(16)][c(32)][8] word=(k&3)*2+((k>>2)&1)          (LDS.64 b-frags)
// Ps: per-warp frag quads [ks(16)][gid(8)][tq^gidswz(4)][4]  (LDS.128 a-frags)
// Row sums via ones-column MMA in the PV loop (ls frag).
#define ATTN_SMEM_FLOATS (4096 + 4096 + 16384)

__global__ __launch_bounds__(256, 2) void attn_mma()
{
    extern __shared__ float sm[];
    float* Ks = sm;            // 4096
    float* Vs = sm + 4096;     // 4096
    float* Ps = sm + 8192;     // 16384 (8 warps x 2048)

    const int qt = blockIdx.x;
    const int bh = blockIdx.y;
    const int b = bh >> 3, h = bh & 7;
    const int tid = threadIdx.x, lane = tid & 31, warp = tid >> 5;
    const int gid = lane >> 2, tig = lane & 3;
    const int gsw = gid & 3;
    const int m0 = qt * 128;
    const float* base = d_qkv + (size_t)b * Sc * (3 * Dc);
    const float scale = 0.17677669529663688f;   // 1/sqrt(32)
    float* Pw = Ps + warp * 2048;

    // Q fragments (scaled, raw fp32 bits), rows warp*16 + gid (+8)
    unsigned qf[4][4];
    {
        const float* q0 = base + (size_t)(m0 + warp * 16 + gid) * (3 * Dc) + h * HDc;
        const float* q1 = q0 + (size_t)8 * (3 * Dc);
        #pragma unroll
        for (int ks = 0; ks < 4; ks++) {
            qf[ks][0] = __float_as_uint(q0[ks * 8 + tig] * scale);
            qf[ks][1] = __float_as_uint(q1[ks * 8 + tig] * scale);
            qf[ks][2] = __float_as_uint(q0[ks * 8 + tig + 4] * scale);
            qf[ks][3] = __float_as_uint(q1[ks * 8 + tig + 4] * scale);
        }
    }

    float oc[4][4];
    #pragma unroll
    for (int i = 0; i < 4; i++)
        #pragma unroll
        for (int j = 0; j < 4; j++) oc[i][j] = 0.f;
    float ls[4] = { 0.f, 0.f, 0.f, 0.f };      // row-sum frag (ones MMA)
    const unsigned bones[2] = { 0x3f800000u, 0x3f800000u };

    for (int c = 0; c < 6; c++) {
        const int kv0 = c * 128;
        __syncthreads();   // all warps done reading Ks/Vs of prev chunk

        // stage K (c-fast map; 4-way-bounded STS.32)
        #pragma unroll
        for (int it = 0; it < 4; it++) {
            int i = tid + it * 256;
            int cc = (i & 7) * 4, r = i >> 3;
            const float* src = base + (size_t)(kv0 + r) * (3 * Dc) + Dc + h * HDc + cc;
            float4 v = *(const float4*)src;
            float vv[4] = { v.x, v.y, v.z, v.w };
            #pragma unroll
            for (int j = 0; j < 4; j++) {
                int cq = cc + j;
                Ks[(((cq >> 3) * 128 + r) * 8) + (((cq & 3) ^ (r & 3)) * 2) + ((cq >> 2) & 1)] = vv[j];
            }
        }
        // stage V (r-fast map)
        #pragma unroll
        for (int it = 0; it < 4; it++) {
            int i = tid + it * 256;
            int r = i & 127, cg = (i >> 7) * 4;
            const float* src = base + (size_t)(kv0 + r) * (3 * Dc) + 2 * Dc + h * HDc + cg;
            float4 v = *(const float4*)src;
            int w = (r & 3) * 2 + ((r >> 2) & 1);
            int qb = (r >> 3) * 32 + cg;
            Vs[(qb + 0) * 8 + w] = v.x; Vs[(qb + 1) * 8 + w] = v.y;
            Vs[(qb + 2) * 8 + w] = v.z; Vs[(qb + 3) * 8 + w] = v.w;
        }
        __syncthreads();

        // S = Q @ K^T, exp, write P (frag-quad layout, warp-private)
        #pragma unroll
        for (int half = 0; half < 2; half++) {
            float sc_[8][4];
            #pragma unroll
            for (int nt = 0; nt < 8; nt++)
                #pragma unroll
                for (int j = 0; j < 4; j++) sc_[nt][j] = 0.f;
            #pragma unroll
            for (int ks = 0; ks < 4; ks++) {
                #pragma unroll
                for (int nt = 0; nt < 8; nt++) {
                    int nb = half * 64 + nt * 8 + gid;
                    float2 k2 = *(const float2*)&Ks[((ks * 128 + nb) * 8) + ((tig ^ gsw) * 2)];
                    unsigned bf[2] = { __float_as_uint(k2.x), __float_as_uint(k2.y) };
                    mma_tf32(sc_[nt], qf[ks], bf);
                }
            }
            #pragma unroll
            for (int nt = 0; nt < 8; nt++) {
                float p0 = __expf(sc_[nt][0]);
                float p1 = __expf(sc_[nt][1]);
                float p2 = __expf(sc_[nt][2]);
                float p3 = __expf(sc_[nt][3]);
                int ksq = half * 8 + nt;
                int tc0 = tig * 2, tc1 = tc0 + 1;
                float* pb = Pw + ksq * 128 + gid * 16;
                *(float2*)&pb[((tc0 & 3) ^ gsw) * 4 + (tc0 >> 2) * 2] = make_float2(p0, p2);
                *(float2*)&pb[((tc1 & 3) ^ gsw) * 4 + (tc1 >> 2) * 2] = make_float2(p1, p3);
            }
        }
        __syncwarp();

        // O += P @ V ; rowsum += P @ ones
        #pragma unroll
        for (int ks = 0; ks < 16; ks++) {
            float4 aq = *(const float4*)&Pw[ks * 128 + gid * 16 + ((tig ^ gsw) * 4)];
            unsigned a[4] = { __float_as_uint(aq.x), __float_as_uint(aq.y),
                              __float_as_uint(aq.z), __float_as_uint(aq.w) };
            #pragma unroll
            for (int nf = 0; nf < 4; nf++) {
                float2 v2 = *(const float2*)&Vs[((ks * 32 + nf * 8 + gid) * 8) + tig * 2];
                unsigned bv[2] = { __float_as_uint(v2.x), __float_as_uint(v2.y) };
                mma_tf32(oc[nf], a, bv);
            }
            mma_tf32(ls, a, bones);
        }
        __syncwarp();   // P reads done before next chunk rewrites
    }

    float inv0 = 1.f / ls[0], inv1 = 1.f / ls[2];

    float* o0 = d_o + (size_t)(b * Sc + m0 + warp * 16 + gid) * Dc + h * HDc;
    float* o1 = o0 + 8 * Dc;
    #pragma unroll
    for (int nf = 0; nf < 4; nf++) {
        int col = nf * 8 + tig * 2;
        *(float2*)&o0[col] = make_float2(oc[nf][0] * inv0, oc[nf][1] * inv0);
        *(float2*)&o1[col] = make_float2(oc[nf][2] * inv1, oc[nf][3] * inv1);
    }
}

// ---------------- launch ----------------------------------------------------
extern "C" void kernel_launch(void* const* d_in, const int* in_sizes, int n_in,
                              void* d_out, int out_size)
{
    const float* x1        = (const float*)d_in[0];
    const float* x2        = (const float*)d_in[1];
    const float* r_w1      = (const float*)d_in[2];
    const float* r_b1      = (const float*)d_in[3];
    const float* ln_g      = (const float*)d_in[4];
    const float* ln_b      = (const float*)d_in[5];
    const float* r_w2      = (const float*)d_in[6];
    const float* r_b2      = (const float*)d_in[7];
    const float* lf_w      = (const float*)d_in[8];
    const float* lf_b      = (const float*)d_in[9];
    const float* af2_w     = (const float*)d_in[10];
    const float* af2_b     = (const float*)d_in[11];
    const float* af3_w     = (const float*)d_in[12];
    const float* af3_b     = (const float*)d_in[13];
    const float* attn_in_w = (const float*)d_in[14];
    const float* attn_in_b = (const float*)d_in[15];
    const float* attn_out_w= (const float*)d_in[16];
    const float* attn_out_b= (const float*)d_in[17];
    float* out = (float*)d_out;

    const int ATTN_SMEM = ATTN_SMEM_FLOATS * (int)sizeof(float);  // 98304
    const int GEMM_SMEM = 3 * GSTG * (int)sizeof(float);          // 110592
    cudaFuncSetAttribute(attn_mma, cudaFuncAttributeMaxDynamicSharedMemorySize, ATTN_SMEM);
    cudaFuncSetAttribute(gemm_all, cudaFuncAttributeMaxDynamicSharedMemorySize, GEMM_SMEM);
    cudaFuncSetAttribute(gemm_final, cudaFuncAttributeMaxDynamicSharedMemorySize, GEMM_SMEM);

    // 1. router weights
    router_kernel<<<Bb, 256>>>(x1, x2, r_w1, r_b1, ln_g, ln_b, r_w2, r_b2);

    // 2. ALL independent GEMMs in one launch (qkv/lf/a1/a2)
    gemm_all<<<2048, 256, GEMM_SMEM>>>(x1, x2, attn_in_w, attn_in_b,
                                       lf_w, lf_b, af2_w, af2_b, af3_w, af3_b);

    // 3. attention via tensor cores (reads d_qkv, writes d_o)
    attn_mma<<<dim3(6, 256), 256, ATTN_SMEM>>>();

    // 4. fused: (d_o @ attn_out_w.T + b) combined with lf/(a1+a2)/x -> out
    gemm_final<<<dim3(2, 192), 256, GEMM_SMEM>>>(attn_out_w, attn_out_b, x1, x2, out);
}

// round 14
// speedup vs baseline: 4.3046x; 1.0575x over previous
#include <cuda_runtime.h>
#include <math.h>

// Shapes (fixed by the problem)
#define Bb   32
#define N1c  512
#define N2c  256
#define Dc   256
#define Hc   8
#define HDc  32
#define Sc   768   // N1 + N2

// ---------------- tf32 MMA (raw fp32 operands; HW truncates to tf32) --------
__device__ __forceinline__ void mma_tf32(float (&c)[4], const unsigned (&a)[4],
                                         const unsigned (&b)[2]) {
    asm("mma.sync.aligned.m16n8k8.row.col.f32.tf32.tf32.f32 "
        "{%0,%1,%2,%3},{%4,%5,%6,%7},{%8,%9},{%0,%1,%2,%3};"
        : "+f"(c[0]), "+f"(c[1]), "+f"(c[2]), "+f"(c[3])
        : "r"(a[0]), "r"(a[1]), "r"(a[2]), "r"(a[3]), "r"(b[0]), "r"(b[1]));
}

__device__ __forceinline__ void cp16(float* dst, const float* src) {
    unsigned ds = (unsigned)__cvta_generic_to_shared(dst);
    asm volatile("cp.async.cg.shared.global [%0], [%1], 16;" :: "r"(ds), "l"(src));
}
__device__ __forceinline__ void cp_commit() {
    asm volatile("cp.async.commit_group;" ::: "memory");
}

// ---------------- scratch (device globals; no allocations allowed) ----------
__device__ __align__(16) float d_qkv [Bb * Sc * 3 * Dc];
__device__ __align__(16) float d_lf  [Bb * Sc * Dc];
__device__ __align__(16) float d_xout[Bb * N1c * Dc];   // a1
__device__ __align__(16) float d_x2o [Bb * N1c * Dc];   // a2
__device__ __align__(16) float d_o   [Bb * Sc * Dc];
__device__ float d_wts [Bb * 4];

// ---------------- router body (dynamic smem) ---------------------------------
__device__ void router_body(float* sm, int b,
    const float* __restrict__ x1, const float* __restrict__ x2,
    const float* __restrict__ r_w1, const float* __restrict__ r_b1,
    const float* __restrict__ ln_g, const float* __restrict__ ln_b,
    const float* __restrict__ r_w2, const float* __restrict__ r_b2)
{
    float* m   = sm;                 // 512
    float4* ps = (float4*)(sm + 512);// 4*64 float4 = 1024 floats
    float* hb  = sm + 1536;          // 256
    float* red = sm + 1792;          // 8
    float* lg  = sm + 1800;          // 4
    int t = threadIdx.x;
    int c4 = t & 63, rq = t >> 6;

    {
        const float4* p = (const float4*)(x1 + (size_t)b * N1c * Dc) + (size_t)rq * 128 * 64 + c4;
        float4 s = make_float4(0.f, 0.f, 0.f, 0.f);
        for (int n = 0; n < 128; n++) {
            float4 v = p[(size_t)n * 64];
            s.x += v.x; s.y += v.y; s.z += v.z; s.w += v.w;
        }
        ps[rq * 64 + c4] = s;
    }
    __syncthreads();
    if (t < 64) {
        float4 a = ps[t], b1 = ps[64 + t], c = ps[128 + t], d = ps[192 + t];
        m[t * 4 + 0] = (a.x + b1.x + c.x + d.x) * (1.f / N1c);
        m[t * 4 + 1] = (a.y + b1.y + c.y + d.y) * (1.f / N1c);
        m[t * 4 + 2] = (a.z + b1.z + c.z + d.z) * (1.f / N1c);
        m[t * 4 + 3] = (a.w + b1.w + c.w + d.w) * (1.f / N1c);
    }
    __syncthreads();
    {
        const float4* p = (const float4*)(x2 + (size_t)b * N2c * Dc) + (size_t)rq * 64 * 64 + c4;
        float4 s = make_float4(0.f, 0.f, 0.f, 0.f);
        for (int n = 0; n < 64; n++) {
            float4 v = p[(size_t)n * 64];
            s.x += v.x; s.y += v.y; s.z += v.z; s.w += v.w;
        }
        ps[rq * 64 + c4] = s;
    }
    __syncthreads();
    if (t < 64) {
        float4 a = ps[t], b1 = ps[64 + t], c = ps[128 + t], d = ps[192 + t];
        m[Dc + t * 4 + 0] = (a.x + b1.x + c.x + d.x) * (1.f / N2c);
        m[Dc + t * 4 + 1] = (a.y + b1.y + c.y + d.y) * (1.f / N2c);
        m[Dc + t * 4 + 2] = (a.z + b1.z + c.z + d.z) * (1.f / N2c);
        m[Dc + t * 4 + 3] = (a.w + b1.w + c.w + d.w) * (1.f / N2c);
    }
    __syncthreads();

    float acc = r_b1[t];
    const float* wr = r_w1 + (size_t)t * (2 * Dc);
    #pragma unroll 4
    for (int k = 0; k < 2 * Dc; k++) acc += m[k] * wr[k];

    float v = acc;
    for (int o = 16; o; o >>= 1) v += __shfl_down_sync(0xffffffffu, v, o);
    if ((t & 31) == 0) red[t >> 5] = v;
    __syncthreads();
    if (t < 8) {
        v = red[t];
        for (int o = 4; o; o >>= 1) v += __shfl_down_sync(0xffu, v, o);
        if (t == 0) red[0] = v;
    }
    __syncthreads();
    float mu = red[0] * (1.f / Dc);
    __syncthreads();
    float dd = acc - mu;
    v = dd * dd;
    for (int o = 16; o; o >>= 1) v += __shfl_down_sync(0xffffffffu, v, o);
    if ((t & 31) == 0) red[t >> 5] = v;
    __syncthreads();
    if (t < 8) {
        v = red[t];
        for (int o = 4; o; o >>= 1) v += __shfl_down_sync(0xffu, v, o);
        if (t == 0) red[0] = v;
    }
    __syncthreads();
    float var = red[0] * (1.f / Dc);
    float y = dd * rsqrtf(var + 1e-5f) * ln_g[t] + ln_b[t];
    float g = 0.5f * y * (1.f + erff(y * 0.70710678118654752f));
    hb[t] = g;
    __syncthreads();

    if (t < 4) {
        float a = r_b2[t];
        const float* w2 = r_w2 + (size_t)t * Dc;
        for (int k = 0; k < Dc; k++) a += hb[k] * w2[k];
        lg[t] = a;
    }
    __syncthreads();
    if (t == 0) {
        float mx = fmaxf(fmaxf(lg[0], lg[1]), fmaxf(lg[2], lg[3]));
        float e0 = expf(lg[0] - mx), e1 = expf(lg[1] - mx);
        float e2 = expf(lg[2] - mx), e3 = expf(lg[3] - mx);
        float inv = 1.f / (e0 + e1 + e2 + e3);
        d_wts[b * 4 + 0] = e0 * inv; d_wts[b * 4 + 1] = e1 * inv;
        d_wts[b * 4 + 2] = e2 * inv; d_wts[b * 4 + 3] = e3 * inv;
    }
}

// ---------------- tf32 MMA GEMM: BM=128, BN=128, BK=32, cp.async x3 stages --
#define GSTG 9216

template<bool BT>
__device__ __forceinline__ void issue_tile32(
    float* sm, const float* __restrict__ A, const float* __restrict__ W,
    int ldB, int m0, int n0, int t)
{
    const int tid = threadIdx.x;
    const int k0 = t * 32;
    float* As = sm + (t % 3) * GSTG;
    float* Bs = As + 4608;
    #pragma unroll
    for (int h = 0; h < 4; h++) {
        int c = tid + h * 256;
        int row = c >> 3, ko = (c & 7) * 4;
        cp16(As + row * 36 + ko, A + (size_t)(m0 + row) * 256 + k0 + ko);
    }
    if (BT) {
        #pragma unroll
        for (int h = 0; h < 4; h++) {
            int c = tid + h * 256;
            int k = c >> 5, nq = (c & 31) * 4;
            cp16(Bs + k * 136 + nq, W + (size_t)(k0 + k) * ldB + n0 + nq);
        }
    } else {
        #pragma unroll
        for (int h = 0; h < 4; h++) {
            int c = tid + h * 256;
            int row = c >> 3, ko = (c & 7) * 4;
            cp16(Bs + row * 36 + ko, W + (size_t)(n0 + row) * 256 + k0 + ko);
        }
    }
    cp_commit();
}

template<bool BT>
__device__ __forceinline__ void mma_mainloop32(
    float* sm, const float* __restrict__ A, const float* __restrict__ W,
    int ldB, int m0, int n0, float (&acc)[2][8][4])
{
    const int tid = threadIdx.x, lane = tid & 31, warp = tid >> 5;
    const int wm = warp >> 1, wn = warp & 1;
    const int gid = lane >> 2, tig = lane & 3;

    #pragma unroll
    for (int i = 0; i < 2; i++)
        #pragma unroll
        for (int j = 0; j < 8; j++)
            #pragma unroll
            for (int c = 0; c < 4; c++) acc[i][j][c] = 0.f;

    issue_tile32<BT>(sm, A, W, ldB, m0, n0, 0);
    issue_tile32<BT>(sm, A, W, ldB, m0, n0, 1);

    for (int t = 0; t < 8; t++) {
        if (t < 7) asm volatile("cp.async.wait_group 1;" ::: "memory");
        else       asm volatile("cp.async.wait_group 0;" ::: "memory");
        __syncthreads();
        if (t + 2 < 8) issue_tile32<BT>(sm, A, W, ldB, m0, n0, t + 2);

        const float* As = sm + (t % 3) * GSTG;
        const float* Bs = As + 4608;
        #pragma unroll
        for (int ks8 = 0; ks8 < 4; ks8++) {
            unsigned af[2][4];
            #pragma unroll
            for (int mt = 0; mt < 2; mt++) {
                int mb = wm * 32 + mt * 16 + gid;
                af[mt][0] = __float_as_uint(As[mb * 36 + ks8 * 8 + tig]);
                af[mt][1] = __float_as_uint(As[(mb + 8) * 36 + ks8 * 8 + tig]);
                af[mt][2] = __float_as_uint(As[mb * 36 + ks8 * 8 + tig + 4]);
                af[mt][3] = __float_as_uint(As[(mb + 8) * 36 + ks8 * 8 + tig + 4]);
            }
            #pragma unroll
            for (int nt = 0; nt < 8; nt++) {
                int nb = wn * 64 + nt * 8 + gid;
                unsigned bf[2];
                if (BT) {
                    bf[0] = __float_as_uint(Bs[(ks8 * 8 + tig) * 136 + nb]);
                    bf[1] = __float_as_uint(Bs[(ks8 * 8 + tig + 4) * 136 + nb]);
                } else {
                    bf[0] = __float_as_uint(Bs[nb * 36 + ks8 * 8 + tig]);
                    bf[1] = __float_as_uint(Bs[nb * 36 + ks8 * 8 + tig + 4]);
                }
                mma_tf32(acc[0][nt], af[0], bf);
                mma_tf32(acc[1][nt], af[1], bf);
            }
        }
    }
}

// ---------------- standard epilogue (fragment layout) ------------------------
template<bool RB>
__device__ __forceinline__ void epi_std(
    float (&acc)[2][8][4], const float* __restrict__ bias, float* __restrict__ C,
    int ldC, int m0, int n0, int rpb, int ostride, int ooff, int act)
{
    const int tid = threadIdx.x, lane = tid & 31, warp = tid >> 5;
    const int wm = warp >> 1, wn = warp & 1;
    const int gid = lane >> 2, tig = lane & 3;

    #pragma unroll
    for (int mt = 0; mt < 2; mt++) {
        #pragma unroll
        for (int rh = 0; rh < 2; rh++) {
            int r = m0 + wm * 32 + mt * 16 + gid + rh * 8;
            float rbv = RB ? bias[r] : 0.f;
            int grow = (r / rpb) * ostride + ooff + (r % rpb);
            float* dst = C + (size_t)grow * ldC;
            #pragma unroll
            for (int nt = 0; nt < 8; nt++) {
                int col = n0 + wn * 64 + nt * 8 + tig * 2;
                float v0 = acc[mt][nt][rh * 2 + 0];
                float v1 = acc[mt][nt][rh * 2 + 1];
                if (RB) { v0 += rbv; v1 += rbv; }
                else {
                    float2 bc = *(const float2*)(bias + col);
                    v0 += bc.x; v1 += bc.y;
                }
                if (act) {
                    v0 = v0 > 0.f ? v0 : expm1f(v0);
                    v1 = v1 > 0.f ? v1 : expm1f(v1);
                }
                *(float2*)(dst + col) = make_float2(v0, v1);
            }
        }
    }
}

// ---------------- kernel 1: qkv GEMMs + router -------------------------------
// grid: [0,768) x1-qkv (nb=bx>>7, my=bx&127); [768,1152) x2-qkv; [1152,1184) router
__global__ __launch_bounds__(256, 2) void k_qkv_router(
    const float* __restrict__ x1, const float* __restrict__ x2,
    const float* __restrict__ attn_in_w, const float* __restrict__ attn_in_b,
    const float* __restrict__ r_w1, const float* __restrict__ r_b1,
    const float* __restrict__ ln_g, const float* __restrict__ ln_b,
    const float* __restrict__ r_w2, const float* __restrict__ r_b2)
{
    extern __shared__ float sm[];
    int bx = blockIdx.x;
    if (bx < 768) {
        int nb = bx >> 7, my = bx & 127;
        float acc[2][8][4];
        mma_mainloop32<false>(sm, x1, attn_in_w, 0, my * 128, nb * 128, acc);
        epi_std<false>(acc, attn_in_b, d_qkv, 3 * Dc, my * 128, nb * 128,
                       N1c, Sc, 0, 0);
    } else if (bx < 1152) {
        int idx = bx - 768;
        int nb = idx >> 6, my = idx & 63;
        float acc[2][8][4];
        mma_mainloop32<false>(sm, x2, attn_in_w, 0, my * 128, nb * 128, acc);
        epi_std<false>(acc, attn_in_b, d_qkv, 3 * Dc, my * 128, nb * 128,
                       N2c, Sc, N1c, 0);
    } else {
        router_body(sm, bx - 1152, x1, x2, r_w1, r_b1, ln_g, ln_b, r_w2, r_b2);
    }
}

// ---------------- attention body (tf32 MMA, interleaved smem) ----------------
__device__ void attn_body(float* sm, int qt, int bh)
{
    float* Ks = sm;            // 4096
    float* Vs = sm + 4096;     // 4096
    float* Ps = sm + 8192;     // 16384 (8 warps x 2048)

    const int b = bh >> 3, h = bh & 7;
    const int tid = threadIdx.x, lane = tid & 31, warp = tid >> 5;
    const int gid = lane >> 2, tig = lane & 3;
    const int gsw = gid & 3;
    const int m0 = qt * 128;
    const float* base = d_qkv + (size_t)b * Sc * (3 * Dc);
    const float scale = 0.17677669529663688f;   // 1/sqrt(32)
    float* Pw = Ps + warp * 2048;

    unsigned qf[4][4];
    {
        const float* q0 = base + (size_t)(m0 + warp * 16 + gid) * (3 * Dc) + h * HDc;
        const float* q1 = q0 + (size_t)8 * (3 * Dc);
        #pragma unroll
        for (int ks = 0; ks < 4; ks++) {
            qf[ks][0] = __float_as_uint(q0[ks * 8 + tig] * scale);
            qf[ks][1] = __float_as_uint(q1[ks * 8 + tig] * scale);
            qf[ks][2] = __float_as_uint(q0[ks * 8 + tig + 4] * scale);
            qf[ks][3] = __float_as_uint(q1[ks * 8 + tig + 4] * scale);
        }
    }

    float oc[4][4];
    #pragma unroll
    for (int i = 0; i < 4; i++)
        #pragma unroll
        for (int j = 0; j < 4; j++) oc[i][j] = 0.f;
    float ls[4] = { 0.f, 0.f, 0.f, 0.f };
    const unsigned bones[2] = { 0x3f800000u, 0x3f800000u };

    for (int c = 0; c < 6; c++) {
        const int kv0 = c * 128;
        __syncthreads();

        #pragma unroll
        for (int it = 0; it < 4; it++) {
            int i = tid + it * 256;
            int cc = (i & 7) * 4, r = i >> 3;
            const float* src = base + (size_t)(kv0 + r) * (3 * Dc) + Dc + h * HDc + cc;
            float4 v = *(const float4*)src;
            float vv[4] = { v.x, v.y, v.z, v.w };
            #pragma unroll
            for (int j = 0; j < 4; j++) {
                int cq = cc + j;
                Ks[(((cq >> 3) * 128 + r) * 8) + (((cq & 3) ^ (r & 3)) * 2) + ((cq >> 2) & 1)] = vv[j];
            }
        }
        #pragma unroll
        for (int it = 0; it < 4; it++) {
            int i = tid + it * 256;
            int r = i & 127, cg = (i >> 7) * 4;
            const float* src = base + (size_t)(kv0 + r) * (3 * Dc) + 2 * Dc + h * HDc + cg;
            float4 v = *(const float4*)src;
            int w = (r & 3) * 2 + ((r >> 2) & 1);
            int qb = (r >> 3) * 32 + cg;
            Vs[(qb + 0) * 8 + w] = v.x; Vs[(qb + 1) * 8 + w] = v.y;
            Vs[(qb + 2) * 8 + w] = v.z; Vs[(qb + 3) * 8 + w] = v.w;
        }
        __syncthreads();

        #pragma unroll
        for (int half = 0; half < 2; half++) {
            float sc_[8][4];
            #pragma unroll
            for (int nt = 0; nt < 8; nt++)
                #pragma unroll
                for (int j = 0; j < 4; j++) sc_[nt][j] = 0.f;
            #pragma unroll
            for (int ks = 0; ks < 4; ks++) {
                #pragma unroll
                for (int nt = 0; nt < 8; nt++) {
                    int nb = half * 64 + nt * 8 + gid;
                    float2 k2 = *(const float2*)&Ks[((ks * 128 + nb) * 8) + ((tig ^ gsw) * 2)];
                    unsigned bf[2] = { __float_as_uint(k2.x), __float_as_uint(k2.y) };
                    mma_tf32(sc_[nt], qf[ks], bf);
                }
            }
            #pragma unroll
            for (int nt = 0; nt < 8; nt++) {
                float p0 = __expf(sc_[nt][0]);
                float p1 = __expf(sc_[nt][1]);
                float p2 = __expf(sc_[nt][2]);
                float p3 = __expf(sc_[nt][3]);
                int ksq = half * 8 + nt;
                int tc0 = tig * 2, tc1 = tc0 + 1;
                float* pb = Pw + ksq * 128 + gid * 16;
                *(float2*)&pb[((tc0 & 3) ^ gsw) * 4 + (tc0 >> 2) * 2] = make_float2(p0, p2);
                *(float2*)&pb[((tc1 & 3) ^ gsw) * 4 + (tc1 >> 2) * 2] = make_float2(p1, p3);
            }
        }
        __syncwarp();

        #pragma unroll
        for (int ks = 0; ks < 16; ks++) {
            float4 aq = *(const float4*)&Pw[ks * 128 + gid * 16 + ((tig ^ gsw) * 4)];
            unsigned a[4] = { __float_as_uint(aq.x), __float_as_uint(aq.y),
                              __float_as_uint(aq.z), __float_as_uint(aq.w) };
            #pragma unroll
            for (int nf = 0; nf < 4; nf++) {
                float2 v2 = *(const float2*)&Vs[((ks * 32 + nf * 8 + gid) * 8) + tig * 2];
                unsigned bv[2] = { __float_as_uint(v2.x), __float_as_uint(v2.y) };
                mma_tf32(oc[nf], a, bv);
            }
            mma_tf32(ls, a, bones);
        }
        __syncwarp();
    }

    float inv0 = 1.f / ls[0], inv1 = 1.f / ls[2];
    float* o0 = d_o + (size_t)(b * Sc + m0 + warp * 16 + gid) * Dc + h * HDc;
    float* o1 = o0 + 8 * Dc;
    #pragma unroll
    for (int nf = 0; nf < 4; nf++) {
        int col = nf * 8 + tig * 2;
        *(float2*)&o0[col] = make_float2(oc[nf][0] * inv0, oc[nf][1] * inv0);
        *(float2*)&o1[col] = make_float2(oc[nf][2] * inv1, oc[nf][3] * inv1);
    }
}

// ---------------- kernel 2 (mega): attention + independent GEMMs -------------
// grid: [0,1536) attn (bh=bx/6, qt=bx%6)
//       [1536,1792) x1-lf   [1792,2048) a1   [2048,2176) x2-lf   [2176,2432) a2
__global__ __launch_bounds__(256, 2) void k_mega(
    const float* __restrict__ x1, const float* __restrict__ x2,
    const float* __restrict__ lf_w, const float* __restrict__ lf_b,
    const float* __restrict__ af2_w, const float* __restrict__ af2_b,
    const float* __restrict__ af3_w, const float* __restrict__ af3_b)
{
    extern __shared__ float sm[];
    const int BIGR = 1 << 30;
    int bx = blockIdx.x;

    if (bx < 1536) {
        attn_body(sm, bx % 6, bx / 6);
        return;
    }
    float acc[2][8][4];
    if (bx < 1792) {
        int idx = bx - 1536;
        int nb = idx >> 7, my = idx & 127;
        mma_mainloop32<false>(sm, x1, lf_w, 0, my * 128, nb * 128, acc);
        epi_std<false>(acc, lf_b, d_lf, Dc, my * 128, nb * 128, N1c, Sc, 0, 1);
    } else if (bx < 2048) {
        int idx = bx - 1792;
        int nb = idx >> 7, my = idx & 127;
        mma_mainloop32<false>(sm, x1, af2_w, 0, my * 128, nb * 128, acc);
        epi_std<false>(acc, af2_b, d_xout, Dc, my * 128, nb * 128, BIGR, 0, 0, 1);
    } else if (bx < 2176) {
        int idx = bx - 2048;
        int nb = idx >> 6, my = idx & 63;
        mma_mainloop32<false>(sm, x2, lf_w, 0, my * 128, nb * 128, acc);
        epi_std<false>(acc, lf_b, d_lf, Dc, my * 128, nb * 128, N2c, Sc, N1c, 1);
    } else {
        int idx = bx - 2176;
        int b = idx >> 3, r = idx & 7;
        int nb = r & 1, my = r >> 1;
        const float* W = x2 + (size_t)b * N2c * Dc;
        float* C = d_x2o + (size_t)b * N1c * Dc;
        mma_mainloop32<true>(sm, af3_w, W, Dc, my * 128, nb * 128, acc);
        epi_std<true>(acc, af3_b, C, Dc, my * 128, nb * 128, BIGR, 0, 0, 1);
    }
}

// ---------------- kernel 3: attn_out GEMM + weighted combine -----------------
__global__ __launch_bounds__(256, 2) void gemm_final(
    const float* __restrict__ W, const float* __restrict__ bias,
    const float* __restrict__ x1, const float* __restrict__ x2,
    float* __restrict__ out)
{
    extern __shared__ float sm[];
    int m0 = blockIdx.y * 128, n0 = blockIdx.x * 128;
    float acc[2][8][4];
    mma_mainloop32<false>(sm, d_o, W, 0, m0, n0, acc);

    const int tid = threadIdx.x, lane = tid & 31, warp = tid >> 5;
    const int wm = warp >> 1, wn = warp & 1;
    const int gid = lane >> 2, tig = lane & 3;

    #pragma unroll
    for (int mt = 0; mt < 2; mt++) {
        #pragma unroll
        for (int rh = 0; rh < 2; rh++) {
            int r = m0 + wm * 32 + mt * 16 + gid + rh * 8;
            int b = r / Sc;
            int s = r - b * Sc;
            const float* w = d_wts + b * 4;
            float w0 = w[0], w1 = w[1], w2 = w[2], w3 = w[3];
            const float* lfr = d_lf + (size_t)r * Dc;
            const float* xo; const float* xo2; const float* xv; float* dst;
            if (s < N1c) {
                size_t rr = (size_t)b * N1c + s;
                xo = d_xout + rr * Dc;
                xo2 = d_x2o + rr * Dc;
                xv = x1 + rr * Dc;
                dst = out + rr * Dc;
            } else {
                int s2 = s - N1c;
                xo = d_xout + ((size_t)b * N1c + s2) * Dc;
                xo2 = d_x2o + ((size_t)b * N1c + s2) * Dc;
                xv = x2 + ((size_t)b * N2c + s2) * Dc;
                dst = out + (size_t)Bb * N1c * Dc + ((size_t)b * N2c + s2) * Dc;
            }
            #pragma unroll
            for (int nt = 0; nt < 8; nt++) {
                int col = n0 + wn * 64 + nt * 8 + tig * 2;
                float2 bc = *(const float2*)(bias + col);
                float op0 = acc[mt][nt][rh * 2 + 0] + bc.x;
                float op1 = acc[mt][nt][rh * 2 + 1] + bc.y;
                float2 l = *(const float2*)(lfr + col);
                float2 g = *(const float2*)(xo + col);
                float2 g2 = *(const float2*)(xo2 + col);
                float2 y = *(const float2*)(xv + col);
                float o0 = w0 * l.x + w1 * (g.x + g2.x) + w2 * op0 + w3 * y.x;
                float o1 = w0 * l.y + w1 * (g.y + g2.y) + w2 * op1 + w3 * y.y;
                *(float2*)(dst + col) = make_float2(o0, o1);
            }
        }
    }
}

// ---------------- launch ----------------------------------------------------
extern "C" void kernel_launch(void* const* d_in, const int* in_sizes, int n_in,
                              void* d_out, int out_size)
{
    const float* x1        = (const float*)d_in[0];
    const float* x2        = (const float*)d_in[1];
    const float* r_w1      = (const float*)d_in[2];
    const float* r_b1      = (const float*)d_in[3];
    const float* ln_g      = (const float*)d_in[4];
    const float* ln_b      = (const float*)d_in[5];
    const float* lf_w      = (const float*)d_in[8];
    const float* lf_b      = (const float*)d_in[9];
    const float* af2_w     = (const float*)d_in[10];
    const float* af2_b     = (const float*)d_in[11];
    const float* af3_w     = (const float*)d_in[12];
    const float* af3_b     = (const float*)d_in[13];
    const float* r_w2      = (const float*)d_in[6];
    const float* r_b2      = (const float*)d_in[7];
    const float* attn_in_w = (const float*)d_in[14];
    const float* attn_in_b = (const float*)d_in[15];
    const float* attn_out_w= (const float*)d_in[16];
    const float* attn_out_b= (const float*)d_in[17];
    float* out = (float*)d_out;

    const int GEMM_SMEM = 3 * GSTG * (int)sizeof(float);  // 110592
    cudaFuncSetAttribute(k_qkv_router, cudaFuncAttributeMaxDynamicSharedMemorySize, GEMM_SMEM);
    cudaFuncSetAttribute(k_mega, cudaFuncAttributeMaxDynamicSharedMemorySize, GEMM_SMEM);
    cudaFuncSetAttribute(gemm_final, cudaFuncAttributeMaxDynamicSharedMemorySize, GEMM_SMEM);

    // 1. qkv GEMMs + router (independent of each other)
    k_qkv_router<<<1184, 256, GEMM_SMEM>>>(x1, x2, attn_in_w, attn_in_b,
                                           r_w1, r_b1, ln_g, ln_b, r_w2, r_b2);

    // 2. attention + all GEMMs that don't feed attention, one launch
    k_mega<<<2432, 256, GEMM_SMEM>>>(x1, x2, lf_w, lf_b, af2_w, af2_b,
                                     af3_w, af3_b);

    // 3. attn_out GEMM fused with weighted combine
    gemm_final<<<dim3(2, 192), 256, GEMM_SMEM>>>(attn_out_w, attn_out_b, x1, x2, out);
}

// round 15
// speedup vs baseline: 4.3265x; 1.0051x over previous
#include <cuda_runtime.h>
#include <math.h>

// Shapes (fixed by the problem)
#define Bb   32
#define N1c  512
#define N2c  256
#define Dc   256
#define Hc   8
#define HDc  32
#define Sc   768   // N1 + N2

// ---------------- tf32 MMA (raw fp32 operands; HW truncates to tf32) --------
__device__ __forceinline__ void mma_tf32(float (&c)[4], const unsigned (&a)[4],
                                         const unsigned (&b)[2]) {
    asm("mma.sync.aligned.m16n8k8.row.col.f32.tf32.tf32.f32 "
        "{%0,%1,%2,%3},{%4,%5,%6,%7},{%8,%9},{%0,%1,%2,%3};"
        : "+f"(c[0]), "+f"(c[1]), "+f"(c[2]), "+f"(c[3])
        : "r"(a[0]), "r"(a[1]), "r"(a[2]), "r"(a[3]), "r"(b[0]), "r"(b[1]));
}

__device__ __forceinline__ void cp16(float* dst, const float* src) {
    unsigned ds = (unsigned)__cvta_generic_to_shared(dst);
    asm volatile("cp.async.cg.shared.global [%0], [%1], 16;" :: "r"(ds), "l"(src));
}
__device__ __forceinline__ void cp_commit() {
    asm volatile("cp.async.commit_group;" ::: "memory");
}

// ---------------- scratch (device globals; no allocations allowed) ----------
__device__ __align__(16) float d_qkv [Bb * Sc * 3 * Dc];
__device__ __align__(16) float d_lf  [Bb * Sc * Dc];
__device__ __align__(16) float d_xout[Bb * N1c * Dc];   // a1
__device__ __align__(16) float d_x2o [Bb * N1c * Dc];   // a2
__device__ __align__(16) float d_o   [Bb * Sc * Dc];
__device__ float d_wts [Bb * 4];

// ---------------- router body (256 threads, dynamic smem) --------------------
__device__ void router_body(float* sm, int b,
    const float* __restrict__ x1, const float* __restrict__ x2,
    const float* __restrict__ r_w1, const float* __restrict__ r_b1,
    const float* __restrict__ ln_g, const float* __restrict__ ln_b,
    const float* __restrict__ r_w2, const float* __restrict__ r_b2)
{
    float* m   = sm;                 // 512
    float4* ps = (float4*)(sm + 512);// 256 float4
    float* hb  = sm + 1536;          // 256
    float* red = sm + 1792;          // 8
    float* lg  = sm + 1800;          // 4
    int t = threadIdx.x;
    int c4 = t & 63, rq = t >> 6;

    {
        const float4* p = (const float4*)(x1 + (size_t)b * N1c * Dc) + (size_t)rq * 128 * 64 + c4;
        float4 s = make_float4(0.f, 0.f, 0.f, 0.f);
        for (int n = 0; n < 128; n++) {
            float4 v = p[(size_t)n * 64];
            s.x += v.x; s.y += v.y; s.z += v.z; s.w += v.w;
        }
        ps[rq * 64 + c4] = s;
    }
    __syncthreads();
    if (t < 64) {
        float4 a = ps[t], b1 = ps[64 + t], c = ps[128 + t], d = ps[192 + t];
        m[t * 4 + 0] = (a.x + b1.x + c.x + d.x) * (1.f / N1c);
        m[t * 4 + 1] = (a.y + b1.y + c.y + d.y) * (1.f / N1c);
        m[t * 4 + 2] = (a.z + b1.z + c.z + d.z) * (1.f / N1c);
        m[t * 4 + 3] = (a.w + b1.w + c.w + d.w) * (1.f / N1c);
    }
    __syncthreads();
    {
        const float4* p = (const float4*)(x2 + (size_t)b * N2c * Dc) + (size_t)rq * 64 * 64 + c4;
        float4 s = make_float4(0.f, 0.f, 0.f, 0.f);
        for (int n = 0; n < 64; n++) {
            float4 v = p[(size_t)n * 64];
            s.x += v.x; s.y += v.y; s.z += v.z; s.w += v.w;
        }
        ps[rq * 64 + c4] = s;
    }
    __syncthreads();
    if (t < 64) {
        float4 a = ps[t], b1 = ps[64 + t], c = ps[128 + t], d = ps[192 + t];
        m[Dc + t * 4 + 0] = (a.x + b1.x + c.x + d.x) * (1.f / N2c);
        m[Dc + t * 4 + 1] = (a.y + b1.y + c.y + d.y) * (1.f / N2c);
        m[Dc + t * 4 + 2] = (a.z + b1.z + c.z + d.z) * (1.f / N2c);
        m[Dc + t * 4 + 3] = (a.w + b1.w + c.w + d.w) * (1.f / N2c);
    }
    __syncthreads();

    float acc = r_b1[t];
    const float* wr = r_w1 + (size_t)t * (2 * Dc);
    #pragma unroll 4
    for (int k = 0; k < 2 * Dc; k++) acc += m[k] * wr[k];

    float v = acc;
    for (int o = 16; o; o >>= 1) v += __shfl_down_sync(0xffffffffu, v, o);
    if ((t & 31) == 0) red[t >> 5] = v;
    __syncthreads();
    if (t < 8) {
        v = red[t];
        for (int o = 4; o; o >>= 1) v += __shfl_down_sync(0xffu, v, o);
        if (t == 0) red[0] = v;
    }
    __syncthreads();
    float mu = red[0] * (1.f / Dc);
    __syncthreads();
    float dd = acc - mu;
    v = dd * dd;
    for (int o = 16; o; o >>= 1) v += __shfl_down_sync(0xffffffffu, v, o);
    if ((t & 31) == 0) red[t >> 5] = v;
    __syncthreads();
    if (t < 8) {
        v = red[t];
        for (int o = 4; o; o >>= 1) v += __shfl_down_sync(0xffu, v, o);
        if (t == 0) red[0] = v;
    }
    __syncthreads();
    float var = red[0] * (1.f / Dc);
    float y = dd * rsqrtf(var + 1e-5f) * ln_g[t] + ln_b[t];
    float g = 0.5f * y * (1.f + erff(y * 0.70710678118654752f));
    hb[t] = g;
    __syncthreads();

    if (t < 4) {
        float a = r_b2[t];
        const float* w2 = r_w2 + (size_t)t * Dc;
        for (int k = 0; k < Dc; k++) a += hb[k] * w2[k];
        lg[t] = a;
    }
    __syncthreads();
    if (t == 0) {
        float mx = fmaxf(fmaxf(lg[0], lg[1]), fmaxf(lg[2], lg[3]));
        float e0 = expf(lg[0] - mx), e1 = expf(lg[1] - mx);
        float e2 = expf(lg[2] - mx), e3 = expf(lg[3] - mx);
        float inv = 1.f / (e0 + e1 + e2 + e3);
        d_wts[b * 4 + 0] = e0 * inv; d_wts[b * 4 + 1] = e1 * inv;
        d_wts[b * 4 + 2] = e2 * inv; d_wts[b * 4 + 3] = e3 * inv;
    }
}

// ============ 256-thread GEMM (BM=128, BN=128, BK=32) — used inside k_mega ===
#define GSTG 9216

template<bool BT>
__device__ __forceinline__ void issue_tile32(
    float* sm, const float* __restrict__ A, const float* __restrict__ W,
    int ldB, int m0, int n0, int t)
{
    const int tid = threadIdx.x;
    const int k0 = t * 32;
    float* As = sm + (t % 3) * GSTG;
    float* Bs = As + 4608;
    #pragma unroll
    for (int h = 0; h < 4; h++) {
        int c = tid + h * 256;
        int row = c >> 3, ko = (c & 7) * 4;
        cp16(As + row * 36 + ko, A + (size_t)(m0 + row) * 256 + k0 + ko);
    }
    if (BT) {
        #pragma unroll
        for (int h = 0; h < 4; h++) {
            int c = tid + h * 256;
            int k = c >> 5, nq = (c & 31) * 4;
            cp16(Bs + k * 136 + nq, W + (size_t)(k0 + k) * ldB + n0 + nq);
        }
    } else {
        #pragma unroll
        for (int h = 0; h < 4; h++) {
            int c = tid + h * 256;
            int row = c >> 3, ko = (c & 7) * 4;
            cp16(Bs + row * 36 + ko, W + (size_t)(n0 + row) * 256 + k0 + ko);
        }
    }
    cp_commit();
}

template<bool BT>
__device__ __forceinline__ void mma_mainloop32(
    float* sm, const float* __restrict__ A, const float* __restrict__ W,
    int ldB, int m0, int n0, float (&acc)[2][8][4])
{
    const int tid = threadIdx.x, lane = tid & 31, warp = tid >> 5;
    const int wm = warp >> 1, wn = warp & 1;
    const int gid = lane >> 2, tig = lane & 3;

    #pragma unroll
    for (int i = 0; i < 2; i++)
        #pragma unroll
        for (int j = 0; j < 8; j++)
            #pragma unroll
            for (int c = 0; c < 4; c++) acc[i][j][c] = 0.f;

    issue_tile32<BT>(sm, A, W, ldB, m0, n0, 0);
    issue_tile32<BT>(sm, A, W, ldB, m0, n0, 1);

    for (int t = 0; t < 8; t++) {
        if (t < 7) asm volatile("cp.async.wait_group 1;" ::: "memory");
        else       asm volatile("cp.async.wait_group 0;" ::: "memory");
        __syncthreads();
        if (t + 2 < 8) issue_tile32<BT>(sm, A, W, ldB, m0, n0, t + 2);

        const float* As = sm + (t % 3) * GSTG;
        const float* Bs = As + 4608;
        #pragma unroll
        for (int ks8 = 0; ks8 < 4; ks8++) {
            unsigned af[2][4];
            #pragma unroll
            for (int mt = 0; mt < 2; mt++) {
                int mb = wm * 32 + mt * 16 + gid;
                af[mt][0] = __float_as_uint(As[mb * 36 + ks8 * 8 + tig]);
                af[mt][1] = __float_as_uint(As[(mb + 8) * 36 + ks8 * 8 + tig]);
                af[mt][2] = __float_as_uint(As[mb * 36 + ks8 * 8 + tig + 4]);
                af[mt][3] = __float_as_uint(As[(mb + 8) * 36 + ks8 * 8 + tig + 4]);
            }
            #pragma unroll
            for (int nt = 0; nt < 8; nt++) {
                int nb = wn * 64 + nt * 8 + gid;
                unsigned bf[2];
                if (BT) {
                    bf[0] = __float_as_uint(Bs[(ks8 * 8 + tig) * 136 + nb]);
                    bf[1] = __float_as_uint(Bs[(ks8 * 8 + tig + 4) * 136 + nb]);
                } else {
                    bf[0] = __float_as_uint(Bs[nb * 36 + ks8 * 8 + tig]);
                    bf[1] = __float_as_uint(Bs[nb * 36 + ks8 * 8 + tig + 4]);
                }
                mma_tf32(acc[0][nt], af[0], bf);
                mma_tf32(acc[1][nt], af[1], bf);
            }
        }
    }
}

template<bool RB>
__device__ __forceinline__ void epi_std(
    float (&acc)[2][8][4], const float* __restrict__ bias, float* __restrict__ C,
    int ldC, int m0, int n0, int rpb, int ostride, int ooff, int act)
{
    const int tid = threadIdx.x, lane = tid & 31, warp = tid >> 5;
    const int wm = warp >> 1, wn = warp & 1;
    const int gid = lane >> 2, tig = lane & 3;

    #pragma unroll
    for (int mt = 0; mt < 2; mt++) {
        #pragma unroll
        for (int rh = 0; rh < 2; rh++) {
            int r = m0 + wm * 32 + mt * 16 + gid + rh * 8;
            float rbv = RB ? bias[r] : 0.f;
            int grow = (r / rpb) * ostride + ooff + (r % rpb);
            float* dst = C + (size_t)grow * ldC;
            #pragma unroll
            for (int nt = 0; nt < 8; nt++) {
                int col = n0 + wn * 64 + nt * 8 + tig * 2;
                float v0 = acc[mt][nt][rh * 2 + 0];
                float v1 = acc[mt][nt][rh * 2 + 1];
                if (RB) { v0 += rbv; v1 += rbv; }
                else {
                    float2 bc = *(const float2*)(bias + col);
                    v0 += bc.x; v1 += bc.y;
                }
                if (act) {
                    v0 = v0 > 0.f ? v0 : expm1f(v0);
                    v1 = v1 > 0.f ? v1 : expm1f(v1);
                }
                *(float2*)(dst + col) = make_float2(v0, v1);
            }
        }
    }
}

// ============ 128-thread GEMM (BM=64, BN=64, BK=32, 4 warps, 4 blocks/SM) ====
// A/B non-BT: [row][36] (frag banks 4*gid+tig all-distinct).
// BT B: [k][72] (frag banks 8*tig+gid all-distinct).
// Stage = 4608 floats; 3 stages = 55296 B -> 4 blocks/SM.
#define G2STG 4608

template<bool BT>
__device__ __forceinline__ void issue_tile64(
    float* sm, const float* __restrict__ A, const float* __restrict__ W,
    int ldB, int m0, int n0, int t)
{
    const int tid = threadIdx.x;
    const int k0 = t * 32;
    float* As = sm + (t % 3) * G2STG;
    float* Bs = As + 2304;
    #pragma unroll
    for (int h = 0; h < 4; h++) {
        int c = tid + h * 128;
        int row = c >> 3, ko = (c & 7) * 4;
        cp16(As + row * 36 + ko, A + (size_t)(m0 + row) * 256 + k0 + ko);
    }
    if (BT) {
        #pragma unroll
        for (int h = 0; h < 4; h++) {
            int c = tid + h * 128;
            int k = c >> 4, nq = (c & 15) * 4;
            cp16(Bs + k * 72 + nq, W + (size_t)(k0 + k) * ldB + n0 + nq);
        }
    } else {
        #pragma unroll
        for (int h = 0; h < 4; h++) {
            int c = tid + h * 128;
            int row = c >> 3, ko = (c & 7) * 4;
            cp16(Bs + row * 36 + ko, W + (size_t)(n0 + row) * 256 + k0 + ko);
        }
    }
    cp_commit();
}

template<bool BT>
__device__ __forceinline__ void mma_loop64(
    float* sm, const float* __restrict__ A, const float* __restrict__ W,
    int ldB, int m0, int n0, float (&acc)[2][4][4])
{
    const int tid = threadIdx.x, lane = tid & 31, warp = tid >> 5;
    const int wm = warp >> 1, wn = warp & 1;
    const int gid = lane >> 2, tig = lane & 3;

    #pragma unroll
    for (int i = 0; i < 2; i++)
        #pragma unroll
        for (int j = 0; j < 4; j++)
            #pragma unroll
            for (int c = 0; c < 4; c++) acc[i][j][c] = 0.f;

    issue_tile64<BT>(sm, A, W, ldB, m0, n0, 0);
    issue_tile64<BT>(sm, A, W, ldB, m0, n0, 1);

    for (int t = 0; t < 8; t++) {
        if (t < 7) asm volatile("cp.async.wait_group 1;" ::: "memory");
        else       asm volatile("cp.async.wait_group 0;" ::: "memory");
        __syncthreads();
        if (t + 2 < 8) issue_tile64<BT>(sm, A, W, ldB, m0, n0, t + 2);

        const float* As = sm + (t % 3) * G2STG;
        const float* Bs = As + 2304;
        #pragma unroll
        for (int ks8 = 0; ks8 < 4; ks8++) {
            unsigned af[2][4];
            #pragma unroll
            for (int mt = 0; mt < 2; mt++) {
                int mb = wm * 32 + mt * 16 + gid;
                af[mt][0] = __float_as_uint(As[mb * 36 + ks8 * 8 + tig]);
                af[mt][1] = __float_as_uint(As[(mb + 8) * 36 + ks8 * 8 + tig]);
                af[mt][2] = __float_as_uint(As[mb * 36 + ks8 * 8 + tig + 4]);
                af[mt][3] = __float_as_uint(As[(mb + 8) * 36 + ks8 * 8 + tig + 4]);
            }
            #pragma unroll
            for (int nt = 0; nt < 4; nt++) {
                int nb = wn * 32 + nt * 8 + gid;
                unsigned bf[2];
                if (BT) {
                    bf[0] = __float_as_uint(Bs[(ks8 * 8 + tig) * 72 + nb]);
                    bf[1] = __float_as_uint(Bs[(ks8 * 8 + tig + 4) * 72 + nb]);
                } else {
                    bf[0] = __float_as_uint(Bs[nb * 36 + ks8 * 8 + tig]);
                    bf[1] = __float_as_uint(Bs[nb * 36 + ks8 * 8 + tig + 4]);
                }
                mma_tf32(acc[0][nt], af[0], bf);
                mma_tf32(acc[1][nt], af[1], bf);
            }
        }
    }
}

template<bool RB>
__device__ __forceinline__ void epi64(
    float (&acc)[2][4][4], const float* __restrict__ bias, float* __restrict__ C,
    int ldC, int m0, int n0, int rpb, int ostride, int ooff, int act)
{
    const int tid = threadIdx.x, lane = tid & 31, warp = tid >> 5;
    const int wm = warp >> 1, wn = warp & 1;
    const int gid = lane >> 2, tig = lane & 3;

    #pragma unroll
    for (int mt = 0; mt < 2; mt++) {
        #pragma unroll
        for (int rh = 0; rh < 2; rh++) {
            int r = m0 + wm * 32 + mt * 16 + gid + rh * 8;
            float rbv = RB ? bias[r] : 0.f;
            int grow = (r / rpb) * ostride + ooff + (r % rpb);
            float* dst = C + (size_t)grow * ldC;
            #pragma unroll
            for (int nt = 0; nt < 4; nt++) {
                int col = n0 + wn * 32 + nt * 8 + tig * 2;
                float v0 = acc[mt][nt][rh * 2 + 0];
                float v1 = acc[mt][nt][rh * 2 + 1];
                if (RB) { v0 += rbv; v1 += rbv; }
                else {
                    float2 bc = *(const float2*)(bias + col);
                    v0 += bc.x; v1 += bc.y;
                }
                if (act) {
                    v0 = v0 > 0.f ? v0 : expm1f(v0);
                    v1 = v1 > 0.f ? v1 : expm1f(v1);
                }
                *(float2*)(dst + col) = make_float2(v0, v1);
            }
        }
    }
}

// ---------------- kernel 1: qkv GEMMs (128-thread, 4 blocks/SM) --------------
// grid: [0,3072) x1 (nb = bx>>8, my = bx&255); [3072,4608) x2 (nb = idx>>7, my = idx&127)
__global__ __launch_bounds__(128, 4) void k_qkv(
    const float* __restrict__ x1, const float* __restrict__ x2,
    const float* __restrict__ attn_in_w, const float* __restrict__ attn_in_b)
{
    extern __shared__ float sm[];
    int bx = blockIdx.x;
    float acc[2][4][4];
    if (bx < 3072) {
        int nb = bx >> 8, my = bx & 255;
        mma_loop64<false>(sm, x1, attn_in_w, 0, my * 64, nb * 64, acc);
        epi64<false>(acc, attn_in_b, d_qkv, 3 * Dc, my * 64, nb * 64,
                     N1c, Sc, 0, 0);
    } else {
        int idx = bx - 3072;
        int nb = idx >> 7, my = idx & 127;
        mma_loop64<false>(sm, x2, attn_in_w, 0, my * 64, nb * 64, acc);
        epi64<false>(acc, attn_in_b, d_qkv, 3 * Dc, my * 64, nb * 64,
                     N2c, Sc, N1c, 0);
    }
}

// ---------------- attention body (tf32 MMA, interleaved smem) ----------------
__device__ void attn_body(float* sm, int qt, int bh)
{
    float* Ks = sm;            // 4096
    float* Vs = sm + 4096;     // 4096
    float* Ps = sm + 8192;     // 16384 (8 warps x 2048)

    const int b = bh >> 3, h = bh & 7;
    const int tid = threadIdx.x, lane = tid & 31, warp = tid >> 5;
    const int gid = lane >> 2, tig = lane & 3;
    const int gsw = gid & 3;
    const int m0 = qt * 128;
    const float* base = d_qkv + (size_t)b * Sc * (3 * Dc);
    const float scale = 0.17677669529663688f;   // 1/sqrt(32)
    float* Pw = Ps + warp * 2048;

    unsigned qf[4][4];
    {
        const float* q0 = base + (size_t)(m0 + warp * 16 + gid) * (3 * Dc) + h * HDc;
        const float* q1 = q0 + (size_t)8 * (3 * Dc);
        #pragma unroll
        for (int ks = 0; ks < 4; ks++) {
            qf[ks][0] = __float_as_uint(q0[ks * 8 + tig] * scale);
            qf[ks][1] = __float_as_uint(q1[ks * 8 + tig] * scale);
            qf[ks][2] = __float_as_uint(q0[ks * 8 + tig + 4] * scale);
            qf[ks][3] = __float_as_uint(q1[ks * 8 + tig + 4] * scale);
        }
    }

    float oc[4][4];
    #pragma unroll
    for (int i = 0; i < 4; i++)
        #pragma unroll
        for (int j = 0; j < 4; j++) oc[i][j] = 0.f;
    float ls[4] = { 0.f, 0.f, 0.f, 0.f };
    const unsigned bones[2] = { 0x3f800000u, 0x3f800000u };

    for (int c = 0; c < 6; c++) {
        const int kv0 = c * 128;
        __syncthreads();

        #pragma unroll
        for (int it = 0; it < 4; it++) {
            int i = tid + it * 256;
            int cc = (i & 7) * 4, r = i >> 3;
            const float* src = base + (size_t)(kv0 + r) * (3 * Dc) + Dc + h * HDc + cc;
            float4 v = *(const float4*)src;
            float vv[4] = { v.x, v.y, v.z, v.w };
            #pragma unroll
            for (int j = 0; j < 4; j++) {
                int cq = cc + j;
                Ks[(((cq >> 3) * 128 + r) * 8) + (((cq & 3) ^ (r & 3)) * 2) + ((cq >> 2) & 1)] = vv[j];
            }
        }
        #pragma unroll
        for (int it = 0; it < 4; it++) {
            int i = tid + it * 256;
            int r = i & 127, cg = (i >> 7) * 4;
            const float* src = base + (size_t)(kv0 + r) * (3 * Dc) + 2 * Dc + h * HDc + cg;
            float4 v = *(const float4*)src;
            int w = (r & 3) * 2 + ((r >> 2) & 1);
            int qb = (r >> 3) * 32 + cg;
            Vs[(qb + 0) * 8 + w] = v.x; Vs[(qb + 1) * 8 + w] = v.y;
            Vs[(qb + 2) * 8 + w] = v.z; Vs[(qb + 3) * 8 + w] = v.w;
        }
        __syncthreads();

        #pragma unroll
        for (int half = 0; half < 2; half++) {
            float sc_[8][4];
            #pragma unroll
            for (int nt = 0; nt < 8; nt++)
                #pragma unroll
                for (int j = 0; j < 4; j++) sc_[nt][j] = 0.f;
            #pragma unroll
            for (int ks = 0; ks < 4; ks++) {
                #pragma unroll
                for (int nt = 0; nt < 8; nt++) {
                    int nb = half * 64 + nt * 8 + gid;
                    float2 k2 = *(const float2*)&Ks[((ks * 128 + nb) * 8) + ((tig ^ gsw) * 2)];
                    unsigned bf[2] = { __float_as_uint(k2.x), __float_as_uint(k2.y) };
                    mma_tf32(sc_[nt], qf[ks], bf);
                }
            }
            #pragma unroll
            for (int nt = 0; nt < 8; nt++) {
                float p0 = __expf(sc_[nt][0]);
                float p1 = __expf(sc_[nt][1]);
                float p2 = __expf(sc_[nt][2]);
                float p3 = __expf(sc_[nt][3]);
                int ksq = half * 8 + nt;
                int tc0 = tig * 2, tc1 = tc0 + 1;
                float* pb = Pw + ksq * 128 + gid * 16;
                *(float2*)&pb[((tc0 & 3) ^ gsw) * 4 + (tc0 >> 2) * 2] = make_float2(p0, p2);
                *(float2*)&pb[((tc1 & 3) ^ gsw) * 4 + (tc1 >> 2) * 2] = make_float2(p1, p3);
            }
        }
        __syncwarp();

        #pragma unroll
        for (int ks = 0; ks < 16; ks++) {
            float4 aq = *(const float4*)&Pw[ks * 128 + gid * 16 + ((tig ^ gsw) * 4)];
            unsigned a[4] = { __float_as_uint(aq.x), __float_as_uint(aq.y),
                              __float_as_uint(aq.z), __float_as_uint(aq.w) };
            #pragma unroll
            for (int nf = 0; nf < 4; nf++) {
                float2 v2 = *(const float2*)&Vs[((ks * 32 + nf * 8 + gid) * 8) + tig * 2];
                unsigned bv[2] = { __float_as_uint(v2.x), __float_as_uint(v2.y) };
                mma_tf32(oc[nf], a, bv);
            }
            mma_tf32(ls, a, bones);
        }
        __syncwarp();
    }

    float inv0 = 1.f / ls[0], inv1 = 1.f / ls[2];
    float* o0 = d_o + (size_t)(b * Sc + m0 + warp * 16 + gid) * Dc + h * HDc;
    float* o1 = o0 + 8 * Dc;
    #pragma unroll
    for (int nf = 0; nf < 4; nf++) {
        int col = nf * 8 + tig * 2;
        *(float2*)&o0[col] = make_float2(oc[nf][0] * inv0, oc[nf][1] * inv0);
        *(float2*)&o1[col] = make_float2(oc[nf][2] * inv1, oc[nf][3] * inv1);
    }
}

// ---------------- kernel 2 (mega): attention + independent GEMMs + router ----
// grid: [0,1536) attn; [1536,1792) x1-lf; [1792,2048) a1; [2048,2176) x2-lf;
//       [2176,2432) a2; [2432,2464) router
__global__ __launch_bounds__(256, 2) void k_mega(
    const float* __restrict__ x1, const float* __restrict__ x2,
    const float* __restrict__ lf_w, const float* __restrict__ lf_b,
    const float* __restrict__ af2_w, const float* __restrict__ af2_b,
    const float* __restrict__ af3_w, const float* __restrict__ af3_b,
    const float* __restrict__ r_w1, const float* __restrict__ r_b1,
    const float* __restrict__ ln_g, const float* __restrict__ ln_b,
    const float* __restrict__ r_w2, const float* __restrict__ r_b2)
{
    extern __shared__ float sm[];
    const int BIGR = 1 << 30;
    int bx = blockIdx.x;

    if (bx < 1536) {
        attn_body(sm, bx % 6, bx / 6);
        return;
    }
    if (bx >= 2432) {
        router_body(sm, bx - 2432, x1, x2, r_w1, r_b1, ln_g, ln_b, r_w2, r_b2);
        return;
    }
    float acc[2][8][4];
    if (bx < 1792) {
        int idx = bx - 1536;
        int nb = idx >> 7, my = idx & 127;
        mma_mainloop32<false>(sm, x1, lf_w, 0, my * 128, nb * 128, acc);
        epi_std<false>(acc, lf_b, d_lf, Dc, my * 128, nb * 128, N1c, Sc, 0, 1);
    } else if (bx < 2048) {
        int idx = bx - 1792;
        int nb = idx >> 7, my = idx & 127;
        mma_mainloop32<false>(sm, x1, af2_w, 0, my * 128, nb * 128, acc);
        epi_std<false>(acc, af2_b, d_xout, Dc, my * 128, nb * 128, BIGR, 0, 0, 1);
    } else if (bx < 2176) {
        int idx = bx - 2048;
        int nb = idx >> 6, my = idx & 63;
        mma_mainloop32<false>(sm, x2, lf_w, 0, my * 128, nb * 128, acc);
        epi_std<false>(acc, lf_b, d_lf, Dc, my * 128, nb * 128, N2c, Sc, N1c, 1);
    } else {
        int idx = bx - 2176;
        int b = idx >> 3, r = idx & 7;
        int nb = r & 1, my = r >> 1;
        const float* W = x2 + (size_t)b * N2c * Dc;
        float* C = d_x2o + (size_t)b * N1c * Dc;
        mma_mainloop32<true>(sm, af3_w, W, Dc, my * 128, nb * 128, acc);
        epi_std<true>(acc, af3_b, C, Dc, my * 128, nb * 128, BIGR, 0, 0, 1);
    }
}

// ---------------- kernel 3: attn_out GEMM + weighted combine (128-thr) ------
__global__ __launch_bounds__(128, 4) void gemm_final(
    const float* __restrict__ W, const float* __restrict__ bias,
    const float* __restrict__ x1, const float* __restrict__ x2,
    float* __restrict__ out)
{
    extern __shared__ float sm[];
    int m0 = blockIdx.y * 64, n0 = blockIdx.x * 64;
    float acc[2][4][4];
    mma_loop64<false>(sm, d_o, W, 0, m0, n0, acc);

    const int tid = threadIdx.x, lane = tid & 31, warp = tid >> 5;
    const int wm = warp >> 1, wn = warp & 1;
    const int gid = lane >> 2, tig = lane & 3;

    #pragma unroll
    for (int mt = 0; mt < 2; mt++) {
        #pragma unroll
        for (int rh = 0; rh < 2; rh++) {
            int r = m0 + wm * 32 + mt * 16 + gid + rh * 8;
            int b = r / Sc;
            int s = r - b * Sc;
            const float* w = d_wts + b * 4;
            float w0 = w[0], w1 = w[1], w2 = w[2], w3 = w[3];
            const float* lfr = d_lf + (size_t)r * Dc;
            const float* xo; const float* xo2; const float* xv; float* dst;
            if (s < N1c) {
                size_t rr = (size_t)b * N1c + s;
                xo = d_xout + rr * Dc;
                xo2 = d_x2o + rr * Dc;
                xv = x1 + rr * Dc;
                dst = out + rr * Dc;
            } else {
                int s2 = s - N1c;
                xo = d_xout + ((size_t)b * N1c + s2) * Dc;
                xo2 = d_x2o + ((size_t)b * N1c + s2) * Dc;
                xv = x2 + ((size_t)b * N2c + s2) * Dc;
                dst = out + (size_t)Bb * N1c * Dc + ((size_t)b * N2c + s2) * Dc;
            }
            #pragma unroll
            for (int nt = 0; nt < 4; nt++) {
                int col = n0 + wn * 32 + nt * 8 + tig * 2;
                float2 bc = *(const float2*)(bias + col);
                float op0 = acc[mt][nt][rh * 2 + 0] + bc.x;
                float op1 = acc[mt][nt][rh * 2 + 1] + bc.y;
                float2 l = *(const float2*)(lfr + col);
                float2 g = *(const float2*)(xo + col);
                float2 g2 = *(const float2*)(xo2 + col);
                float2 y = *(const float2*)(xv + col);
                float o0 = w0 * l.x + w1 * (g.x + g2.x) + w2 * op0 + w3 * y.x;
                float o1 = w0 * l.y + w1 * (g.y + g2.y) + w2 * op1 + w3 * y.y;
                *(float2*)(dst + col) = make_float2(o0, o1);
            }
        }
    }
}

// ---------------- launch ----------------------------------------------------
extern "C" void kernel_launch(void* const* d_in, const int* in_sizes, int n_in,
                              void* d_out, int out_size)
{
    const float* x1        = (const float*)d_in[0];
    const float* x2        = (const float*)d_in[1];
    const float* r_w1      = (const float*)d_in[2];
    const float* r_b1      = (const float*)d_in[3];
    const float* ln_g      = (const float*)d_in[4];
    const float* ln_b      = (const float*)d_in[5];
    const float* r_w2      = (const float*)d_in[6];
    const float* r_b2      = (const float*)d_in[7];
    const float* lf_w      = (const float*)d_in[8];
    const float* lf_b      = (const float*)d_in[9];
    const float* af2_w     = (const float*)d_in[10];
    const float* af2_b     = (const float*)d_in[11];
    const float* af3_w     = (const float*)d_in[12];
    const float* af3_b     = (const float*)d_in[13];
    const float* attn_in_w = (const float*)d_in[14];
    const float* attn_in_b = (const float*)d_in[15];
    const float* attn_out_w= (const float*)d_in[16];
    const float* attn_out_b= (const float*)d_in[17];
    float* out = (float*)d_out;

    const int MEGA_SMEM = 3 * GSTG * (int)sizeof(float);   // 110592
    const int G64_SMEM  = 3 * G2STG * (int)sizeof(float);  // 55296
    cudaFuncSetAttribute(k_qkv, cudaFuncAttributeMaxDynamicSharedMemorySize, G64_SMEM);
    cudaFuncSetAttribute(k_mega, cudaFuncAttributeMaxDynamicSharedMemorySize, MEGA_SMEM);
    cudaFuncSetAttribute(gemm_final, cudaFuncAttributeMaxDynamicSharedMemorySize, G64_SMEM);

    // 1. qkv GEMMs (128-thread blocks, 4/SM)
    k_qkv<<<4608, 128, G64_SMEM>>>(x1, x2, attn_in_w, attn_in_b);

    // 2. attention + independent GEMMs + router, one launch
    k_mega<<<2464, 256, MEGA_SMEM>>>(x1, x2, lf_w, lf_b, af2_w, af2_b,
                                     af3_w, af3_b,
                                     r_w1, r_b1, ln_g, ln_b, r_w2, r_b2);

    // 3. attn_out GEMM fused with weighted combine
    gemm_final<<<dim3(4, 384), 128, G64_SMEM>>>(attn_out_w, attn_out_b, x1, x2, out);
}

// round 16
// speedup vs baseline: 4.6797x; 1.0816x over previous
#include <cuda_runtime.h>
#include <math.h>

// Shapes (fixed by the problem)
#define Bb   32
#define N1c  512
#define N2c  256
#define Dc   256
#define Hc   8
#define HDc  32
#define Sc   768   // N1 + N2

// ---------------- tf32 MMA (raw fp32 operands; HW truncates to tf32) --------
__device__ __forceinline__ void mma_tf32(float (&c)[4], const unsigned (&a)[4],
                                         const unsigned (&b)[2]) {
    asm("mma.sync.aligned.m16n8k8.row.col.f32.tf32.tf32.f32 "
        "{%0,%1,%2,%3},{%4,%5,%6,%7},{%8,%9},{%0,%1,%2,%3};"
        : "+f"(c[0]), "+f"(c[1]), "+f"(c[2]), "+f"(c[3])
        : "r"(a[0]), "r"(a[1]), "r"(a[2]), "r"(a[3]), "r"(b[0]), "r"(b[1]));
}

__device__ __forceinline__ void cp16(float* dst, const float* src) {
    unsigned ds = (unsigned)__cvta_generic_to_shared(dst);
    asm volatile("cp.async.cg.shared.global [%0], [%1], 16;" :: "r"(ds), "l"(src));
}
__device__ __forceinline__ void cp_commit() {
    asm volatile("cp.async.commit_group;" ::: "memory");
}

// ---------------- scratch (device globals; no allocations allowed) ----------
__device__ __align__(16) float d_qkv [Bb * Sc * 3 * Dc];
__device__ __align__(16) float d_lf  [Bb * Sc * Dc];
__device__ __align__(16) float d_xout[Bb * N1c * Dc];   // a1
__device__ __align__(16) float d_x2o [Bb * N1c * Dc];   // a2
__device__ __align__(16) float d_o   [Bb * Sc * Dc];
__device__ float d_wts [Bb * 4];

// ---------------- router body (256 threads, dynamic smem) --------------------
__device__ void router_body(float* sm, int b,
    const float* __restrict__ x1, const float* __restrict__ x2,
    const float* __restrict__ r_w1, const float* __restrict__ r_b1,
    const float* __restrict__ ln_g, const float* __restrict__ ln_b,
    const float* __restrict__ r_w2, const float* __restrict__ r_b2)
{
    float* m   = sm;                 // 512
    float4* ps = (float4*)(sm + 512);// 256 float4
    float* hb  = sm + 1536;          // 256
    float* red = sm + 1792;          // 8
    float* lg  = sm + 1800;          // 4
    int t = threadIdx.x;
    int c4 = t & 63, rq = t >> 6;

    {
        const float4* p = (const float4*)(x1 + (size_t)b * N1c * Dc) + (size_t)rq * 128 * 64 + c4;
        float4 s = make_float4(0.f, 0.f, 0.f, 0.f);
        for (int n = 0; n < 128; n++) {
            float4 v = p[(size_t)n * 64];
            s.x += v.x; s.y += v.y; s.z += v.z; s.w += v.w;
        }
        ps[rq * 64 + c4] = s;
    }
    __syncthreads();
    if (t < 64) {
        float4 a = ps[t], b1 = ps[64 + t], c = ps[128 + t], d = ps[192 + t];
        m[t * 4 + 0] = (a.x + b1.x + c.x + d.x) * (1.f / N1c);
        m[t * 4 + 1] = (a.y + b1.y + c.y + d.y) * (1.f / N1c);
        m[t * 4 + 2] = (a.z + b1.z + c.z + d.z) * (1.f / N1c);
        m[t * 4 + 3] = (a.w + b1.w + c.w + d.w) * (1.f / N1c);
    }
    __syncthreads();
    {
        const float4* p = (const float4*)(x2 + (size_t)b * N2c * Dc) + (size_t)rq * 64 * 64 + c4;
        float4 s = make_float4(0.f, 0.f, 0.f, 0.f);
        for (int n = 0; n < 64; n++) {
            float4 v = p[(size_t)n * 64];
            s.x += v.x; s.y += v.y; s.z += v.z; s.w += v.w;
        }
        ps[rq * 64 + c4] = s;
    }
    __syncthreads();
    if (t < 64) {
        float4 a = ps[t], b1 = ps[64 + t], c = ps[128 + t], d = ps[192 + t];
        m[Dc + t * 4 + 0] = (a.x + b1.x + c.x + d.x) * (1.f / N2c);
        m[Dc + t * 4 + 1] = (a.y + b1.y + c.y + d.y) * (1.f / N2c);
        m[Dc + t * 4 + 2] = (a.z + b1.z + c.z + d.z) * (1.f / N2c);
        m[Dc + t * 4 + 3] = (a.w + b1.w + c.w + d.w) * (1.f / N2c);
    }
    __syncthreads();

    float acc = r_b1[t];
    const float* wr = r_w1 + (size_t)t * (2 * Dc);
    #pragma unroll 4
    for (int k = 0; k < 2 * Dc; k++) acc += m[k] * wr[k];

    float v = acc;
    for (int o = 16; o; o >>= 1) v += __shfl_down_sync(0xffffffffu, v, o);
    if ((t & 31) == 0) red[t >> 5] = v;
    __syncthreads();
    if (t < 8) {
        v = red[t];
        for (int o = 4; o; o >>= 1) v += __shfl_down_sync(0xffu, v, o);
        if (t == 0) red[0] = v;
    }
    __syncthreads();
    float mu = red[0] * (1.f / Dc);
    __syncthreads();
    float dd = acc - mu;
    v = dd * dd;
    for (int o = 16; o; o >>= 1) v += __shfl_down_sync(0xffffffffu, v, o);
    if ((t & 31) == 0) red[t >> 5] = v;
    __syncthreads();
    if (t < 8) {
        v = red[t];
        for (int o = 4; o; o >>= 1) v += __shfl_down_sync(0xffu, v, o);
        if (t == 0) red[0] = v;
    }
    __syncthreads();
    float var = red[0] * (1.f / Dc);
    float y = dd * rsqrtf(var + 1e-5f) * ln_g[t] + ln_b[t];
    float g = 0.5f * y * (1.f + erff(y * 0.70710678118654752f));
    hb[t] = g;
    __syncthreads();

    if (t < 4) {
        float a = r_b2[t];
        const float* w2 = r_w2 + (size_t)t * Dc;
        for (int k = 0; k < Dc; k++) a += hb[k] * w2[k];
        lg[t] = a;
    }
    __syncthreads();
    if (t == 0) {
        float mx = fmaxf(fmaxf(lg[0], lg[1]), fmaxf(lg[2], lg[3]));
        float e0 = expf(lg[0] - mx), e1 = expf(lg[1] - mx);
        float e2 = expf(lg[2] - mx), e3 = expf(lg[3] - mx);
        float inv = 1.f / (e0 + e1 + e2 + e3);
        d_wts[b * 4 + 0] = e0 * inv; d_wts[b * 4 + 1] = e1 * inv;
        d_wts[b * 4 + 2] = e2 * inv; d_wts[b * 4 + 3] = e3 * inv;
    }
}

// ============ 256-thread GEMM (BM=128, BN=128, BK=32, 3-stage cp.async) =====
#define GSTG 9216

template<bool BT>
__device__ __forceinline__ void issue_tile32(
    float* sm, const float* __restrict__ A, const float* __restrict__ W,
    int ldB, int m0, int n0, int t)
{
    const int tid = threadIdx.x;
    const int k0 = t * 32;
    float* As = sm + (t % 3) * GSTG;
    float* Bs = As + 4608;
    #pragma unroll
    for (int h = 0; h < 4; h++) {
        int c = tid + h * 256;
        int row = c >> 3, ko = (c & 7) * 4;
        cp16(As + row * 36 + ko, A + (size_t)(m0 + row) * 256 + k0 + ko);
    }
    if (BT) {
        #pragma unroll
        for (int h = 0; h < 4; h++) {
            int c = tid + h * 256;
            int k = c >> 5, nq = (c & 31) * 4;
            cp16(Bs + k * 136 + nq, W + (size_t)(k0 + k) * ldB + n0 + nq);
        }
    } else {
        #pragma unroll
        for (int h = 0; h < 4; h++) {
            int c = tid + h * 256;
            int row = c >> 3, ko = (c & 7) * 4;
            cp16(Bs + row * 36 + ko, W + (size_t)(n0 + row) * 256 + k0 + ko);
        }
    }
    cp_commit();
}

template<bool BT>
__device__ __forceinline__ void mma_mainloop32(
    float* sm, const float* __restrict__ A, const float* __restrict__ W,
    int ldB, int m0, int n0, float (&acc)[2][8][4])
{
    const int tid = threadIdx.x, lane = tid & 31, warp = tid >> 5;
    const int wm = warp >> 1, wn = warp & 1;
    const int gid = lane >> 2, tig = lane & 3;

    #pragma unroll
    for (int i = 0; i < 2; i++)
        #pragma unroll
        for (int j = 0; j < 8; j++)
            #pragma unroll
            for (int c = 0; c < 4; c++) acc[i][j][c] = 0.f;

    issue_tile32<BT>(sm, A, W, ldB, m0, n0, 0);
    issue_tile32<BT>(sm, A, W, ldB, m0, n0, 1);

    for (int t = 0; t < 8; t++) {
        if (t < 7) asm volatile("cp.async.wait_group 1;" ::: "memory");
        else       asm volatile("cp.async.wait_group 0;" ::: "memory");
        __syncthreads();
        if (t + 2 < 8) issue_tile32<BT>(sm, A, W, ldB, m0, n0, t + 2);

        const float* As = sm + (t % 3) * GSTG;
        const float* Bs = As + 4608;
        #pragma unroll
        for (int ks8 = 0; ks8 < 4; ks8++) {
            unsigned af[2][4];
            #pragma unroll
            for (int mt = 0; mt < 2; mt++) {
                int mb = wm * 32 + mt * 16 + gid;
                af[mt][0] = __float_as_uint(As[mb * 36 + ks8 * 8 + tig]);
                af[mt][1] = __float_as_uint(As[(mb + 8) * 36 + ks8 * 8 + tig]);
                af[mt][2] = __float_as_uint(As[mb * 36 + ks8 * 8 + tig + 4]);
                af[mt][3] = __float_as_uint(As[(mb + 8) * 36 + ks8 * 8 + tig + 4]);
            }
            #pragma unroll
            for (int nt = 0; nt < 8; nt++) {
                int nb = wn * 64 + nt * 8 + gid;
                unsigned bf[2];
                if (BT) {
                    bf[0] = __float_as_uint(Bs[(ks8 * 8 + tig) * 136 + nb]);
                    bf[1] = __float_as_uint(Bs[(ks8 * 8 + tig + 4) * 136 + nb]);
                } else {
                    bf[0] = __float_as_uint(Bs[nb * 36 + ks8 * 8 + tig]);
                    bf[1] = __float_as_uint(Bs[nb * 36 + ks8 * 8 + tig + 4]);
                }
                mma_tf32(acc[0][nt], af[0], bf);
                mma_tf32(acc[1][nt], af[1], bf);
            }
        }
    }
}

template<bool RB>
__device__ __forceinline__ void epi_std(
    float (&acc)[2][8][4], const float* __restrict__ bias, float* __restrict__ C,
    int ldC, int m0, int n0, int rpb, int ostride, int ooff, int act)
{
    const int tid = threadIdx.x, lane = tid & 31, warp = tid >> 5;
    const int wm = warp >> 1, wn = warp & 1;
    const int gid = lane >> 2, tig = lane & 3;

    #pragma unroll
    for (int mt = 0; mt < 2; mt++) {
        #pragma unroll
        for (int rh = 0; rh < 2; rh++) {
            int r = m0 + wm * 32 + mt * 16 + gid + rh * 8;
            float rbv = RB ? bias[r] : 0.f;
            int grow = (r / rpb) * ostride + ooff + (r % rpb);
            float* dst = C + (size_t)grow * ldC;
            #pragma unroll
            for (int nt = 0; nt < 8; nt++) {
                int col = n0 + wn * 64 + nt * 8 + tig * 2;
                float v0 = acc[mt][nt][rh * 2 + 0];
                float v1 = acc[mt][nt][rh * 2 + 1];
                if (RB) { v0 += rbv; v1 += rbv; }
                else {
                    float2 bc = *(const float2*)(bias + col);
                    v0 += bc.x; v1 += bc.y;
                }
                if (act) {
                    v0 = v0 > 0.f ? v0 : expm1f(v0);
                    v1 = v1 > 0.f ? v1 : expm1f(v1);
                }
                *(float2*)(dst + col) = make_float2(v0, v1);
            }
        }
    }
}

// ============ 128-thread GEMM (BM=64, BN=64, BK=32, 4 blocks/SM) =============
#define G2STG 4608

template<bool BT>
__device__ __forceinline__ void issue_tile64(
    float* sm, const float* __restrict__ A, const float* __restrict__ W,
    int ldB, int m0, int n0, int t)
{
    const int tid = threadIdx.x;
    const int k0 = t * 32;
    float* As = sm + (t % 3) * G2STG;
    float* Bs = As + 2304;
    #pragma unroll
    for (int h = 0; h < 4; h++) {
        int c = tid + h * 128;
        int row = c >> 3, ko = (c & 7) * 4;
        cp16(As + row * 36 + ko, A + (size_t)(m0 + row) * 256 + k0 + ko);
    }
    if (BT) {
        #pragma unroll
        for (int h = 0; h < 4; h++) {
            int c = tid + h * 128;
            int k = c >> 4, nq = (c & 15) * 4;
            cp16(Bs + k * 72 + nq, W + (size_t)(k0 + k) * ldB + n0 + nq);
        }
    } else {
        #pragma unroll
        for (int h = 0; h < 4; h++) {
            int c = tid + h * 128;
            int row = c >> 3, ko = (c & 7) * 4;
            cp16(Bs + row * 36 + ko, W + (size_t)(n0 + row) * 256 + k0 + ko);
        }
    }
    cp_commit();
}

template<bool BT>
__device__ __forceinline__ void mma_loop64(
    float* sm, const float* __restrict__ A, const float* __restrict__ W,
    int ldB, int m0, int n0, float (&acc)[2][4][4])
{
    const int tid = threadIdx.x, lane = tid & 31, warp = tid >> 5;
    const int wm = warp >> 1, wn = warp & 1;
    const int gid = lane >> 2, tig = lane & 3;

    #pragma unroll
    for (int i = 0; i < 2; i++)
        #pragma unroll
        for (int j = 0; j < 4; j++)
            #pragma unroll
            for (int c = 0; c < 4; c++) acc[i][j][c] = 0.f;

    issue_tile64<BT>(sm, A, W, ldB, m0, n0, 0);
    issue_tile64<BT>(sm, A, W, ldB, m0, n0, 1);

    for (int t = 0; t < 8; t++) {
        if (t < 7) asm volatile("cp.async.wait_group 1;" ::: "memory");
        else       asm volatile("cp.async.wait_group 0;" ::: "memory");
        __syncthreads();
        if (t + 2 < 8) issue_tile64<BT>(sm, A, W, ldB, m0, n0, t + 2);

        const float* As = sm + (t % 3) * G2STG;
        const float* Bs = As + 2304;
        #pragma unroll
        for (int ks8 = 0; ks8 < 4; ks8++) {
            unsigned af[2][4];
            #pragma unroll
            for (int mt = 0; mt < 2; mt++) {
                int mb = wm * 32 + mt * 16 + gid;
                af[mt][0] = __float_as_uint(As[mb * 36 + ks8 * 8 + tig]);
                af[mt][1] = __float_as_uint(As[(mb + 8) * 36 + ks8 * 8 + tig]);
                af[mt][2] = __float_as_uint(As[mb * 36 + ks8 * 8 + tig + 4]);
                af[mt][3] = __float_as_uint(As[(mb + 8) * 36 + ks8 * 8 + tig + 4]);
            }
            #pragma unroll
            for (int nt = 0; nt < 4; nt++) {
                int nb = wn * 32 + nt * 8 + gid;
                unsigned bf[2];
                if (BT) {
                    bf[0] = __float_as_uint(Bs[(ks8 * 8 + tig) * 72 + nb]);
                    bf[1] = __float_as_uint(Bs[(ks8 * 8 + tig + 4) * 72 + nb]);
                } else {
                    bf[0] = __float_as_uint(Bs[nb * 36 + ks8 * 8 + tig]);
                    bf[1] = __float_as_uint(Bs[nb * 36 + ks8 * 8 + tig + 4]);
                }
                mma_tf32(acc[0][nt], af[0], bf);
                mma_tf32(acc[1][nt], af[1], bf);
            }
        }
    }
}

template<bool RB>
__device__ __forceinline__ void epi64(
    float (&acc)[2][4][4], const float* __restrict__ bias, float* __restrict__ C,
    int ldC, int m0, int n0, int rpb, int ostride, int ooff, int act)
{
    const int tid = threadIdx.x, lane = tid & 31, warp = tid >> 5;
    const int wm = warp >> 1, wn = warp & 1;
    const int gid = lane >> 2, tig = lane & 3;

    #pragma unroll
    for (int mt = 0; mt < 2; mt++) {
        #pragma unroll
        for (int rh = 0; rh < 2; rh++) {
            int r = m0 + wm * 32 + mt * 16 + gid + rh * 8;
            float rbv = RB ? bias[r] : 0.f;
            int grow = (r / rpb) * ostride + ooff + (r % rpb);
            float* dst = C + (size_t)grow * ldC;
            #pragma unroll
            for (int nt = 0; nt < 4; nt++) {
                int col = n0 + wn * 32 + nt * 8 + tig * 2;
                float v0 = acc[mt][nt][rh * 2 + 0];
                float v1 = acc[mt][nt][rh * 2 + 1];
                if (RB) { v0 += rbv; v1 += rbv; }
                else {
                    float2 bc = *(const float2*)(bias + col);
                    v0 += bc.x; v1 += bc.y;
                }
                if (act) {
                    v0 = v0 > 0.f ? v0 : expm1f(v0);
                    v1 = v1 > 0.f ? v1 : expm1f(v1);
                }
                *(float2*)(dst + col) = make_float2(v0, v1);
            }
        }
    }
}

// ---------------- kernel 1: qkv GEMMs (128-thread, 4 blocks/SM) --------------
__global__ __launch_bounds__(128, 4) void k_qkv(
    const float* __restrict__ x1, const float* __restrict__ x2,
    const float* __restrict__ attn_in_w, const float* __restrict__ attn_in_b)
{
    extern __shared__ float sm[];
    int bx = blockIdx.x;
    float acc[2][4][4];
    if (bx < 3072) {
        int nb = bx >> 8, my = bx & 255;
        mma_loop64<false>(sm, x1, attn_in_w, 0, my * 64, nb * 64, acc);
        epi64<false>(acc, attn_in_b, d_qkv, 3 * Dc, my * 64, nb * 64,
                     N1c, Sc, 0, 0);
    } else {
        int idx = bx - 3072;
        int nb = idx >> 7, my = idx & 127;
        mma_loop64<false>(sm, x2, attn_in_w, 0, my * 64, nb * 64, acc);
        epi64<false>(acc, attn_in_b, d_qkv, 3 * Dc, my * 64, nb * 64,
                     N2c, Sc, N1c, 0);
    }
}

// ---------------- attention body (tf32 MMA, interleaved smem) ----------------
__device__ void attn_body(float* sm, int qt, int bh)
{
    float* Ks = sm;            // 4096
    float* Vs = sm + 4096;     // 4096
    float* Ps = sm + 8192;     // 16384 (8 warps x 2048)

    const int b = bh >> 3, h = bh & 7;
    const int tid = threadIdx.x, lane = tid & 31, warp = tid >> 5;
    const int gid = lane >> 2, tig = lane & 3;
    const int gsw = gid & 3;
    const int m0 = qt * 128;
    const float* base = d_qkv + (size_t)b * Sc * (3 * Dc);
    const float scale = 0.17677669529663688f;   // 1/sqrt(32)
    float* Pw = Ps + warp * 2048;

    unsigned qf[4][4];
    {
        const float* q0 = base + (size_t)(m0 + warp * 16 + gid) * (3 * Dc) + h * HDc;
        const float* q1 = q0 + (size_t)8 * (3 * Dc);
        #pragma unroll
        for (int ks = 0; ks < 4; ks++) {
            qf[ks][0] = __float_as_uint(q0[ks * 8 + tig] * scale);
            qf[ks][1] = __float_as_uint(q1[ks * 8 + tig] * scale);
            qf[ks][2] = __float_as_uint(q0[ks * 8 + tig + 4] * scale);
            qf[ks][3] = __float_as_uint(q1[ks * 8 + tig + 4] * scale);
        }
    }

    float oc[4][4];
    #pragma unroll
    for (int i = 0; i < 4; i++)
        #pragma unroll
        for (int j = 0; j < 4; j++) oc[i][j] = 0.f;
    float ls[4] = { 0.f, 0.f, 0.f, 0.f };
    const unsigned bones[2] = { 0x3f800000u, 0x3f800000u };

    for (int c = 0; c < 6; c++) {
        const int kv0 = c * 128;
        __syncthreads();

        #pragma unroll
        for (int it = 0; it < 4; it++) {
            int i = tid + it * 256;
            int cc = (i & 7) * 4, r = i >> 3;
            const float* src = base + (size_t)(kv0 + r) * (3 * Dc) + Dc + h * HDc + cc;
            float4 v = *(const float4*)src;
            float vv[4] = { v.x, v.y, v.z, v.w };
            #pragma unroll
            for (int j = 0; j < 4; j++) {
                int cq = cc + j;
                Ks[(((cq >> 3) * 128 + r) * 8) + (((cq & 3) ^ (r & 3)) * 2) + ((cq >> 2) & 1)] = vv[j];
            }
        }
        #pragma unroll
        for (int it = 0; it < 4; it++) {
            int i = tid + it * 256;
            int r = i & 127, cg = (i >> 7) * 4;
            const float* src = base + (size_t)(kv0 + r) * (3 * Dc) + 2 * Dc + h * HDc + cg;
            float4 v = *(const float4*)src;
            int w = (r & 3) * 2 + ((r >> 2) & 1);
            int qb = (r >> 3) * 32 + cg;
            Vs[(qb + 0) * 8 + w] = v.x; Vs[(qb + 1) * 8 + w] = v.y;
            Vs[(qb + 2) * 8 + w] = v.z; Vs[(qb + 3) * 8 + w] = v.w;
        }
        __syncthreads();

        #pragma unroll
        for (int half = 0; half < 2; half++) {
            float sc_[8][4];
            #pragma unroll
            for (int nt = 0; nt < 8; nt++)
                #pragma unroll
                for (int j = 0; j < 4; j++) sc_[nt][j] = 0.f;
            #pragma unroll
            for (int ks = 0; ks < 4; ks++) {
                #pragma unroll
                for (int nt = 0; nt < 8; nt++) {
                    int nb = half * 64 + nt * 8 + gid;
                    float2 k2 = *(const float2*)&Ks[((ks * 128 + nb) * 8) + ((tig ^ gsw) * 2)];
                    unsigned bf[2] = { __float_as_uint(k2.x), __float_as_uint(k2.y) };
                    mma_tf32(sc_[nt], qf[ks], bf);
                }
            }
            #pragma unroll
            for (int nt = 0; nt < 8; nt++) {
                float p0 = __expf(sc_[nt][0]);
                float p1 = __expf(sc_[nt][1]);
                float p2 = __expf(sc_[nt][2]);
                float p3 = __expf(sc_[nt][3]);
                int ksq = half * 8 + nt;
                int tc0 = tig * 2, tc1 = tc0 + 1;
                float* pb = Pw + ksq * 128 + gid * 16;
                *(float2*)&pb[((tc0 & 3) ^ gsw) * 4 + (tc0 >> 2) * 2] = make_float2(p0, p2);
                *(float2*)&pb[((tc1 & 3) ^ gsw) * 4 + (tc1 >> 2) * 2] = make_float2(p1, p3);
            }
        }
        __syncwarp();

        #pragma unroll
        for (int ks = 0; ks < 16; ks++) {
            float4 aq = *(const float4*)&Pw[ks * 128 + gid * 16 + ((tig ^ gsw) * 4)];
            unsigned a[4] = { __float_as_uint(aq.x), __float_as_uint(aq.y),
                              __float_as_uint(aq.z), __float_as_uint(aq.w) };
            #pragma unroll
            for (int nf = 0; nf < 4; nf++) {
                float2 v2 = *(const float2*)&Vs[((ks * 32 + nf * 8 + gid) * 8) + tig * 2];
                unsigned bv[2] = { __float_as_uint(v2.x), __float_as_uint(v2.y) };
                mma_tf32(oc[nf], a, bv);
            }
            mma_tf32(ls, a, bones);
        }
        __syncwarp();
    }

    float inv0 = 1.f / ls[0], inv1 = 1.f / ls[2];
    float* o0 = d_o + (size_t)(b * Sc + m0 + warp * 16 + gid) * Dc + h * HDc;
    float* o1 = o0 + 8 * Dc;
    #pragma unroll
    for (int nf = 0; nf < 4; nf++) {
        int col = nf * 8 + tig * 2;
        *(float2*)&o0[col] = make_float2(oc[nf][0] * inv0, oc[nf][1] * inv0);
        *(float2*)&o1[col] = make_float2(oc[nf][2] * inv1, oc[nf][3] * inv1);
    }
}

// ---------------- kernel 2 (mega): router FIRST + attention + GEMMs ----------
// grid: [0,32) router; [32,1568) attn; [1568,1824) x1-lf; [1824,2080) a1;
//       [2080,2208) x2-lf; [2208,2464) a2
__global__ __launch_bounds__(256, 2) void k_mega(
    const float* __restrict__ x1, const float* __restrict__ x2,
    const float* __restrict__ lf_w, const float* __restrict__ lf_b,
    const float* __restrict__ af2_w, const float* __restrict__ af2_b,
    const float* __restrict__ af3_w, const float* __restrict__ af3_b,
    const float* __restrict__ r_w1, const float* __restrict__ r_b1,
    const float* __restrict__ ln_g, const float* __restrict__ ln_b,
    const float* __restrict__ r_w2, const float* __restrict__ r_b2)
{
    extern __shared__ float sm[];
    const int BIGR = 1 << 30;
    int bx = blockIdx.x;

    if (bx < 32) {
        router_body(sm, bx, x1, x2, r_w1, r_b1, ln_g, ln_b, r_w2, r_b2);
        return;
    }
    if (bx < 1568) {
        int idx = bx - 32;
        attn_body(sm, idx % 6, idx / 6);
        return;
    }
    float acc[2][8][4];
    if (bx < 1824) {
        int idx = bx - 1568;
        int nb = idx >> 7, my = idx & 127;
        mma_mainloop32<false>(sm, x1, lf_w, 0, my * 128, nb * 128, acc);
        epi_std<false>(acc, lf_b, d_lf, Dc, my * 128, nb * 128, N1c, Sc, 0, 1);
    } else if (bx < 2080) {
        int idx = bx - 1824;
        int nb = idx >> 7, my = idx & 127;
        mma_mainloop32<false>(sm, x1, af2_w, 0, my * 128, nb * 128, acc);
        epi_std<false>(acc, af2_b, d_xout, Dc, my * 128, nb * 128, BIGR, 0, 0, 1);
    } else if (bx < 2208) {
        int idx = bx - 2080;
        int nb = idx >> 6, my = idx & 63;
        mma_mainloop32<false>(sm, x2, lf_w, 0, my * 128, nb * 128, acc);
        epi_std<false>(acc, lf_b, d_lf, Dc, my * 128, nb * 128, N2c, Sc, N1c, 1);
    } else {
        int idx = bx - 2208;
        int b = idx >> 3, r = idx & 7;
        int nb = r & 1, my = r >> 1;
        const float* W = x2 + (size_t)b * N2c * Dc;
        float* C = d_x2o + (size_t)b * N1c * Dc;
        mma_mainloop32<true>(sm, af3_w, W, Dc, my * 128, nb * 128, acc);
        epi_std<true>(acc, af3_b, C, Dc, my * 128, nb * 128, BIGR, 0, 0, 1);
    }
}

// ---------------- kernel 3: attn_out GEMM + weighted combine (256-thr) -------
__global__ __launch_bounds__(256, 2) void gemm_final(
    const float* __restrict__ W, const float* __restrict__ bias,
    const float* __restrict__ x1, const float* __restrict__ x2,
    float* __restrict__ out)
{
    extern __shared__ float sm[];
    int m0 = blockIdx.y * 128, n0 = blockIdx.x * 128;
    float acc[2][8][4];
    mma_mainloop32<false>(sm, d_o, W, 0, m0, n0, acc);

    const int tid = threadIdx.x, lane = tid & 31, warp = tid >> 5;
    const int wm = warp >> 1, wn = warp & 1;
    const int gid = lane >> 2, tig = lane & 3;

    #pragma unroll
    for (int mt = 0; mt < 2; mt++) {
        #pragma unroll
        for (int rh = 0; rh < 2; rh++) {
            int r = m0 + wm * 32 + mt * 16 + gid + rh * 8;
            int b = r / Sc;
            int s = r - b * Sc;
            const float* w = d_wts + b * 4;
            float w0 = w[0], w1 = w[1], w2 = w[2], w3 = w[3];
            const float* lfr = d_lf + (size_t)r * Dc;
            const float* xo; const float* xo2; const float* xv; float* dst;
            if (s < N1c) {
                size_t rr = (size_t)b * N1c + s;
                xo = d_xout + rr * Dc;
                xo2 = d_x2o + rr * Dc;
                xv = x1 + rr * Dc;
                dst = out + rr * Dc;
            } else {
                int s2 = s - N1c;
                xo = d_xout + ((size_t)b * N1c + s2) * Dc;
                xo2 = d_x2o + ((size_t)b * N1c + s2) * Dc;
                xv = x2 + ((size_t)b * N2c + s2) * Dc;
                dst = out + (size_t)Bb * N1c * Dc + ((size_t)b * N2c + s2) * Dc;
            }
            #pragma unroll
            for (int nt = 0; nt < 8; nt++) {
                int col = n0 + wn * 64 + nt * 8 + tig * 2;
                float2 bc = *(const float2*)(bias + col);
                float op0 = acc[mt][nt][rh * 2 + 0] + bc.x;
                float op1 = acc[mt][nt][rh * 2 + 1] + bc.y;
                float2 l = *(const float2*)(lfr + col);
                float2 g = *(const float2*)(xo + col);
                float2 g2 = *(const float2*)(xo2 + col);
                float2 y = *(const float2*)(xv + col);
                float o0 = w0 * l.x + w1 * (g.x + g2.x) + w2 * op0 + w3 * y.x;
                float o1 = w0 * l.y + w1 * (g.y + g2.y) + w2 * op1 + w3 * y.y;
                *(float2*)(dst + col) = make_float2(o0, o1);
            }
        }
    }
}

// ---------------- launch ----------------------------------------------------
extern "C" void kernel_launch(void* const* d_in, const int* in_sizes, int n_in,
                              void* d_out, int out_size)
{
    const float* x1        = (const float*)d_in[0];
    const float* x2        = (const float*)d_in[1];
    const float* r_w1      = (const float*)d_in[2];
    const float* r_b1      = (const float*)d_in[3];
    const float* ln_g      = (const float*)d_in[4];
    const float* ln_b      = (const float*)d_in[5];
    const float* r_w2      = (const float*)d_in[6];
    const float* r_b2      = (const float*)d_in[7];
    const float* lf_w      = (const float*)d_in[8];
    const float* lf_b      = (const float*)d_in[9];
    const float* af2_w     = (const float*)d_in[10];
    const float* af2_b     = (const float*)d_in[11];
    const float* af3_w     = (const float*)d_in[12];
    const float* af3_b     = (const float*)d_in[13];
    const float* attn_in_w = (const float*)d_in[14];
    const float* attn_in_b = (const float*)d_in[15];
    const float* attn_out_w= (const float*)d_in[16];
    const float* attn_out_b= (const float*)d_in[17];
    float* out = (float*)d_out;

    const int MEGA_SMEM = 3 * GSTG * (int)sizeof(float);   // 110592
    const int G64_SMEM  = 3 * G2STG * (int)sizeof(float);  // 55296
    cudaFuncSetAttribute(k_qkv, cudaFuncAttributeMaxDynamicSharedMemorySize, G64_SMEM);
    cudaFuncSetAttribute(k_mega, cudaFuncAttributeMaxDynamicSharedMemorySize, MEGA_SMEM);
    cudaFuncSetAttribute(gemm_final, cudaFuncAttributeMaxDynamicSharedMemorySize, MEGA_SMEM);

    // 1. qkv GEMMs (128-thread blocks, 4/SM)
    k_qkv<<<4608, 128, G64_SMEM>>>(x1, x2, attn_in_w, attn_in_b);

    // 2. router (wave-1) + attention + independent GEMMs, one launch
    k_mega<<<2464, 256, MEGA_SMEM>>>(x1, x2, lf_w, lf_b, af2_w, af2_b,
                                     af3_w, af3_b,
                                     r_w1, r_b1, ln_g, ln_b, r_w2, r_b2);

    // 3. attn_out GEMM fused with weighted combine (256-thread, BN=128)
    gemm_final<<<dim3(2, 192), 256, MEGA_SMEM>>>(attn_out_w, attn_out_b, x1, x2, out);
}